// round 8
// baseline (speedup 1.0000x reference)
#include <cuda_runtime.h>
#include <cstdint>

#define BB 4
#define NN 16384
#define MM 1024

// ---- static scratch (no allocation) ----
__device__ float  g_support[BB*NN*32];
__device__ float4 g_filt[BB*NN];
__device__ int    g_cidx[BB*MM];
__device__ float  g_cent[BB*MM*32];
__device__ unsigned long long g_slot[BB][2][32];  // parity-buffered, seq-tagged candidates
__device__ int    g_bidx[2*BB*MM*64];
__device__ int    g_bcnt[2*BB*MM];
__device__ float  g_att[2*BB*MM*32];
__device__ float  g_h1[2*BB*MM*64];
__device__ float  g_h2[2*BB*MM*128];
__device__ float  g_s1a[2*64], g_s2a[2*64], g_s1b[2*128], g_s2b[2*128];
__device__ float  g_A1[2*64], g_C1[2*64], g_A2[2*128], g_C2[2*128];

__device__ __forceinline__ unsigned long long ldacq(const unsigned long long* p) {
    unsigned long long v;
    asm volatile("ld.acquire.gpu.u64 %0, [%1];" : "=l"(v) : "l"(p) : "memory");
    return v;
}
__device__ __forceinline__ void strel(unsigned long long* p, unsigned long long v) {
    asm volatile("st.release.gpu.u64 [%0], %1;" :: "l"(p), "l"(v) : "memory");
}

__global__ void k_init() {
    int t = threadIdx.x;
    if (t < 256) ((unsigned long long*)g_slot)[t] = 0ull;
    if (t < 128) { g_s1a[t] = 0.f; g_s2a[t] = 0.f; }
    if (t < 256) { g_s1b[t] = 0.f; g_s2b[t] = 0.f; }
}

// transpose [B,32,N] channel-major inputs -> point-major support + 4-dim filter
__global__ __launch_bounds__(256) void k_build(const float* __restrict__ xyz,
                                               const float* __restrict__ pf) {
    __shared__ float t[32][33];
    int b  = blockIdx.x >> 9;
    int n0 = (blockIdx.x & 511) << 5;
    int tid = threadIdx.x;
#pragma unroll
    for (int i = 0; i < 4; i++) {
        int e = tid + i*256, c = e >> 5, n = e & 31;
        float v = (c < 3) ? xyz[(b*3 + c)*NN + n0 + n] : pf[(b*29 + (c-3))*NN + n0 + n];
        t[n][c] = v;
    }
    __syncthreads();
    int n = tid >> 3, c0 = (tid & 7) << 2;
    *(float4*)&g_support[((size_t)(b*NN + n0 + n))*32 + c0] =
        make_float4(t[n][c0], t[n][c0+1], t[n][c0+2], t[n][c0+3]);
    if (tid < 32)
        g_filt[b*NN + n0 + tid] = make_float4(t[tid][3], t[tid][4], t[tid][5], t[tid][6]);
}

// FPS: persistent, 32 blocks/batch, 1 point/thread, packed-f32x2 distance math.
// Sync: parity-buffered seq-tagged mailboxes; every block polls all 32 slots
// and redundantly computes the global argmax (single publish->detect hop).
__global__ void __launch_bounds__(512, 1) k_fps() {
    int b = blockIdx.x >> 5, blk = blockIdx.x & 31, tid = threadIdx.x;
    __shared__ unsigned long long sred[16];
    __shared__ int sf;
    int p = (blk << 9) + tid;            // 32 blocks * 512 threads = 16384 points
    unsigned long long nx[16];           // packed (-x) pairs, 32 dims
    {
        const float4* a = (const float4*)&g_support[(size_t)(b*NN + p)*32];
#pragma unroll
        for (int i = 0; i < 8; i++) {
            float4 v = a[i];
            asm("mov.b64 %0, {%1, %2};" : "=l"(nx[2*i])   : "f"(-v.x), "f"(-v.y));
            asm("mov.b64 %0, {%1, %2};" : "=l"(nx[2*i+1]) : "f"(-v.z), "f"(-v.w));
        }
    }
    float d = 1e10f;
    int f = 0;
    if (blk == 0 && tid == 0) g_cidx[b*MM] = 0;
    const unsigned long long M46 = (1ull << 46) - 1ull;
    for (int t = 0; t < MM; t++) {
        const ulonglong2* cp = (const ulonglong2*)&g_support[(size_t)(b*NN + f)*32];
        unsigned long long acc01 = 0ull, acc23 = 0ull;   // packed (0.f,0.f)
#pragma unroll
        for (int i = 0; i < 8; i++) {
            ulonglong2 cv = cp[i];
            unsigned long long e01, e23;
            asm("add.rn.f32x2 %0, %1, %2;"     : "=l"(e01)   : "l"(cv.x), "l"(nx[2*i]));
            asm("fma.rn.f32x2 %0, %1, %2, %3;" : "=l"(acc01) : "l"(e01), "l"(e01), "l"(acc01));
            asm("add.rn.f32x2 %0, %1, %2;"     : "=l"(e23)   : "l"(cv.y), "l"(nx[2*i+1]));
            asm("fma.rn.f32x2 %0, %1, %2, %3;" : "=l"(acc23) : "l"(e23), "l"(e23), "l"(acc23));
        }
        float a0, a1, a2, a3;
        asm("mov.b64 {%0, %1}, %2;" : "=f"(a0), "=f"(a1) : "l"(acc01));
        asm("mov.b64 {%0, %1}, %2;" : "=f"(a2), "=f"(a3) : "l"(acc23));
        d = fminf(d, (a0 + a1) + (a2 + a3));
        if (t == MM - 1) break;          // nobody needs the next centroid
        // pack [dist:32][inv_idx:14]; larger == (farther, then lower index)
        unsigned long long pk = ((unsigned long long)__float_as_uint(d) << 14)
                              | (unsigned long long)(16383 - p);
#pragma unroll
        for (int o = 16; o; o >>= 1) {
            unsigned long long q = __shfl_down_sync(0xFFFFFFFFu, pk, o);
            if (q > pk) pk = q;
        }
        if ((tid & 31) == 0) sred[tid >> 5] = pk;
        __syncthreads();
        if (tid < 32) {
            unsigned long long pk2 = (tid < 16) ? sred[tid] : 0ull;
#pragma unroll
            for (int o = 8; o; o >>= 1) {
                unsigned long long q = __shfl_down_sync(0xFFFFFFFFu, pk2, o);
                if (q > pk2) pk2 = q;
            }
            unsigned want = (unsigned)(t + 1);
            unsigned long long* slots = g_slot[b][(t + 1) & 1];
            if (tid == 0)
                strel(&slots[blk], (pk2 & M46) | ((unsigned long long)want << 46));
            unsigned long long v;
            do { v = ldacq(&slots[tid]); }
            while (!__all_sync(0xFFFFFFFFu, (unsigned)(v >> 46) == want));
            unsigned long long m = v & M46;
#pragma unroll
            for (int o = 16; o; o >>= 1) {
                unsigned long long q = __shfl_down_sync(0xFFFFFFFFu, m, o);
                if (q > m) m = q;
            }
            if (tid == 0) {
                int idx = 16383 - (int)(m & 16383ull);
                if (blk == 0) g_cidx[b*MM + t + 1] = idx;
                sf = idx;
            }
        }
        __syncthreads();
        f = sf;
    }
}

__global__ __launch_bounds__(256) void k_gather(float* __restrict__ out) {
    int gt = blockIdx.x * 256 + threadIdx.x;
    int bm = gt >> 5, lane = gt & 31;
    int b = bm >> 10, m = bm & 1023;
    int ci = g_cidx[bm];
    float v = g_support[(size_t)(b*NN + ci)*32 + lane];
    g_cent[bm*32 + lane] = v;
    if (lane < 3) out[(b*3 + lane)*MM + m] = v;
}

// ball query: 4-dim lower-bound prune, exact 32-dim verify for survivors
__global__ __launch_bounds__(256) void k_ball(float r2, int kmax, int s) {
    int w = threadIdx.x >> 5, lane = threadIdx.x & 31;
    int bm = blockIdx.x * 8 + w;
    int b = bm >> 10;
    const float* cen = &g_cent[bm*32];
    float c3 = cen[3], c4 = cen[4], c5 = cen[5], c6 = cen[6];
    int cnt = 0;
    int* outIdx = &g_bidx[(size_t)(s*4096 + bm)*64];
    const float4* filt = &g_filt[b*NN];
    for (int it = 0; it < NN/32; it++) {
        int n = (it << 5) + lane;
        float4 fv = filt[n];
        float dx = fv.x - c3; float d4 = dx*dx;
        dx = fv.y - c4; d4 = fmaf(dx, dx, d4);
        dx = fv.z - c5; d4 = fmaf(dx, dx, d4);
        dx = fv.w - c6; d4 = fmaf(dx, dx, d4);
        bool pred = false;
        if (d4 <= r2) {
            const float* pp = &g_support[(size_t)(b*NN + n)*32];
            float dd = 0.f;
#pragma unroll
            for (int i = 0; i < 32; i++) { float e = pp[i] - cen[i]; dd = fmaf(e, e, dd); }
            pred = (dd <= r2);
        }
        unsigned bal = __ballot_sync(0xFFFFFFFFu, pred);
        while (bal && cnt < kmax) {
            int l = __ffs(bal) - 1; bal &= bal - 1;
            if (lane == 0) outIdx[cnt] = (it << 5) + l;
            cnt++;
        }
        if (cnt >= kmax) break;
    }
    if (lane == 0) g_bcnt[s*4096 + bm] = cnt;
}

// attention over unmasked neighbors only (masked softmax weights are exactly 0)
__global__ __launch_bounds__(256) void k_att(const float* __restrict__ wq,
                                             const float* __restrict__ wk,
                                             const float* __restrict__ wv,
                                             const float* __restrict__ wo, int s) {
    __shared__ float s_q[32*64], s_k[32*64], s_v[32*64], s_oT[64*32];
    __shared__ float s_x[8][32], s_y[8][32], s_o[8][64], s_l[8][128];
    int tid = threadIdx.x;
    for (int i = tid; i < 2048; i += 256) {
        int oc = i >> 5, c = i & 31;
        s_q[c*64 + oc] = wq[i];
        s_k[c*64 + oc] = wk[i];
        s_v[c*64 + oc] = wv[i];
        int oc2 = i >> 6, c2 = i & 63;
        s_oT[c2*32 + oc2] = wo[i];
    }
    __syncthreads();
    int w = tid >> 5, lane = tid & 31;
    int bm = blockIdx.x * 8 + w;
    int b = bm >> 10;
    float xv = g_cent[bm*32 + lane];
    s_x[w][lane] = xv;
    __syncwarp();
    float q0 = 0.f, q1 = 0.f;
#pragma unroll
    for (int c = 0; c < 32; c++) {
        float xc = s_x[w][c];
        q0 = fmaf(s_q[c*64 + lane],      xc, q0);
        q1 = fmaf(s_q[c*64 + 32 + lane], xc, q1);
    }
    int cnt = g_bcnt[s*4096 + bm];
    const int* bidx = &g_bidx[(size_t)(s*4096 + bm)*64];
    const float rs = 0.17677669529663687f;  // 1/sqrt(32)
    for (int j = 0; j < cnt; j++) {
        int id = bidx[j];
        float yv = g_support[(size_t)(b*NN + id)*32 + lane] - s_x[w][lane];
        s_y[w][lane] = yv; __syncwarp();
        float k0 = 0.f, k1 = 0.f;
#pragma unroll
        for (int c = 0; c < 32; c++) {
            float yc = s_y[w][c];
            k0 = fmaf(s_k[c*64 + lane],      yc, k0);
            k1 = fmaf(s_k[c*64 + 32 + lane], yc, k1);
        }
        float l0 = q0*k0, l1 = q1*k1;
#pragma unroll
        for (int o = 16; o; o >>= 1) {
            l0 += __shfl_xor_sync(0xFFFFFFFFu, l0, o);
            l1 += __shfl_xor_sync(0xFFFFFFFFu, l1, o);
        }
        if (lane == 0) { s_l[w][j] = l0*rs; s_l[w][64 + j] = l1*rs; }
        __syncwarp();
    }
#pragma unroll
    for (int h = 0; h < 2; h++) {
        float v0 = (lane      < cnt) ? s_l[w][h*64 + lane]      : -3e38f;
        float v1 = (lane + 32 < cnt) ? s_l[w][h*64 + lane + 32] : -3e38f;
        float mx = fmaxf(v0, v1);
#pragma unroll
        for (int o = 16; o; o >>= 1) mx = fmaxf(mx, __shfl_xor_sync(0xFFFFFFFFu, mx, o));
        float e0 = (lane      < cnt) ? __expf(v0 - mx) : 0.f;
        float e1 = (lane + 32 < cnt) ? __expf(v1 - mx) : 0.f;
        float sm = e0 + e1;
#pragma unroll
        for (int o = 16; o; o >>= 1) sm += __shfl_xor_sync(0xFFFFFFFFu, sm, o);
        float inv = 1.f / sm;
        if (lane      < cnt) s_l[w][h*64 + lane]      = e0 * inv;
        if (lane + 32 < cnt) s_l[w][h*64 + lane + 32] = e1 * inv;
    }
    __syncwarp();
    float o0 = 0.f, o1 = 0.f;
    for (int j = 0; j < cnt; j++) {
        int id = bidx[j];
        float yv = g_support[(size_t)(b*NN + id)*32 + lane] - s_x[w][lane];
        s_y[w][lane] = yv; __syncwarp();
        float v0 = 0.f, v1 = 0.f;
#pragma unroll
        for (int c = 0; c < 32; c++) {
            float yc = s_y[w][c];
            v0 = fmaf(s_v[c*64 + lane],      yc, v0);
            v1 = fmaf(s_v[c*64 + 32 + lane], yc, v1);
        }
        o0 = fmaf(s_l[w][j],      v0, o0);
        o1 = fmaf(s_l[w][64 + j], v1, o1);
        __syncwarp();
    }
    s_o[w][lane] = o0; s_o[w][32 + lane] = o1; __syncwarp();
    float outv = s_x[w][lane];
#pragma unroll
    for (int c = 0; c < 64; c++) outv = fmaf(s_oT[c*32 + lane], s_o[w][c], outv);
    g_att[(size_t)(s*4096 + bm)*32 + lane] = outv;
}

__global__ __launch_bounds__(256) void k_mlp1(const float* __restrict__ W0,
                                              const float* __restrict__ b0, int s) {
    __shared__ float sW[32*64];
    __shared__ float s_in[4][32];
    __shared__ float sh[4][64];
    int tid = threadIdx.x;
    for (int i = tid; i < 2048; i += 256) { int oc = i >> 5, c = i & 31; sW[c*64 + oc] = W0[i]; }
    int bm0 = blockIdx.x * 4;
    if (tid < 128) s_in[tid >> 5][tid & 31] = g_att[(size_t)(s*4096 + bm0)*32 + tid];
    __syncthreads();
    int oc = tid & 63, q = tid >> 6;
    float h = b0[oc];
#pragma unroll
    for (int c = 0; c < 32; c++) h = fmaf(sW[c*64 + oc], s_in[q][c], h);
    g_h1[(size_t)(s*4096 + bm0 + q)*64 + oc] = h;
    sh[q][oc] = h;
    __syncthreads();
    if (q == 0) {
        float s1 = 0.f, s2 = 0.f;
#pragma unroll
        for (int qq = 0; qq < 4; qq++) { float v = sh[qq][oc]; s1 += v; s2 = fmaf(v, v, s2); }
        atomicAdd(&g_s1a[s*64 + oc], s1);
        atomicAdd(&g_s2a[s*64 + oc], s2);
    }
}

__global__ void k_fin1(const float* __restrict__ g, const float* __restrict__ beta, int s) {
    int oc = threadIdx.x;
    float mu  = g_s1a[s*64 + oc] * (1.f/4096.f);
    float var = g_s2a[s*64 + oc] * (1.f/4096.f) - mu*mu;
    float A = g[oc] * rsqrtf(var + 1e-5f);
    g_A1[s*64 + oc] = A;
    g_C1[s*64 + oc] = beta[oc] - mu*A;
}

__global__ __launch_bounds__(256) void k_mlp2(const float* __restrict__ W1,
                                              const float* __restrict__ b1, int s) {
    __shared__ float sW[64*128];
    __shared__ float sact[2][64];
    __shared__ float sh[2][128];
    int tid = threadIdx.x;
    for (int i = tid; i < 8192; i += 256) { int oc = i >> 6, c = i & 63; sW[c*128 + oc] = W1[i]; }
    int bm0 = blockIdx.x * 2;
    if (tid < 128) {
        int q = tid >> 6, c = tid & 63;
        float v = g_h1[(size_t)(s*4096 + bm0 + q)*64 + c];
        v = g_A1[s*64 + c]*v + g_C1[s*64 + c];
        sact[q][c] = v > 0.f ? v : 0.02f*v;
    }
    __syncthreads();
    int oc = tid & 127, q = tid >> 7;
    float h = b1[oc];
#pragma unroll
    for (int c = 0; c < 64; c++) h = fmaf(sW[c*128 + oc], sact[q][c], h);
    g_h2[(size_t)(s*4096 + bm0 + q)*128 + oc] = h;
    sh[q][oc] = h;
    __syncthreads();
    if (q == 0) {
        float a = sh[0][oc], bb = sh[1][oc];
        atomicAdd(&g_s1b[s*128 + oc], a + bb);
        atomicAdd(&g_s2b[s*128 + oc], fmaf(a, a, bb*bb));
    }
}

__global__ void k_fin2(const float* __restrict__ g, const float* __restrict__ beta, int s) {
    int oc = threadIdx.x;
    float mu  = g_s1b[s*128 + oc] * (1.f/4096.f);
    float var = g_s2b[s*128 + oc] * (1.f/4096.f) - mu*mu;
    float A = g[oc] * rsqrtf(var + 1e-5f);
    g_A2[s*128 + oc] = A;
    g_C2[s*128 + oc] = beta[oc] - mu*A;
}

__global__ __launch_bounds__(256) void k_out(float* __restrict__ out, int s) {
    int idx = blockIdx.x * 256 + threadIdx.x;
    int m = idx & 1023;
    int t2 = idx >> 10;
    int oc = t2 & 127, b = t2 >> 7;
    int bm = b*1024 + m;
    float v = g_h2[(size_t)(s*4096 + bm)*128 + oc];
    v = g_A2[s*128 + oc]*v + g_C2[s*128 + oc];
    out[12288 + (((b*256) + s*128 + oc) << 10) + m] = v;
}

extern "C" void kernel_launch(void* const* d_in, const int* in_sizes, int n_in,
                              void* d_out, int out_size) {
    (void)in_sizes; (void)n_in; (void)out_size;
    const float* xyz = (const float*)d_in[0];
    const float* pf  = (const float*)d_in[1];
    float* out = (float*)d_out;
    k_init<<<1, 256>>>();
    k_build<<<2048, 256>>>(xyz, pf);
    k_fps<<<128, 512>>>();
    k_gather<<<512, 256>>>(out);
    const float r2s[2] = {0.1f*0.1f, 0.2f*0.2f};
    const int   kms[2] = {32, 64};
    for (int s = 0; s < 2; s++) {
        int o = 2 + s*12;
        k_ball<<<512, 256>>>(r2s[s], kms[s], s);
        k_att<<<512, 256>>>((const float*)d_in[o],   (const float*)d_in[o+1],
                            (const float*)d_in[o+2], (const float*)d_in[o+3], s);
        k_mlp1<<<1024, 256>>>((const float*)d_in[o+4], (const float*)d_in[o+5], s);
        k_fin1<<<1, 64>>>((const float*)d_in[o+6], (const float*)d_in[o+7], s);
        k_mlp2<<<2048, 256>>>((const float*)d_in[o+8], (const float*)d_in[o+9], s);
        k_fin2<<<1, 128>>>((const float*)d_in[o+10], (const float*)d_in[o+11], s);
        k_out<<<2048, 256>>>(out, s);
    }
}

// round 9
// speedup vs baseline: 3.0999x; 3.0999x over previous
#include <cuda_runtime.h>
#include <cstdint>

#define BB 4
#define NN 16384
#define MM 1024

// ---- static scratch (no allocation) ----
__device__ float  g_support[BB*NN*32];
__device__ float4 g_filt[BB*NN];
__device__ int    g_cidx[BB*MM];
__device__ float  g_cent[BB*MM*32];
__device__ int    g_bidx[2*BB*MM*64];
__device__ int    g_bcnt[2*BB*MM];
__device__ float  g_att[2*BB*MM*32];
__device__ float  g_h1[2*BB*MM*64];
__device__ float  g_h2[2*BB*MM*128];
__device__ float  g_s1a[2*64], g_s2a[2*64], g_s1b[2*128], g_s2b[2*128];
__device__ float  g_A1[2*64], g_C1[2*64], g_A2[2*128], g_C2[2*128];

__global__ void k_init() {
    int t = threadIdx.x;
    if (t < 128) { g_s1a[t] = 0.f; g_s2a[t] = 0.f; }
    if (t < 256) { g_s1b[t] = 0.f; g_s2b[t] = 0.f; }
}

// transpose [B,32,N] channel-major inputs -> point-major support + 4-dim filter
__global__ __launch_bounds__(256) void k_build(const float* __restrict__ xyz,
                                               const float* __restrict__ pf) {
    __shared__ float t[32][33];
    int b  = blockIdx.x >> 9;
    int n0 = (blockIdx.x & 511) << 5;
    int tid = threadIdx.x;
#pragma unroll
    for (int i = 0; i < 4; i++) {
        int e = tid + i*256, c = e >> 5, n = e & 31;
        float v = (c < 3) ? xyz[(b*3 + c)*NN + n0 + n] : pf[(b*29 + (c-3))*NN + n0 + n];
        t[n][c] = v;
    }
    __syncthreads();
    int n = tid >> 3, c0 = (tid & 7) << 2;
    *(float4*)&g_support[((size_t)(b*NN + n0 + n))*32 + c0] =
        make_float4(t[n][c0], t[n][c0+1], t[n][c0+2], t[n][c0+3]);
    if (tid < 32)
        g_filt[b*NN + n0 + tid] = make_float4(t[tid][3], t[tid][4], t[tid][5], t[tid][6]);
}

__device__ __forceinline__ uint32_t smem_u32(const void* p) {
    uint32_t a;
    asm("{ .reg .u64 t; cvta.to.shared.u64 t, %1; cvt.u32.u64 %0, t; }" : "=r"(a) : "l"(p));
    return a;
}
__device__ __forceinline__ unsigned long long dsmem_ld(uint32_t laddr, uint32_t rank) {
    uint32_t ra; unsigned long long v;
    asm volatile("mapa.shared::cluster.u32 %0, %1, %2;" : "=r"(ra) : "r"(laddr), "r"(rank));
    asm volatile("ld.shared::cluster.u64 %0, [%1];" : "=l"(v) : "r"(ra) : "memory");
    return v;
}

// FPS: one 16-CTA cluster per batch, 512 thr/CTA, 2 pts/thread (f32x2 math).
// Per-iter sync: SMEM parity slots + barrier.cluster + DSMEM peer reads.
__global__ void __launch_bounds__(512, 1) k_fps() {
    int b   = blockIdx.x >> 4;        // 4 clusters of 16 CTAs
    int crk = blockIdx.x & 15;        // cluster rank
    int tid = threadIdx.x;
    __shared__ unsigned long long sred[16];
    __shared__ unsigned long long slot[2];   // parity-buffered cluster candidate
    __shared__ int sf;
    int p0 = (crk << 9) + tid;        // 0..8191
    int p1 = p0 + 8192;
    unsigned long long nx0[16], nx1[16];     // packed (-x) pairs per point
    {
        const float4* a = (const float4*)&g_support[(size_t)(b*NN + p0)*32];
        const float4* c = (const float4*)&g_support[(size_t)(b*NN + p1)*32];
#pragma unroll
        for (int i = 0; i < 8; i++) {
            float4 v = a[i], u = c[i];
            asm("mov.b64 %0, {%1, %2};" : "=l"(nx0[2*i])   : "f"(-v.x), "f"(-v.y));
            asm("mov.b64 %0, {%1, %2};" : "=l"(nx0[2*i+1]) : "f"(-v.z), "f"(-v.w));
            asm("mov.b64 %0, {%1, %2};" : "=l"(nx1[2*i])   : "f"(-u.x), "f"(-u.y));
            asm("mov.b64 %0, {%1, %2};" : "=l"(nx1[2*i+1]) : "f"(-u.z), "f"(-u.w));
        }
    }
    float d0 = 1e10f, d1 = 1e10f;
    int f = 0;
    if (crk == 0 && tid == 0) g_cidx[b*MM] = 0;
    for (int t = 0; t < MM; t++) {
        const ulonglong2* cp = (const ulonglong2*)&g_support[(size_t)(b*NN + f)*32];
        unsigned long long A01 = 0ull, A23 = 0ull, B01 = 0ull, B23 = 0ull;
#pragma unroll
        for (int i = 0; i < 8; i++) {
            ulonglong2 cv = cp[i];
            unsigned long long e;
            asm("add.rn.f32x2 %0, %1, %2;"     : "=l"(e)   : "l"(cv.x), "l"(nx0[2*i]));
            asm("fma.rn.f32x2 %0, %1, %2, %3;" : "=l"(A01) : "l"(e), "l"(e), "l"(A01));
            asm("add.rn.f32x2 %0, %1, %2;"     : "=l"(e)   : "l"(cv.y), "l"(nx0[2*i+1]));
            asm("fma.rn.f32x2 %0, %1, %2, %3;" : "=l"(A23) : "l"(e), "l"(e), "l"(A23));
            asm("add.rn.f32x2 %0, %1, %2;"     : "=l"(e)   : "l"(cv.x), "l"(nx1[2*i]));
            asm("fma.rn.f32x2 %0, %1, %2, %3;" : "=l"(B01) : "l"(e), "l"(e), "l"(B01));
            asm("add.rn.f32x2 %0, %1, %2;"     : "=l"(e)   : "l"(cv.y), "l"(nx1[2*i+1]));
            asm("fma.rn.f32x2 %0, %1, %2, %3;" : "=l"(B23) : "l"(e), "l"(e), "l"(B23));
        }
        float a0,a1,a2,a3;
        asm("mov.b64 {%0, %1}, %2;" : "=f"(a0), "=f"(a1) : "l"(A01));
        asm("mov.b64 {%0, %1}, %2;" : "=f"(a2), "=f"(a3) : "l"(A23));
        d0 = fminf(d0, (a0 + a1) + (a2 + a3));
        asm("mov.b64 {%0, %1}, %2;" : "=f"(a0), "=f"(a1) : "l"(B01));
        asm("mov.b64 {%0, %1}, %2;" : "=f"(a2), "=f"(a3) : "l"(B23));
        d1 = fminf(d1, (a0 + a1) + (a2 + a3));
        if (t == MM - 1) break;                    // last centroid never consumed
        float dm; unsigned pi;
        if (d0 >= d1) { dm = d0; pi = (unsigned)p0; } else { dm = d1; pi = (unsigned)p1; }
        unsigned long long pk = ((unsigned long long)__float_as_uint(dm) << 14)
                              | (unsigned long long)(16383u - pi);   // tie -> lowest idx
#pragma unroll
        for (int o = 16; o; o >>= 1) {
            unsigned long long q = __shfl_down_sync(0xFFFFFFFFu, pk, o);
            if (q > pk) pk = q;
        }
        if ((tid & 31) == 0) sred[tid >> 5] = pk;
        __syncthreads();
        if (tid < 32) {
            unsigned long long pk2 = (tid < 16) ? sred[tid] : 0ull;
#pragma unroll
            for (int o = 8; o; o >>= 1) {
                unsigned long long q = __shfl_down_sync(0xFFFFFFFFu, pk2, o);
                if (q > pk2) pk2 = q;
            }
            if (tid == 0) slot[t & 1] = pk2;
        }
        asm volatile("barrier.cluster.arrive.aligned;" ::: "memory");
        asm volatile("barrier.cluster.wait.aligned;" ::: "memory");
        if (tid < 32) {
            uint32_t laddr = smem_u32(&slot[t & 1]);
            unsigned long long v = dsmem_ld(laddr, (uint32_t)(tid & 15));
#pragma unroll
            for (int o = 16; o; o >>= 1) {
                unsigned long long q = __shfl_down_sync(0xFFFFFFFFu, v, o);
                if (q > v) v = q;
            }
            if (tid == 0) {
                int idx = 16383 - (int)(v & 16383ull);
                if (crk == 0) g_cidx[b*MM + t + 1] = idx;
                sf = idx;
            }
        }
        __syncthreads();
        f = sf;
    }
}

__global__ __launch_bounds__(256) void k_gather(float* __restrict__ out) {
    int gt = blockIdx.x * 256 + threadIdx.x;
    int bm = gt >> 5, lane = gt & 31;
    int b = bm >> 10, m = bm & 1023;
    int ci = g_cidx[bm];
    float v = g_support[(size_t)(b*NN + ci)*32 + lane];
    g_cent[bm*32 + lane] = v;
    if (lane < 3) out[(b*3 + lane)*MM + m] = v;
}

// ball query: 4-dim lower-bound prune, exact 32-dim verify for survivors
__global__ __launch_bounds__(256) void k_ball(float r2, int kmax, int s) {
    int w = threadIdx.x >> 5, lane = threadIdx.x & 31;
    int bm = blockIdx.x * 8 + w;
    int b = bm >> 10;
    const float* cen = &g_cent[bm*32];
    float c3 = cen[3], c4 = cen[4], c5 = cen[5], c6 = cen[6];
    int cnt = 0;
    int* outIdx = &g_bidx[(size_t)(s*4096 + bm)*64];
    const float4* filt = &g_filt[b*NN];
    for (int it = 0; it < NN/32; it++) {
        int n = (it << 5) + lane;
        float4 fv = filt[n];
        float dx = fv.x - c3; float d4 = dx*dx;
        dx = fv.y - c4; d4 = fmaf(dx, dx, d4);
        dx = fv.z - c5; d4 = fmaf(dx, dx, d4);
        dx = fv.w - c6; d4 = fmaf(dx, dx, d4);
        bool pred = false;
        if (d4 <= r2) {
            const float* pp = &g_support[(size_t)(b*NN + n)*32];
            float dd = 0.f;
#pragma unroll
            for (int i = 0; i < 32; i++) { float e = pp[i] - cen[i]; dd = fmaf(e, e, dd); }
            pred = (dd <= r2);
        }
        unsigned bal = __ballot_sync(0xFFFFFFFFu, pred);
        while (bal && cnt < kmax) {
            int l = __ffs(bal) - 1; bal &= bal - 1;
            if (lane == 0) outIdx[cnt] = (it << 5) + l;
            cnt++;
        }
        if (cnt >= kmax) break;
    }
    if (lane == 0) g_bcnt[s*4096 + bm] = cnt;
}

// attention over unmasked neighbors only (masked softmax weights are exactly 0)
__global__ __launch_bounds__(256) void k_att(const float* __restrict__ wq,
                                             const float* __restrict__ wk,
                                             const float* __restrict__ wv,
                                             const float* __restrict__ wo, int s) {
    __shared__ float s_q[32*64], s_k[32*64], s_v[32*64], s_oT[64*32];
    __shared__ float s_x[8][32], s_y[8][32], s_o[8][64], s_l[8][128];
    int tid = threadIdx.x;
    for (int i = tid; i < 2048; i += 256) {
        int oc = i >> 5, c = i & 31;
        s_q[c*64 + oc] = wq[i];
        s_k[c*64 + oc] = wk[i];
        s_v[c*64 + oc] = wv[i];
        int oc2 = i >> 6, c2 = i & 63;
        s_oT[c2*32 + oc2] = wo[i];
    }
    __syncthreads();
    int w = tid >> 5, lane = tid & 31;
    int bm = blockIdx.x * 8 + w;
    int b = bm >> 10;
    float xv = g_cent[bm*32 + lane];
    s_x[w][lane] = xv;
    __syncwarp();
    float q0 = 0.f, q1 = 0.f;
#pragma unroll
    for (int c = 0; c < 32; c++) {
        float xc = s_x[w][c];
        q0 = fmaf(s_q[c*64 + lane],      xc, q0);
        q1 = fmaf(s_q[c*64 + 32 + lane], xc, q1);
    }
    int cnt = g_bcnt[s*4096 + bm];
    const int* bidx = &g_bidx[(size_t)(s*4096 + bm)*64];
    const float rs = 0.17677669529663687f;  // 1/sqrt(32)
    for (int j = 0; j < cnt; j++) {
        int id = bidx[j];
        float yv = g_support[(size_t)(b*NN + id)*32 + lane] - s_x[w][lane];
        s_y[w][lane] = yv; __syncwarp();
        float k0 = 0.f, k1 = 0.f;
#pragma unroll
        for (int c = 0; c < 32; c++) {
            float yc = s_y[w][c];
            k0 = fmaf(s_k[c*64 + lane],      yc, k0);
            k1 = fmaf(s_k[c*64 + 32 + lane], yc, k1);
        }
        float l0 = q0*k0, l1 = q1*k1;
#pragma unroll
        for (int o = 16; o; o >>= 1) {
            l0 += __shfl_xor_sync(0xFFFFFFFFu, l0, o);
            l1 += __shfl_xor_sync(0xFFFFFFFFu, l1, o);
        }
        if (lane == 0) { s_l[w][j] = l0*rs; s_l[w][64 + j] = l1*rs; }
        __syncwarp();
    }
#pragma unroll
    for (int h = 0; h < 2; h++) {
        float v0 = (lane      < cnt) ? s_l[w][h*64 + lane]      : -3e38f;
        float v1 = (lane + 32 < cnt) ? s_l[w][h*64 + lane + 32] : -3e38f;
        float mx = fmaxf(v0, v1);
#pragma unroll
        for (int o = 16; o; o >>= 1) mx = fmaxf(mx, __shfl_xor_sync(0xFFFFFFFFu, mx, o));
        float e0 = (lane      < cnt) ? __expf(v0 - mx) : 0.f;
        float e1 = (lane + 32 < cnt) ? __expf(v1 - mx) : 0.f;
        float sm = e0 + e1;
#pragma unroll
        for (int o = 16; o; o >>= 1) sm += __shfl_xor_sync(0xFFFFFFFFu, sm, o);
        float inv = 1.f / sm;
        if (lane      < cnt) s_l[w][h*64 + lane]      = e0 * inv;
        if (lane + 32 < cnt) s_l[w][h*64 + lane + 32] = e1 * inv;
    }
    __syncwarp();
    float o0 = 0.f, o1 = 0.f;
    for (int j = 0; j < cnt; j++) {
        int id = bidx[j];
        float yv = g_support[(size_t)(b*NN + id)*32 + lane] - s_x[w][lane];
        s_y[w][lane] = yv; __syncwarp();
        float v0 = 0.f, v1 = 0.f;
#pragma unroll
        for (int c = 0; c < 32; c++) {
            float yc = s_y[w][c];
            v0 = fmaf(s_v[c*64 + lane],      yc, v0);
            v1 = fmaf(s_v[c*64 + 32 + lane], yc, v1);
        }
        o0 = fmaf(s_l[w][j],      v0, o0);
        o1 = fmaf(s_l[w][64 + j], v1, o1);
        __syncwarp();
    }
    s_o[w][lane] = o0; s_o[w][32 + lane] = o1; __syncwarp();
    float outv = s_x[w][lane];
#pragma unroll
    for (int c = 0; c < 64; c++) outv = fmaf(s_oT[c*32 + lane], s_o[w][c], outv);
    g_att[(size_t)(s*4096 + bm)*32 + lane] = outv;
}

__global__ __launch_bounds__(256) void k_mlp1(const float* __restrict__ W0,
                                              const float* __restrict__ b0, int s) {
    __shared__ float sW[32*64];
    __shared__ float s_in[4][32];
    __shared__ float sh[4][64];
    int tid = threadIdx.x;
    for (int i = tid; i < 2048; i += 256) { int oc = i >> 5, c = i & 31; sW[c*64 + oc] = W0[i]; }
    int bm0 = blockIdx.x * 4;
    if (tid < 128) s_in[tid >> 5][tid & 31] = g_att[(size_t)(s*4096 + bm0)*32 + tid];
    __syncthreads();
    int oc = tid & 63, q = tid >> 6;
    float h = b0[oc];
#pragma unroll
    for (int c = 0; c < 32; c++) h = fmaf(sW[c*64 + oc], s_in[q][c], h);
    g_h1[(size_t)(s*4096 + bm0 + q)*64 + oc] = h;
    sh[q][oc] = h;
    __syncthreads();
    if (q == 0) {
        float s1 = 0.f, s2 = 0.f;
#pragma unroll
        for (int qq = 0; qq < 4; qq++) { float v = sh[qq][oc]; s1 += v; s2 = fmaf(v, v, s2); }
        atomicAdd(&g_s1a[s*64 + oc], s1);
        atomicAdd(&g_s2a[s*64 + oc], s2);
    }
}

__global__ void k_fin1(const float* __restrict__ g, const float* __restrict__ beta, int s) {
    int oc = threadIdx.x;
    float mu  = g_s1a[s*64 + oc] * (1.f/4096.f);
    float var = g_s2a[s*64 + oc] * (1.f/4096.f) - mu*mu;
    float A = g[oc] * rsqrtf(var + 1e-5f);
    g_A1[s*64 + oc] = A;
    g_C1[s*64 + oc] = beta[oc] - mu*A;
}

__global__ __launch_bounds__(256) void k_mlp2(const float* __restrict__ W1,
                                              const float* __restrict__ b1, int s) {
    __shared__ float sW[64*128];
    __shared__ float sact[2][64];
    __shared__ float sh[2][128];
    int tid = threadIdx.x;
    for (int i = tid; i < 8192; i += 256) { int oc = i >> 6, c = i & 63; sW[c*128 + oc] = W1[i]; }
    int bm0 = blockIdx.x * 2;
    if (tid < 128) {
        int q = tid >> 6, c = tid & 63;
        float v = g_h1[(size_t)(s*4096 + bm0 + q)*64 + c];
        v = g_A1[s*64 + c]*v + g_C1[s*64 + c];
        sact[q][c] = v > 0.f ? v : 0.02f*v;
    }
    __syncthreads();
    int oc = tid & 127, q = tid >> 7;
    float h = b1[oc];
#pragma unroll
    for (int c = 0; c < 64; c++) h = fmaf(sW[c*128 + oc], sact[q][c], h);
    g_h2[(size_t)(s*4096 + bm0 + q)*128 + oc] = h;
    sh[q][oc] = h;
    __syncthreads();
    if (q == 0) {
        float a = sh[0][oc], bb = sh[1][oc];
        atomicAdd(&g_s1b[s*128 + oc], a + bb);
        atomicAdd(&g_s2b[s*128 + oc], fmaf(a, a, bb*bb));
    }
}

__global__ void k_fin2(const float* __restrict__ g, const float* __restrict__ beta, int s) {
    int oc = threadIdx.x;
    float mu  = g_s1b[s*128 + oc] * (1.f/4096.f);
    float var = g_s2b[s*128 + oc] * (1.f/4096.f) - mu*mu;
    float A = g[oc] * rsqrtf(var + 1e-5f);
    g_A2[s*128 + oc] = A;
    g_C2[s*128 + oc] = beta[oc] - mu*A;
}

__global__ __launch_bounds__(256) void k_out(float* __restrict__ out, int s) {
    int idx = blockIdx.x * 256 + threadIdx.x;
    int m = idx & 1023;
    int t2 = idx >> 10;
    int oc = t2 & 127, b = t2 >> 7;
    int bm = b*1024 + m;
    float v = g_h2[(size_t)(s*4096 + bm)*128 + oc];
    v = g_A2[s*128 + oc]*v + g_C2[s*128 + oc];
    out[12288 + (((b*256) + s*128 + oc) << 10) + m] = v;
}

extern "C" void kernel_launch(void* const* d_in, const int* in_sizes, int n_in,
                              void* d_out, int out_size) {
    (void)in_sizes; (void)n_in; (void)out_size;
    const float* xyz = (const float*)d_in[0];
    const float* pf  = (const float*)d_in[1];
    float* out = (float*)d_out;
    k_init<<<1, 256>>>();
    k_build<<<2048, 256>>>(xyz, pf);
    {
        cudaFuncSetAttribute(k_fps, cudaFuncAttributeNonPortableClusterSizeAllowed, 1);
        cudaLaunchConfig_t cfg = {};
        cfg.gridDim  = dim3(64, 1, 1);
        cfg.blockDim = dim3(512, 1, 1);
        cfg.dynamicSmemBytes = 0;
        cfg.stream = 0;
        cudaLaunchAttribute at[1];
        at[0].id = cudaLaunchAttributeClusterDimension;
        at[0].val.clusterDim.x = 16; at[0].val.clusterDim.y = 1; at[0].val.clusterDim.z = 1;
        cfg.attrs = at;
        cfg.numAttrs = 1;
        cudaLaunchKernelEx(&cfg, k_fps);
    }
    k_gather<<<512, 256>>>(out);
    const float r2s[2] = {0.1f*0.1f, 0.2f*0.2f};
    const int   kms[2] = {32, 64};
    for (int s = 0; s < 2; s++) {
        int o = 2 + s*12;
        k_ball<<<512, 256>>>(r2s[s], kms[s], s);
        k_att<<<512, 256>>>((const float*)d_in[o],   (const float*)d_in[o+1],
                            (const float*)d_in[o+2], (const float*)d_in[o+3], s);
        k_mlp1<<<1024, 256>>>((const float*)d_in[o+4], (const float*)d_in[o+5], s);
        k_fin1<<<1, 64>>>((const float*)d_in[o+6], (const float*)d_in[o+7], s);
        k_mlp2<<<2048, 256>>>((const float*)d_in[o+8], (const float*)d_in[o+9], s);
        k_fin2<<<1, 128>>>((const float*)d_in[o+10], (const float*)d_in[o+11], s);
        k_out<<<2048, 256>>>(out, s);
    }
}

// round 11
// speedup vs baseline: 3.7815x; 1.2199x over previous
#include <cuda_runtime.h>
#include <cuda_fp16.h>
#include <cstdint>
#include <cstring>

#define BB 4
#define NN 16384
#define MM 1024

// ---- static scratch (no allocation) ----
__device__ float  g_support[BB*NN*32];
__device__ __align__(8) __half2 g_filth[BB*NN*2];   // 4 filter dims as fp16
__device__ int    g_cidx[BB*MM];
__device__ float  g_cent[BB*MM*32];
__device__ int    g_bidx[2*BB*MM*64];
__device__ int    g_bcnt[2*BB*MM];
__device__ float  g_att[2*BB*MM*32];
__device__ float  g_h1[2*BB*MM*64];
__device__ float  g_h2[2*BB*MM*128];
__device__ float  g_s1a[2*64], g_s2a[2*64], g_s1b[2*128], g_s2b[2*128];
__device__ float  g_A1[2*64], g_C1[2*64], g_A2[2*128], g_C2[2*128];

__global__ void k_init() {
    int t = threadIdx.x;
    if (t < 128) { g_s1a[t] = 0.f; g_s2a[t] = 0.f; }
    if (t < 256) { g_s1b[t] = 0.f; g_s2b[t] = 0.f; }
}

// transpose [B,32,N] channel-major inputs -> point-major support + fp16 filter
__global__ __launch_bounds__(256) void k_build(const float* __restrict__ xyz,
                                               const float* __restrict__ pf) {
    __shared__ float t[32][33];
    int b  = blockIdx.x >> 9;
    int n0 = (blockIdx.x & 511) << 5;
    int tid = threadIdx.x;
#pragma unroll
    for (int i = 0; i < 4; i++) {
        int e = tid + i*256, c = e >> 5, n = e & 31;
        float v = (c < 3) ? xyz[(b*3 + c)*NN + n0 + n] : pf[(b*29 + (c-3))*NN + n0 + n];
        t[n][c] = v;
    }
    __syncthreads();
    int n = tid >> 3, c0 = (tid & 7) << 2;
    *(float4*)&g_support[((size_t)(b*NN + n0 + n))*32 + c0] =
        make_float4(t[n][c0], t[n][c0+1], t[n][c0+2], t[n][c0+3]);
    if (tid < 32) {
        __half2 h01 = __float22half2_rn(make_float2(t[tid][3], t[tid][4]));
        __half2 h23 = __float22half2_rn(make_float2(t[tid][5], t[tid][6]));
        uint2 u; memcpy(&u.x, &h01, 4); memcpy(&u.y, &h23, 4);
        ((uint2*)g_filth)[b*NN + n0 + tid] = u;
    }
}

__device__ __forceinline__ uint32_t smem_u32(const void* p) {
    uint32_t a;
    asm("{ .reg .u64 t; cvta.to.shared.u64 t, %1; cvt.u32.u64 %0, t; }" : "=r"(a) : "l"(p));
    return a;
}
__device__ __forceinline__ void remote_st(uint32_t laddr, uint32_t rank, unsigned long long v) {
    uint32_t ra;
    asm volatile("mapa.shared::cluster.u32 %0, %1, %2;" : "=r"(ra) : "r"(laddr), "r"(rank));
    asm volatile("st.relaxed.cluster.shared::cluster.u64 [%0], %1;" :: "r"(ra), "l"(v) : "memory");
}
__device__ __forceinline__ unsigned long long ldvol(const unsigned long long* p) {
    unsigned long long v;
    asm volatile("ld.volatile.shared.u64 %0, [%1];" : "=l"(v) : "r"(smem_u32(p)) : "memory");
    return v;
}
__device__ __forceinline__ void stvol(unsigned long long* p, unsigned long long v) {
    asm volatile("st.volatile.shared.u64 [%0], %1;" :: "r"(smem_u32(p)), "l"(v) : "memory");
}

// FPS: one 16-CTA cluster per batch, 512 thr/CTA, 2 pts/thread (f32x2 math).
// Sync v6: gen-tagged SMEM mailboxes + DSMEM remote pushes; no in-loop barriers.
__global__ void __launch_bounds__(512, 1) k_fps() {
    __shared__ unsigned long long sred[16];   // tagged warp candidates
    __shared__ unsigned long long slots[16];  // rank0 only: tagged CTA candidates
    __shared__ unsigned long long resw;       // tagged result word
    int b   = blockIdx.x >> 4;
    int crk = blockIdx.x & 15;
    int tid = threadIdx.x, wid = tid >> 5, lane = tid & 31;
    if (tid < 16) { sred[tid] = 0ull; slots[tid] = 0ull; }
    if (tid == 0) resw = 0ull;
    __syncthreads();
    asm volatile("barrier.cluster.arrive.aligned;" ::: "memory");
    asm volatile("barrier.cluster.wait.aligned;"   ::: "memory");
    int p0 = (crk << 9) + tid, p1 = p0 + 8192;
    unsigned long long nx0[16], nx1[16];
    {
        const float4* a = (const float4*)&g_support[(size_t)(b*NN + p0)*32];
        const float4* c = (const float4*)&g_support[(size_t)(b*NN + p1)*32];
#pragma unroll
        for (int i = 0; i < 8; i++) {
            float4 v = a[i], u = c[i];
            asm("mov.b64 %0, {%1, %2};" : "=l"(nx0[2*i])   : "f"(-v.x), "f"(-v.y));
            asm("mov.b64 %0, {%1, %2};" : "=l"(nx0[2*i+1]) : "f"(-v.z), "f"(-v.w));
            asm("mov.b64 %0, {%1, %2};" : "=l"(nx1[2*i])   : "f"(-u.x), "f"(-u.y));
            asm("mov.b64 %0, {%1, %2};" : "=l"(nx1[2*i+1]) : "f"(-u.z), "f"(-u.w));
        }
    }
    float d0 = 1e10f, d1 = 1e10f;
    int f = 0;
    if (crk == 0 && tid == 0) g_cidx[b*MM] = 0;
    uint32_t a_slots = smem_u32(slots);
    uint32_t a_res   = smem_u32(&resw);
    const unsigned long long M46 = (1ull << 46) - 1ull;
    for (int t = 0; t < MM; t++) {
        const ulonglong2* cp = (const ulonglong2*)&g_support[(size_t)(b*NN + f)*32];
        unsigned long long A01 = 0ull, A23 = 0ull, B01 = 0ull, B23 = 0ull;
#pragma unroll
        for (int i = 0; i < 8; i++) {
            ulonglong2 cv = cp[i];
            unsigned long long e;
            asm("add.rn.f32x2 %0, %1, %2;"     : "=l"(e)   : "l"(cv.x), "l"(nx0[2*i]));
            asm("fma.rn.f32x2 %0, %1, %2, %3;" : "=l"(A01) : "l"(e), "l"(e), "l"(A01));
            asm("add.rn.f32x2 %0, %1, %2;"     : "=l"(e)   : "l"(cv.y), "l"(nx0[2*i+1]));
            asm("fma.rn.f32x2 %0, %1, %2, %3;" : "=l"(A23) : "l"(e), "l"(e), "l"(A23));
            asm("add.rn.f32x2 %0, %1, %2;"     : "=l"(e)   : "l"(cv.x), "l"(nx1[2*i]));
            asm("fma.rn.f32x2 %0, %1, %2, %3;" : "=l"(B01) : "l"(e), "l"(e), "l"(B01));
            asm("add.rn.f32x2 %0, %1, %2;"     : "=l"(e)   : "l"(cv.y), "l"(nx1[2*i+1]));
            asm("fma.rn.f32x2 %0, %1, %2, %3;" : "=l"(B23) : "l"(e), "l"(e), "l"(B23));
        }
        float a0,a1,a2,a3;
        asm("mov.b64 {%0, %1}, %2;" : "=f"(a0), "=f"(a1) : "l"(A01));
        asm("mov.b64 {%0, %1}, %2;" : "=f"(a2), "=f"(a3) : "l"(A23));
        d0 = fminf(d0, (a0 + a1) + (a2 + a3));
        asm("mov.b64 {%0, %1}, %2;" : "=f"(a0), "=f"(a1) : "l"(B01));
        asm("mov.b64 {%0, %1}, %2;" : "=f"(a2), "=f"(a3) : "l"(B23));
        d1 = fminf(d1, (a0 + a1) + (a2 + a3));
        if (t == MM - 1) break;
        unsigned want = (unsigned)(t + 1);
        float dm; unsigned pi;
        if (d0 >= d1) { dm = d0; pi = (unsigned)p0; } else { dm = d1; pi = (unsigned)p1; }
        // tagged candidate: [gen:18][dist:32][inv_idx:14]; equal tags -> max == best payload
        unsigned long long pk = ((unsigned long long)want << 46)
                              | ((unsigned long long)__float_as_uint(dm) << 14)
                              | (unsigned long long)(16383u - pi);
#pragma unroll
        for (int o = 16; o; o >>= 1) {
            unsigned long long q = __shfl_down_sync(0xFFFFFFFFu, pk, o);
            if (q > pk) pk = q;
        }
        if (lane == 0) stvol(&sred[wid], pk);
        if (wid == 0) {
            unsigned long long v = 0ull;
            do { if (lane < 16) v = ldvol(&sred[lane]); }
            while (!__all_sync(0xFFFFFFFFu, lane >= 16 || (unsigned)(v >> 46) == want));
            if (lane >= 16) v = 0ull;
#pragma unroll
            for (int o = 8; o; o >>= 1) {
                unsigned long long q = __shfl_down_sync(0xFFFFFFFFu, v, o);
                if (q > v) v = q;
            }
            if (lane == 0) {
                if (crk == 0) stvol(&slots[0], v);
                else          remote_st(a_slots + crk*8u, 0u, v);
            }
        }
        if (crk == 0 && wid == 0) {
            unsigned long long v = 0ull;
            do { if (lane < 16) v = ldvol(&slots[lane]); }
            while (!__all_sync(0xFFFFFFFFu, lane >= 16 || (unsigned)(v >> 46) == want));
            if (lane >= 16) v = 0ull;
#pragma unroll
            for (int o = 8; o; o >>= 1) {
                unsigned long long q = __shfl_down_sync(0xFFFFFFFFu, v, o);
                if (q > v) v = q;
            }
            v = __shfl_sync(0xFFFFFFFFu, v, 0);
            int idx = 16383 - (int)(v & 16383ull);
            unsigned long long rv = ((unsigned long long)want << 32) | (unsigned)idx;
            if (lane == 0) g_cidx[b*MM + t + 1] = idx;
            if (lane < 16) {
                if (lane == 0) stvol(&resw, rv);
                else           remote_st(a_res, (uint32_t)lane, rv);
            }
        }
        unsigned long long r;
        do { r = ldvol(&resw); } while ((unsigned)(r >> 32) != want);
        f = (int)(unsigned)r;
    }
    // cluster must stay alive until all remote stores targeting it are done
    asm volatile("barrier.cluster.arrive.aligned;" ::: "memory");
    asm volatile("barrier.cluster.wait.aligned;"   ::: "memory");
}

__global__ __launch_bounds__(256) void k_gather(float* __restrict__ out) {
    int gt = blockIdx.x * 256 + threadIdx.x;
    int bm = gt >> 5, lane = gt & 31;
    int b = bm >> 10, m = bm & 1023;
    int ci = g_cidx[bm];
    float v = g_support[(size_t)(b*NN + ci)*32 + lane];
    g_cent[bm*32 + lane] = v;
    if (lane < 3) out[(b*3 + lane)*MM + m] = v;
}

// ball query BOTH scales in one scan: fp16 4-dim lower-bound prune (+0.01 margin),
// exact fp32 32-dim verify classifies into r=0.1 (k=32) and r=0.2 (k=64) lists.
__global__ __launch_bounds__(256) void k_ball2() {
    int w = threadIdx.x >> 5, lane = threadIdx.x & 31;
    int bm = blockIdx.x * 8 + w;
    int b = bm >> 10;
    const float* cen = &g_cent[bm*32];
    float c3 = cen[3], c4 = cen[4], c5 = cen[5], c6 = cen[6];
    int cnt0 = 0, cnt1 = 0;
    int* o0 = &g_bidx[(size_t)bm*64];
    int* o1 = &g_bidx[(size_t)(4096 + bm)*64];
    const uint2* filt = &((const uint2*)g_filth)[b*NN];
    const float R2S = 0.01f, R2L = 0.04f, TH = 0.04f + 0.01f;
    for (int it = 0; it < NN/32; it++) {
        int n = (it << 5) + lane;
        uint2 fv = filt[n];
        __half2 h01, h23;
        memcpy(&h01, &fv.x, 4); memcpy(&h23, &fv.y, 4);
        float2 f01 = __half22float2(h01), f23 = __half22float2(h23);
        float dx = f01.x - c3; float d4 = dx*dx;
        dx = f01.y - c4; d4 = fmaf(dx, dx, d4);
        dx = f23.x - c5; d4 = fmaf(dx, dx, d4);
        dx = f23.y - c6; d4 = fmaf(dx, dx, d4);
        bool p0 = false, p1 = false;
        if (d4 <= TH) {
            const float* pp = &g_support[(size_t)(b*NN + n)*32];
            float dd = 0.f;
#pragma unroll
            for (int i = 0; i < 32; i++) { float e = pp[i] - cen[i]; dd = fmaf(e, e, dd); }
            p1 = (dd <= R2L);
            p0 = (dd <= R2S);
        }
        unsigned bal1 = __ballot_sync(0xFFFFFFFFu, p1);
        unsigned bal0 = __ballot_sync(0xFFFFFFFFu, p0);
        while (bal1) {
            int l = __ffs(bal1) - 1; bal1 &= bal1 - 1;
            int idx = (it << 5) + l;
            if (cnt1 < 64) { if (lane == 0) o1[cnt1] = idx; cnt1++; }
            if (((bal0 >> l) & 1u) && cnt0 < 32) { if (lane == 0) o0[cnt0] = idx; cnt0++; }
        }
        if (cnt1 >= 64 && cnt0 >= 32) break;
    }
    if (lane == 0) { g_bcnt[bm] = cnt0; g_bcnt[4096 + bm] = cnt1; }
}

// attention over unmasked neighbors only (masked softmax weights are exactly 0)
__global__ __launch_bounds__(256) void k_att(const float* __restrict__ wq,
                                             const float* __restrict__ wk,
                                             const float* __restrict__ wv,
                                             const float* __restrict__ wo, int s) {
    __shared__ float s_q[32*64], s_k[32*64], s_v[32*64], s_oT[64*32];
    __shared__ float s_x[8][32], s_y[8][32], s_o[8][64], s_l[8][128];
    int tid = threadIdx.x;
    for (int i = tid; i < 2048; i += 256) {
        int oc = i >> 5, c = i & 31;
        s_q[c*64 + oc] = wq[i];
        s_k[c*64 + oc] = wk[i];
        s_v[c*64 + oc] = wv[i];
        int oc2 = i >> 6, c2 = i & 63;
        s_oT[c2*32 + oc2] = wo[i];
    }
    __syncthreads();
    int w = tid >> 5, lane = tid & 31;
    int bm = blockIdx.x * 8 + w;
    int b = bm >> 10;
    float xv = g_cent[bm*32 + lane];
    s_x[w][lane] = xv;
    __syncwarp();
    float q0 = 0.f, q1 = 0.f;
#pragma unroll
    for (int c = 0; c < 32; c++) {
        float xc = s_x[w][c];
        q0 = fmaf(s_q[c*64 + lane],      xc, q0);
        q1 = fmaf(s_q[c*64 + 32 + lane], xc, q1);
    }
    int cnt = g_bcnt[s*4096 + bm];
    const int* bidx = &g_bidx[(size_t)(s*4096 + bm)*64];
    const float rs = 0.17677669529663687f;  // 1/sqrt(32)
    for (int j = 0; j < cnt; j++) {
        int id = bidx[j];
        float yv = g_support[(size_t)(b*NN + id)*32 + lane] - s_x[w][lane];
        s_y[w][lane] = yv; __syncwarp();
        float k0 = 0.f, k1 = 0.f;
#pragma unroll
        for (int c = 0; c < 32; c++) {
            float yc = s_y[w][c];
            k0 = fmaf(s_k[c*64 + lane],      yc, k0);
            k1 = fmaf(s_k[c*64 + 32 + lane], yc, k1);
        }
        float l0 = q0*k0, l1 = q1*k1;
#pragma unroll
        for (int o = 16; o; o >>= 1) {
            l0 += __shfl_xor_sync(0xFFFFFFFFu, l0, o);
            l1 += __shfl_xor_sync(0xFFFFFFFFu, l1, o);
        }
        if (lane == 0) { s_l[w][j] = l0*rs; s_l[w][64 + j] = l1*rs; }
        __syncwarp();
    }
#pragma unroll
    for (int h = 0; h < 2; h++) {
        float v0 = (lane      < cnt) ? s_l[w][h*64 + lane]      : -3e38f;
        float v1 = (lane + 32 < cnt) ? s_l[w][h*64 + lane + 32] : -3e38f;
        float mx = fmaxf(v0, v1);
#pragma unroll
        for (int o = 16; o; o >>= 1) mx = fmaxf(mx, __shfl_xor_sync(0xFFFFFFFFu, mx, o));
        float e0 = (lane      < cnt) ? __expf(v0 - mx) : 0.f;
        float e1 = (lane + 32 < cnt) ? __expf(v1 - mx) : 0.f;
        float sm = e0 + e1;
#pragma unroll
        for (int o = 16; o; o >>= 1) sm += __shfl_xor_sync(0xFFFFFFFFu, sm, o);
        float inv = 1.f / sm;
        if (lane      < cnt) s_l[w][h*64 + lane]      = e0 * inv;
        if (lane + 32 < cnt) s_l[w][h*64 + lane + 32] = e1 * inv;
    }
    __syncwarp();
    float o0 = 0.f, o1 = 0.f;
    for (int j = 0; j < cnt; j++) {
        int id = bidx[j];
        float yv = g_support[(size_t)(b*NN + id)*32 + lane] - s_x[w][lane];
        s_y[w][lane] = yv; __syncwarp();
        float v0 = 0.f, v1 = 0.f;
#pragma unroll
        for (int c = 0; c < 32; c++) {
            float yc = s_y[w][c];
            v0 = fmaf(s_v[c*64 + lane],      yc, v0);
            v1 = fmaf(s_v[c*64 + 32 + lane], yc, v1);
        }
        o0 = fmaf(s_l[w][j],      v0, o0);
        o1 = fmaf(s_l[w][64 + j], v1, o1);
        __syncwarp();
    }
    s_o[w][lane] = o0; s_o[w][32 + lane] = o1; __syncwarp();
    float outv = s_x[w][lane];
#pragma unroll
    for (int c = 0; c < 64; c++) outv = fmaf(s_oT[c*32 + lane], s_o[w][c], outv);
    g_att[(size_t)(s*4096 + bm)*32 + lane] = outv;
}

__global__ __launch_bounds__(256) void k_mlp1(const float* __restrict__ W0,
                                              const float* __restrict__ b0, int s) {
    __shared__ float sW[32*64];
    __shared__ float s_in[4][32];
    __shared__ float sh[4][64];
    int tid = threadIdx.x;
    for (int i = tid; i < 2048; i += 256) { int oc = i >> 5, c = i & 31; sW[c*64 + oc] = W0[i]; }
    int bm0 = blockIdx.x * 4;
    if (tid < 128) s_in[tid >> 5][tid & 31] = g_att[(size_t)(s*4096 + bm0)*32 + tid];
    __syncthreads();
    int oc = tid & 63, q = tid >> 6;
    float h = b0[oc];
#pragma unroll
    for (int c = 0; c < 32; c++) h = fmaf(sW[c*64 + oc], s_in[q][c], h);
    g_h1[(size_t)(s*4096 + bm0 + q)*64 + oc] = h;
    sh[q][oc] = h;
    __syncthreads();
    if (q == 0) {
        float s1 = 0.f, s2 = 0.f;
#pragma unroll
        for (int qq = 0; qq < 4; qq++) { float v = sh[qq][oc]; s1 += v; s2 = fmaf(v, v, s2); }
        atomicAdd(&g_s1a[s*64 + oc], s1);
        atomicAdd(&g_s2a[s*64 + oc], s2);
    }
}

__global__ void k_fin1(const float* __restrict__ g, const float* __restrict__ beta, int s) {
    int oc = threadIdx.x;
    float mu  = g_s1a[s*64 + oc] * (1.f/4096.f);
    float var = g_s2a[s*64 + oc] * (1.f/4096.f) - mu*mu;
    float A = g[oc] * rsqrtf(var + 1e-5f);
    g_A1[s*64 + oc] = A;
    g_C1[s*64 + oc] = beta[oc] - mu*A;
}

__global__ __launch_bounds__(256) void k_mlp2(const float* __restrict__ W1,
                                              const float* __restrict__ b1, int s) {
    __shared__ float sW[64*128];
    __shared__ float sact[2][64];
    __shared__ float sh[2][128];
    int tid = threadIdx.x;
    for (int i = tid; i < 8192; i += 256) { int oc = i >> 6, c = i & 63; sW[c*128 + oc] = W1[i]; }
    int bm0 = blockIdx.x * 2;
    if (tid < 128) {
        int q = tid >> 6, c = tid & 63;
        float v = g_h1[(size_t)(s*4096 + bm0 + q)*64 + c];
        v = g_A1[s*64 + c]*v + g_C1[s*64 + c];
        sact[q][c] = v > 0.f ? v : 0.02f*v;
    }
    __syncthreads();
    int oc = tid & 127, q = tid >> 7;
    float h = b1[oc];
#pragma unroll
    for (int c = 0; c < 64; c++) h = fmaf(sW[c*128 + oc], sact[q][c], h);
    g_h2[(size_t)(s*4096 + bm0 + q)*128 + oc] = h;
    sh[q][oc] = h;
    __syncthreads();
    if (q == 0) {
        float a = sh[0][oc], bb = sh[1][oc];
        atomicAdd(&g_s1b[s*128 + oc], a + bb);
        atomicAdd(&g_s2b[s*128 + oc], fmaf(a, a, bb*bb));
    }
}

__global__ void k_fin2(const float* __restrict__ g, const float* __restrict__ beta, int s) {
    int oc = threadIdx.x;
    float mu  = g_s1b[s*128 + oc] * (1.f/4096.f);
    float var = g_s2b[s*128 + oc] * (1.f/4096.f) - mu*mu;
    float A = g[oc] * rsqrtf(var + 1e-5f);
    g_A2[s*128 + oc] = A;
    g_C2[s*128 + oc] = beta[oc] - mu*A;
}

__global__ __launch_bounds__(256) void k_out(float* __restrict__ out, int s) {
    int idx = blockIdx.x * 256 + threadIdx.x;
    int m = idx & 1023;
    int t2 = idx >> 10;
    int oc = t2 & 127, b = t2 >> 7;
    int bm = b*1024 + m;
    float v = g_h2[(size_t)(s*4096 + bm)*128 + oc];
    v = g_A2[s*128 + oc]*v + g_C2[s*128 + oc];
    out[12288 + (((b*256) + s*128 + oc) << 10) + m] = v;
}

extern "C" void kernel_launch(void* const* d_in, const int* in_sizes, int n_in,
                              void* d_out, int out_size) {
    (void)in_sizes; (void)n_in; (void)out_size;
    const float* xyz = (const float*)d_in[0];
    const float* pf  = (const float*)d_in[1];
    float* out = (float*)d_out;
    k_init<<<1, 256>>>();
    k_build<<<2048, 256>>>(xyz, pf);
    {
        cudaFuncSetAttribute(k_fps, cudaFuncAttributeNonPortableClusterSizeAllowed, 1);
        cudaLaunchConfig_t cfg = {};
        cfg.gridDim  = dim3(64, 1, 1);
        cfg.blockDim = dim3(512, 1, 1);
        cfg.dynamicSmemBytes = 0;
        cfg.stream = 0;
        cudaLaunchAttribute at[1];
        at[0].id = cudaLaunchAttributeClusterDimension;
        at[0].val.clusterDim.x = 16; at[0].val.clusterDim.y = 1; at[0].val.clusterDim.z = 1;
        cfg.attrs = at;
        cfg.numAttrs = 1;
        cudaLaunchKernelEx(&cfg, k_fps);
    }
    k_gather<<<512, 256>>>(out);
    k_ball2<<<512, 256>>>();
    for (int s = 0; s < 2; s++) {
        int o = 2 + s*12;
        k_att<<<512, 256>>>((const float*)d_in[o],   (const float*)d_in[o+1],
                            (const float*)d_in[o+2], (const float*)d_in[o+3], s);
        k_mlp1<<<1024, 256>>>((const float*)d_in[o+4], (const float*)d_in[o+5], s);
        k_fin1<<<1, 64>>>((const float*)d_in[o+6], (const float*)d_in[o+7], s);
        k_mlp2<<<2048, 256>>>((const float*)d_in[o+8], (const float*)d_in[o+9], s);
        k_fin2<<<1, 128>>>((const float*)d_in[o+10], (const float*)d_in[o+11], s);
        k_out<<<2048, 256>>>(out, s);
    }
}

// round 12
// speedup vs baseline: 4.0906x; 1.0818x over previous
#include <cuda_runtime.h>
#include <cuda_fp16.h>
#include <cstdint>
#include <cstring>

#define BB 4
#define NN 16384
#define MM 1024

// ---- static scratch (no allocation) ----
__device__ float  g_support[BB*NN*32];
__device__ __align__(8) __half2 g_filth[BB*NN*2];   // 4 filter dims as fp16
__device__ int    g_cidx[BB*MM];
__device__ float  g_cent[BB*MM*32];
__device__ int    g_bidx[2*BB*MM*64];
__device__ int    g_bcnt[2*BB*MM];
__device__ float  g_att[2*BB*MM*32];
__device__ float  g_h1[2*BB*MM*64];
__device__ float  g_h2[2*BB*MM*128];
__device__ float  g_s1a[2*64], g_s2a[2*64], g_s1b[2*128], g_s2b[2*128];
__device__ float  g_A1[2*64], g_C1[2*64], g_A2[2*128], g_C2[2*128];

__global__ void k_init() {
    int t = threadIdx.x;
    if (t < 128) { g_s1a[t] = 0.f; g_s2a[t] = 0.f; }
    if (t < 256) { g_s1b[t] = 0.f; g_s2b[t] = 0.f; }
}

// transpose [B,32,N] channel-major inputs -> point-major support + fp16 filter
__global__ __launch_bounds__(256) void k_build(const float* __restrict__ xyz,
                                               const float* __restrict__ pf) {
    __shared__ float t[32][33];
    int b  = blockIdx.x >> 9;
    int n0 = (blockIdx.x & 511) << 5;
    int tid = threadIdx.x;
#pragma unroll
    for (int i = 0; i < 4; i++) {
        int e = tid + i*256, c = e >> 5, n = e & 31;
        float v = (c < 3) ? xyz[(b*3 + c)*NN + n0 + n] : pf[(b*29 + (c-3))*NN + n0 + n];
        t[n][c] = v;
    }
    __syncthreads();
    int n = tid >> 3, c0 = (tid & 7) << 2;
    *(float4*)&g_support[((size_t)(b*NN + n0 + n))*32 + c0] =
        make_float4(t[n][c0], t[n][c0+1], t[n][c0+2], t[n][c0+3]);
    if (tid < 32) {
        __half2 h01 = __float22half2_rn(make_float2(t[tid][3], t[tid][4]));
        __half2 h23 = __float22half2_rn(make_float2(t[tid][5], t[tid][6]));
        uint2 u; memcpy(&u.x, &h01, 4); memcpy(&u.y, &h23, 4);
        ((uint2*)g_filth)[b*NN + n0 + tid] = u;
    }
}

__device__ __forceinline__ uint32_t smem_u32(const void* p) {
    uint32_t a;
    asm("{ .reg .u64 t; cvta.to.shared.u64 t, %1; cvt.u32.u64 %0, t; }" : "=r"(a) : "l"(p));
    return a;
}
__device__ __forceinline__ void remote_st(uint32_t laddr, uint32_t rank, unsigned long long v) {
    uint32_t ra;
    asm volatile("mapa.shared::cluster.u32 %0, %1, %2;" : "=r"(ra) : "r"(laddr), "r"(rank));
    asm volatile("st.relaxed.cluster.shared::cluster.u64 [%0], %1;" :: "r"(ra), "l"(v) : "memory");
}
__device__ __forceinline__ unsigned long long ldvol(const unsigned long long* p) {
    unsigned long long v;
    asm volatile("ld.volatile.shared.u64 %0, [%1];" : "=l"(v) : "r"(smem_u32(p)) : "memory");
    return v;
}
__device__ __forceinline__ void stvol(unsigned long long* p, unsigned long long v) {
    asm volatile("st.volatile.shared.u64 [%0], %1;" :: "r"(smem_u32(p)), "l"(v) : "memory");
}

// FPS: one 16-CTA cluster per batch, 512 thr/CTA, 2 pts/thread (f32x2 math).
// Sync v7: all-to-all DSMEM candidate exchange (single hop), parity-buffered,
// gen-tagged; every warp redundantly reduces the global argmax. No barriers.
__global__ void __launch_bounds__(512, 1) k_fps() {
    __shared__ unsigned long long sred[16];       // tagged warp candidates
    __shared__ unsigned long long slots[2][16];   // parity x rank: tagged CTA candidates
    int b   = blockIdx.x >> 4;
    int crk = blockIdx.x & 15;
    int tid = threadIdx.x, wid = tid >> 5, lane = tid & 31;
    if (tid < 16) { sred[tid] = 0ull; slots[0][tid] = 0ull; slots[1][tid] = 0ull; }
    __syncthreads();
    asm volatile("barrier.cluster.arrive.aligned;" ::: "memory");
    asm volatile("barrier.cluster.wait.aligned;"   ::: "memory");
    int p0 = (crk << 9) + tid, p1 = p0 + 8192;
    unsigned long long nx0[16], nx1[16];
    {
        const float4* a = (const float4*)&g_support[(size_t)(b*NN + p0)*32];
        const float4* c = (const float4*)&g_support[(size_t)(b*NN + p1)*32];
#pragma unroll
        for (int i = 0; i < 8; i++) {
            float4 v = a[i], u = c[i];
            asm("mov.b64 %0, {%1, %2};" : "=l"(nx0[2*i])   : "f"(-v.x), "f"(-v.y));
            asm("mov.b64 %0, {%1, %2};" : "=l"(nx0[2*i+1]) : "f"(-v.z), "f"(-v.w));
            asm("mov.b64 %0, {%1, %2};" : "=l"(nx1[2*i])   : "f"(-u.x), "f"(-u.y));
            asm("mov.b64 %0, {%1, %2};" : "=l"(nx1[2*i+1]) : "f"(-u.z), "f"(-u.w));
        }
    }
    float d0 = 1e10f, d1 = 1e10f;
    int f = 0;
    if (crk == 0 && tid == 0) g_cidx[b*MM] = 0;
    uint32_t a_slots = smem_u32(slots);
    for (int t = 0; t < MM; t++) {
        const ulonglong2* cp = (const ulonglong2*)&g_support[(size_t)(b*NN + f)*32];
        unsigned long long A01 = 0ull, A23 = 0ull, B01 = 0ull, B23 = 0ull;
#pragma unroll
        for (int i = 0; i < 8; i++) {
            ulonglong2 cv = cp[i];
            unsigned long long e;
            asm("add.rn.f32x2 %0, %1, %2;"     : "=l"(e)   : "l"(cv.x), "l"(nx0[2*i]));
            asm("fma.rn.f32x2 %0, %1, %2, %3;" : "=l"(A01) : "l"(e), "l"(e), "l"(A01));
            asm("add.rn.f32x2 %0, %1, %2;"     : "=l"(e)   : "l"(cv.y), "l"(nx0[2*i+1]));
            asm("fma.rn.f32x2 %0, %1, %2, %3;" : "=l"(A23) : "l"(e), "l"(e), "l"(A23));
            asm("add.rn.f32x2 %0, %1, %2;"     : "=l"(e)   : "l"(cv.x), "l"(nx1[2*i]));
            asm("fma.rn.f32x2 %0, %1, %2, %3;" : "=l"(B01) : "l"(e), "l"(e), "l"(B01));
            asm("add.rn.f32x2 %0, %1, %2;"     : "=l"(e)   : "l"(cv.y), "l"(nx1[2*i+1]));
            asm("fma.rn.f32x2 %0, %1, %2, %3;" : "=l"(B23) : "l"(e), "l"(e), "l"(B23));
        }
        float a0,a1,a2,a3;
        asm("mov.b64 {%0, %1}, %2;" : "=f"(a0), "=f"(a1) : "l"(A01));
        asm("mov.b64 {%0, %1}, %2;" : "=f"(a2), "=f"(a3) : "l"(A23));
        d0 = fminf(d0, (a0 + a1) + (a2 + a3));
        asm("mov.b64 {%0, %1}, %2;" : "=f"(a0), "=f"(a1) : "l"(B01));
        asm("mov.b64 {%0, %1}, %2;" : "=f"(a2), "=f"(a3) : "l"(B23));
        d1 = fminf(d1, (a0 + a1) + (a2 + a3));
        if (t == MM - 1) break;
        unsigned want = (unsigned)(t + 1);
        float dm; unsigned pi;
        if (d0 >= d1) { dm = d0; pi = (unsigned)p0; } else { dm = d1; pi = (unsigned)p1; }
        // tagged candidate: [gen:18][dist:32][inv_idx:14]
        unsigned long long pk = ((unsigned long long)want << 46)
                              | ((unsigned long long)__float_as_uint(dm) << 14)
                              | (unsigned long long)(16383u - pi);
#pragma unroll
        for (int o = 16; o; o >>= 1) {
            unsigned long long q = __shfl_down_sync(0xFFFFFFFFu, pk, o);
            if (q > pk) pk = q;
        }
        if (lane == 0) stvol(&sred[wid], pk);
        if (wid == 0) {
            // aggregate CTA candidate, push to every rank's slot (single hop)
            unsigned long long v = 0ull;
            do { if (lane < 16) v = ldvol(&sred[lane]); }
            while (!__all_sync(0xFFFFFFFFu, lane >= 16 || (unsigned)(v >> 46) == want));
            if (lane >= 16) v = 0ull;
#pragma unroll
            for (int o = 8; o; o >>= 1) {
                unsigned long long q = __shfl_down_sync(0xFFFFFFFFu, v, o);
                if (q > v) v = q;
            }
            v = __shfl_sync(0xFFFFFFFFu, v, 0);
            if (lane < 16)
                remote_st(a_slots + (((want & 1u)*16u + (unsigned)crk) << 3), (uint32_t)lane, v);
        }
        // every warp polls local slots and reduces the global argmax
        {
            unsigned long long v = 0ull;
            const unsigned long long* sl = slots[want & 1];
            do { if (lane < 16) v = ldvol(&sl[lane]); }
            while (!__all_sync(0xFFFFFFFFu, lane >= 16 || (unsigned)(v >> 46) == want));
            if (lane >= 16) v = 0ull;
#pragma unroll
            for (int o = 8; o; o >>= 1) {
                unsigned long long q = __shfl_down_sync(0xFFFFFFFFu, v, o);
                if (q > v) v = q;
            }
            v = __shfl_sync(0xFFFFFFFFu, v, 0);
            f = 16383 - (int)(v & 16383ull);
        }
        if (crk == 0 && tid == 0) g_cidx[b*MM + t + 1] = f;
    }
    // cluster must stay alive until all remote stores targeting it are done
    asm volatile("barrier.cluster.arrive.aligned;" ::: "memory");
    asm volatile("barrier.cluster.wait.aligned;"   ::: "memory");
}

__global__ __launch_bounds__(256) void k_gather(float* __restrict__ out) {
    int gt = blockIdx.x * 256 + threadIdx.x;
    int bm = gt >> 5, lane = gt & 31;
    int b = bm >> 10, m = bm & 1023;
    int ci = g_cidx[bm];
    float v = g_support[(size_t)(b*NN + ci)*32 + lane];
    g_cent[bm*32 + lane] = v;
    if (lane < 3) out[(b*3 + lane)*MM + m] = v;
}

// ball query BOTH scales in one scan: fp16 4-dim lower-bound prune (+0.01 margin),
// exact fp32 32-dim verify classifies into r=0.1 (k=32) and r=0.2 (k=64) lists.
__global__ __launch_bounds__(256) void k_ball2() {
    int w = threadIdx.x >> 5, lane = threadIdx.x & 31;
    int bm = blockIdx.x * 8 + w;
    int b = bm >> 10;
    const float* cen = &g_cent[bm*32];
    float c3 = cen[3], c4 = cen[4], c5 = cen[5], c6 = cen[6];
    int cnt0 = 0, cnt1 = 0;
    int* o0 = &g_bidx[(size_t)bm*64];
    int* o1 = &g_bidx[(size_t)(4096 + bm)*64];
    const uint2* filt = &((const uint2*)g_filth)[b*NN];
    const float R2S = 0.01f, R2L = 0.04f, TH = 0.04f + 0.01f;
    for (int it = 0; it < NN/32; it++) {
        int n = (it << 5) + lane;
        uint2 fv = filt[n];
        __half2 h01, h23;
        memcpy(&h01, &fv.x, 4); memcpy(&h23, &fv.y, 4);
        float2 f01 = __half22float2(h01), f23 = __half22float2(h23);
        float dx = f01.x - c3; float d4 = dx*dx;
        dx = f01.y - c4; d4 = fmaf(dx, dx, d4);
        dx = f23.x - c5; d4 = fmaf(dx, dx, d4);
        dx = f23.y - c6; d4 = fmaf(dx, dx, d4);
        bool p0 = false, p1 = false;
        if (d4 <= TH) {
            const float* pp = &g_support[(size_t)(b*NN + n)*32];
            float dd = 0.f;
#pragma unroll
            for (int i = 0; i < 32; i++) { float e = pp[i] - cen[i]; dd = fmaf(e, e, dd); }
            p1 = (dd <= R2L);
            p0 = (dd <= R2S);
        }
        unsigned bal1 = __ballot_sync(0xFFFFFFFFu, p1);
        unsigned bal0 = __ballot_sync(0xFFFFFFFFu, p0);
        while (bal1) {
            int l = __ffs(bal1) - 1; bal1 &= bal1 - 1;
            int idx = (it << 5) + l;
            if (cnt1 < 64) { if (lane == 0) o1[cnt1] = idx; cnt1++; }
            if (((bal0 >> l) & 1u) && cnt0 < 32) { if (lane == 0) o0[cnt0] = idx; cnt0++; }
        }
        if (cnt1 >= 64 && cnt0 >= 32) break;
    }
    if (lane == 0) { g_bcnt[bm] = cnt0; g_bcnt[4096 + bm] = cnt1; }
}

// attention over unmasked neighbors only (masked softmax weights are exactly 0)
__global__ __launch_bounds__(256) void k_att(const float* __restrict__ wq,
                                             const float* __restrict__ wk,
                                             const float* __restrict__ wv,
                                             const float* __restrict__ wo, int s) {
    __shared__ float s_q[32*64], s_k[32*64], s_v[32*64], s_oT[64*32];
    __shared__ float s_x[8][32], s_y[8][32], s_o[8][64], s_l[8][128];
    int tid = threadIdx.x;
    for (int i = tid; i < 2048; i += 256) {
        int oc = i >> 5, c = i & 31;
        s_q[c*64 + oc] = wq[i];
        s_k[c*64 + oc] = wk[i];
        s_v[c*64 + oc] = wv[i];
        int oc2 = i >> 6, c2 = i & 63;
        s_oT[c2*32 + oc2] = wo[i];
    }
    __syncthreads();
    int w = tid >> 5, lane = tid & 31;
    int bm = blockIdx.x * 8 + w;
    int b = bm >> 10;
    float xv = g_cent[bm*32 + lane];
    s_x[w][lane] = xv;
    __syncwarp();
    float q0 = 0.f, q1 = 0.f;
#pragma unroll
    for (int c = 0; c < 32; c++) {
        float xc = s_x[w][c];
        q0 = fmaf(s_q[c*64 + lane],      xc, q0);
        q1 = fmaf(s_q[c*64 + 32 + lane], xc, q1);
    }
    int cnt = g_bcnt[s*4096 + bm];
    const int* bidx = &g_bidx[(size_t)(s*4096 + bm)*64];
    const float rs = 0.17677669529663687f;  // 1/sqrt(32)
    for (int j = 0; j < cnt; j++) {
        int id = bidx[j];
        float yv = g_support[(size_t)(b*NN + id)*32 + lane] - s_x[w][lane];
        s_y[w][lane] = yv; __syncwarp();
        float k0 = 0.f, k1 = 0.f;
#pragma unroll
        for (int c = 0; c < 32; c++) {
            float yc = s_y[w][c];
            k0 = fmaf(s_k[c*64 + lane],      yc, k0);
            k1 = fmaf(s_k[c*64 + 32 + lane], yc, k1);
        }
        float l0 = q0*k0, l1 = q1*k1;
#pragma unroll
        for (int o = 16; o; o >>= 1) {
            l0 += __shfl_xor_sync(0xFFFFFFFFu, l0, o);
            l1 += __shfl_xor_sync(0xFFFFFFFFu, l1, o);
        }
        if (lane == 0) { s_l[w][j] = l0*rs; s_l[w][64 + j] = l1*rs; }
        __syncwarp();
    }
#pragma unroll
    for (int h = 0; h < 2; h++) {
        float v0 = (lane      < cnt) ? s_l[w][h*64 + lane]      : -3e38f;
        float v1 = (lane + 32 < cnt) ? s_l[w][h*64 + lane + 32] : -3e38f;
        float mx = fmaxf(v0, v1);
#pragma unroll
        for (int o = 16; o; o >>= 1) mx = fmaxf(mx, __shfl_xor_sync(0xFFFFFFFFu, mx, o));
        float e0 = (lane      < cnt) ? __expf(v0 - mx) : 0.f;
        float e1 = (lane + 32 < cnt) ? __expf(v1 - mx) : 0.f;
        float sm = e0 + e1;
#pragma unroll
        for (int o = 16; o; o >>= 1) sm += __shfl_xor_sync(0xFFFFFFFFu, sm, o);
        float inv = 1.f / sm;
        if (lane      < cnt) s_l[w][h*64 + lane]      = e0 * inv;
        if (lane + 32 < cnt) s_l[w][h*64 + lane + 32] = e1 * inv;
    }
    __syncwarp();
    float o0 = 0.f, o1 = 0.f;
    for (int j = 0; j < cnt; j++) {
        int id = bidx[j];
        float yv = g_support[(size_t)(b*NN + id)*32 + lane] - s_x[w][lane];
        s_y[w][lane] = yv; __syncwarp();
        float v0 = 0.f, v1 = 0.f;
#pragma unroll
        for (int c = 0; c < 32; c++) {
            float yc = s_y[w][c];
            v0 = fmaf(s_v[c*64 + lane],      yc, v0);
            v1 = fmaf(s_v[c*64 + 32 + lane], yc, v1);
        }
        o0 = fmaf(s_l[w][j],      v0, o0);
        o1 = fmaf(s_l[w][64 + j], v1, o1);
        __syncwarp();
    }
    s_o[w][lane] = o0; s_o[w][32 + lane] = o1; __syncwarp();
    float outv = s_x[w][lane];
#pragma unroll
    for (int c = 0; c < 64; c++) outv = fmaf(s_oT[c*32 + lane], s_o[w][c], outv);
    g_att[(size_t)(s*4096 + bm)*32 + lane] = outv;
}

__global__ __launch_bounds__(256) void k_mlp1(const float* __restrict__ W0,
                                              const float* __restrict__ b0, int s) {
    __shared__ float sW[32*64];
    __shared__ float s_in[4][32];
    __shared__ float sh[4][64];
    int tid = threadIdx.x;
    for (int i = tid; i < 2048; i += 256) { int oc = i >> 5, c = i & 31; sW[c*64 + oc] = W0[i]; }
    int bm0 = blockIdx.x * 4;
    if (tid < 128) s_in[tid >> 5][tid & 31] = g_att[(size_t)(s*4096 + bm0)*32 + tid];
    __syncthreads();
    int oc = tid & 63, q = tid >> 6;
    float h = b0[oc];
#pragma unroll
    for (int c = 0; c < 32; c++) h = fmaf(sW[c*64 + oc], s_in[q][c], h);
    g_h1[(size_t)(s*4096 + bm0 + q)*64 + oc] = h;
    sh[q][oc] = h;
    __syncthreads();
    if (q == 0) {
        float s1 = 0.f, s2 = 0.f;
#pragma unroll
        for (int qq = 0; qq < 4; qq++) { float v = sh[qq][oc]; s1 += v; s2 = fmaf(v, v, s2); }
        atomicAdd(&g_s1a[s*64 + oc], s1);
        atomicAdd(&g_s2a[s*64 + oc], s2);
    }
}

__global__ void k_fin1(const float* __restrict__ g, const float* __restrict__ beta, int s) {
    int oc = threadIdx.x;
    float mu  = g_s1a[s*64 + oc] * (1.f/4096.f);
    float var = g_s2a[s*64 + oc] * (1.f/4096.f) - mu*mu;
    float A = g[oc] * rsqrtf(var + 1e-5f);
    g_A1[s*64 + oc] = A;
    g_C1[s*64 + oc] = beta[oc] - mu*A;
}

__global__ __launch_bounds__(256) void k_mlp2(const float* __restrict__ W1,
                                              const float* __restrict__ b1, int s) {
    __shared__ float sW[64*128];
    __shared__ float sact[2][64];
    __shared__ float sh[2][128];
    int tid = threadIdx.x;
    for (int i = tid; i < 8192; i += 256) { int oc = i >> 6, c = i & 63; sW[c*128 + oc] = W1[i]; }
    int bm0 = blockIdx.x * 2;
    if (tid < 128) {
        int q = tid >> 6, c = tid & 63;
        float v = g_h1[(size_t)(s*4096 + bm0 + q)*64 + c];
        v = g_A1[s*64 + c]*v + g_C1[s*64 + c];
        sact[q][c] = v > 0.f ? v : 0.02f*v;
    }
    __syncthreads();
    int oc = tid & 127, q = tid >> 7;
    float h = b1[oc];
#pragma unroll
    for (int c = 0; c < 64; c++) h = fmaf(sW[c*128 + oc], sact[q][c], h);
    g_h2[(size_t)(s*4096 + bm0 + q)*128 + oc] = h;
    sh[q][oc] = h;
    __syncthreads();
    if (q == 0) {
        float a = sh[0][oc], bb = sh[1][oc];
        atomicAdd(&g_s1b[s*128 + oc], a + bb);
        atomicAdd(&g_s2b[s*128 + oc], fmaf(a, a, bb*bb));
    }
}

__global__ void k_fin2(const float* __restrict__ g, const float* __restrict__ beta, int s) {
    int oc = threadIdx.x;
    float mu  = g_s1b[s*128 + oc] * (1.f/4096.f);
    float var = g_s2b[s*128 + oc] * (1.f/4096.f) - mu*mu;
    float A = g[oc] * rsqrtf(var + 1e-5f);
    g_A2[s*128 + oc] = A;
    g_C2[s*128 + oc] = beta[oc] - mu*A;
}

__global__ __launch_bounds__(256) void k_out(float* __restrict__ out, int s) {
    int idx = blockIdx.x * 256 + threadIdx.x;
    int m = idx & 1023;
    int t2 = idx >> 10;
    int oc = t2 & 127, b = t2 >> 7;
    int bm = b*1024 + m;
    float v = g_h2[(size_t)(s*4096 + bm)*128 + oc];
    v = g_A2[s*128 + oc]*v + g_C2[s*128 + oc];
    out[12288 + (((b*256) + s*128 + oc) << 10) + m] = v;
}

extern "C" void kernel_launch(void* const* d_in, const int* in_sizes, int n_in,
                              void* d_out, int out_size) {
    (void)in_sizes; (void)n_in; (void)out_size;
    const float* xyz = (const float*)d_in[0];
    const float* pf  = (const float*)d_in[1];
    float* out = (float*)d_out;
    k_init<<<1, 256>>>();
    k_build<<<2048, 256>>>(xyz, pf);
    {
        cudaFuncSetAttribute(k_fps, cudaFuncAttributeNonPortableClusterSizeAllowed, 1);
        cudaLaunchConfig_t cfg = {};
        cfg.gridDim  = dim3(64, 1, 1);
        cfg.blockDim = dim3(512, 1, 1);
        cfg.dynamicSmemBytes = 0;
        cfg.stream = 0;
        cudaLaunchAttribute at[1];
        at[0].id = cudaLaunchAttributeClusterDimension;
        at[0].val.clusterDim.x = 16; at[0].val.clusterDim.y = 1; at[0].val.clusterDim.z = 1;
        cfg.attrs = at;
        cfg.numAttrs = 1;
        cudaLaunchKernelEx(&cfg, k_fps);
    }
    k_gather<<<512, 256>>>(out);
    k_ball2<<<512, 256>>>();
    for (int s = 0; s < 2; s++) {
        int o = 2 + s*12;
        k_att<<<512, 256>>>((const float*)d_in[o],   (const float*)d_in[o+1],
                            (const float*)d_in[o+2], (const float*)d_in[o+3], s);
        k_mlp1<<<1024, 256>>>((const float*)d_in[o+4], (const float*)d_in[o+5], s);
        k_fin1<<<1, 64>>>((const float*)d_in[o+6], (const float*)d_in[o+7], s);
        k_mlp2<<<2048, 256>>>((const float*)d_in[o+8], (const float*)d_in[o+9], s);
        k_fin2<<<1, 128>>>((const float*)d_in[o+10], (const float*)d_in[o+11], s);
        k_out<<<2048, 256>>>(out, s);
    }
}

// round 13
// speedup vs baseline: 4.3094x; 1.0535x over previous
#include <cuda_runtime.h>
#include <cuda_fp16.h>
#include <cstdint>
#include <cstring>

#define BB 4
#define NN 16384
#define MM 1024

// ---- static scratch (no allocation) ----
__device__ float  g_support[BB*NN*32];
__device__ __align__(8) __half2 g_filth[BB*NN*2];   // 4 filter dims as fp16
__device__ float  g_cent[BB*MM*32];
__device__ int    g_bidx[2*BB*MM*64];
__device__ int    g_bcnt[2*BB*MM];
__device__ float  g_att[2*BB*MM*32];
__device__ float  g_h1[2*BB*MM*64];
__device__ float  g_h2[2*BB*MM*128];
__device__ float  g_s1a[2*64], g_s2a[2*64], g_s1b[2*128], g_s2b[2*128];
__device__ float  g_A1[2*64], g_C1[2*64], g_A2[2*128], g_C2[2*128];

__global__ void k_init() {
    int t = threadIdx.x;
    if (t < 128) { g_s1a[t] = 0.f; g_s2a[t] = 0.f; }
    if (t < 256) { g_s1b[t] = 0.f; g_s2b[t] = 0.f; }
}

// transpose [B,32,N] channel-major inputs -> point-major support + fp16 filter
__global__ __launch_bounds__(256) void k_build(const float* __restrict__ xyz,
                                               const float* __restrict__ pf) {
    __shared__ float t[32][33];
    int b  = blockIdx.x >> 9;
    int n0 = (blockIdx.x & 511) << 5;
    int tid = threadIdx.x;
#pragma unroll
    for (int i = 0; i < 4; i++) {
        int e = tid + i*256, c = e >> 5, n = e & 31;
        float v = (c < 3) ? xyz[(b*3 + c)*NN + n0 + n] : pf[(b*29 + (c-3))*NN + n0 + n];
        t[n][c] = v;
    }
    __syncthreads();
    int n = tid >> 3, c0 = (tid & 7) << 2;
    *(float4*)&g_support[((size_t)(b*NN + n0 + n))*32 + c0] =
        make_float4(t[n][c0], t[n][c0+1], t[n][c0+2], t[n][c0+3]);
    if (tid < 32) {
        __half2 h01 = __float22half2_rn(make_float2(t[tid][3], t[tid][4]));
        __half2 h23 = __float22half2_rn(make_float2(t[tid][5], t[tid][6]));
        uint2 u; memcpy(&u.x, &h01, 4); memcpy(&u.y, &h23, 4);
        ((uint2*)g_filth)[b*NN + n0 + tid] = u;
    }
}

__device__ __forceinline__ uint32_t smem_u32(const void* p) {
    uint32_t a;
    asm("{ .reg .u64 t; cvta.to.shared.u64 t, %1; cvt.u32.u64 %0, t; }" : "=r"(a) : "l"(p));
    return a;
}
__device__ __forceinline__ void remote_st(uint32_t laddr, uint32_t rank, unsigned long long v) {
    uint32_t ra;
    asm volatile("mapa.shared::cluster.u32 %0, %1, %2;" : "=r"(ra) : "r"(laddr), "r"(rank));
    asm volatile("st.relaxed.cluster.shared::cluster.u64 [%0], %1;" :: "r"(ra), "l"(v) : "memory");
}
__device__ __forceinline__ unsigned long long ldvol(const unsigned long long* p) {
    unsigned long long v;
    asm volatile("ld.volatile.shared.u64 %0, [%1];" : "=l"(v) : "r"(smem_u32(p)) : "memory");
    return v;
}

// FPS: one 16-CTA cluster per batch, 512 thr/CTA, 2 pts/thread (f32x2 math).
// Sync v8: bar.sync intra-CTA; all-to-all DSMEM exchange (as R12) cross-CTA.
// Winning point's owner thread writes the centroid + new_xyz inline.
__global__ void __launch_bounds__(512, 1) k_fps(float* __restrict__ out) {
    __shared__ unsigned long long sred[16];       // untagged warp candidates
    __shared__ unsigned long long slots[2][16];   // parity x rank: tagged CTA candidates
    int b   = blockIdx.x >> 4;
    int crk = blockIdx.x & 15;
    int tid = threadIdx.x, wid = tid >> 5, lane = tid & 31;
    if (tid < 16) { slots[0][tid] = 0ull; slots[1][tid] = 0ull; }
    __syncthreads();
    asm volatile("barrier.cluster.arrive.aligned;" ::: "memory");
    asm volatile("barrier.cluster.wait.aligned;"   ::: "memory");
    int p0 = (crk << 9) + tid, p1 = p0 + 8192;
    unsigned long long nx0[16], nx1[16];
    {
        const float4* a = (const float4*)&g_support[(size_t)(b*NN + p0)*32];
        const float4* c = (const float4*)&g_support[(size_t)(b*NN + p1)*32];
#pragma unroll
        for (int i = 0; i < 8; i++) {
            float4 v = a[i], u = c[i];
            asm("mov.b64 %0, {%1, %2};" : "=l"(nx0[2*i])   : "f"(-v.x), "f"(-v.y));
            asm("mov.b64 %0, {%1, %2};" : "=l"(nx0[2*i+1]) : "f"(-v.z), "f"(-v.w));
            asm("mov.b64 %0, {%1, %2};" : "=l"(nx1[2*i])   : "f"(-u.x), "f"(-u.y));
            asm("mov.b64 %0, {%1, %2};" : "=l"(nx1[2*i+1]) : "f"(-u.z), "f"(-u.w));
        }
    }
    float d0 = 1e10f, d1 = 1e10f;
    int f = 0;
    // centroid m=0 is point 0: owner is crk0/tid0/half0
    if (crk == 0 && tid == 0) {
        float2* dst = (float2*)&g_cent[(size_t)b*MM*32];
#pragma unroll
        for (int i = 0; i < 16; i++) {
            float lo, hi;
            asm("mov.b64 {%0, %1}, %2;" : "=f"(lo), "=f"(hi) : "l"(nx0[i]));
            dst[i] = make_float2(-lo, -hi);
        }
        float l0, h0, l1, h1;
        asm("mov.b64 {%0, %1}, %2;" : "=f"(l0), "=f"(h0) : "l"(nx0[0]));
        asm("mov.b64 {%0, %1}, %2;" : "=f"(l1), "=f"(h1) : "l"(nx0[1]));
        out[(b*3 + 0)*MM] = -l0; out[(b*3 + 1)*MM] = -h0; out[(b*3 + 2)*MM] = -l1;
    }
    uint32_t a_slots = smem_u32(slots);
    for (int t = 0; t < MM; t++) {
        const ulonglong2* cp = (const ulonglong2*)&g_support[(size_t)(b*NN + f)*32];
        unsigned long long A01 = 0ull, A23 = 0ull, B01 = 0ull, B23 = 0ull;
#pragma unroll
        for (int i = 0; i < 8; i++) {
            ulonglong2 cv = cp[i];
            unsigned long long e;
            asm("add.rn.f32x2 %0, %1, %2;"     : "=l"(e)   : "l"(cv.x), "l"(nx0[2*i]));
            asm("fma.rn.f32x2 %0, %1, %2, %3;" : "=l"(A01) : "l"(e), "l"(e), "l"(A01));
            asm("add.rn.f32x2 %0, %1, %2;"     : "=l"(e)   : "l"(cv.y), "l"(nx0[2*i+1]));
            asm("fma.rn.f32x2 %0, %1, %2, %3;" : "=l"(A23) : "l"(e), "l"(e), "l"(A23));
            asm("add.rn.f32x2 %0, %1, %2;"     : "=l"(e)   : "l"(cv.x), "l"(nx1[2*i]));
            asm("fma.rn.f32x2 %0, %1, %2, %3;" : "=l"(B01) : "l"(e), "l"(e), "l"(B01));
            asm("add.rn.f32x2 %0, %1, %2;"     : "=l"(e)   : "l"(cv.y), "l"(nx1[2*i+1]));
            asm("fma.rn.f32x2 %0, %1, %2, %3;" : "=l"(B23) : "l"(e), "l"(e), "l"(B23));
        }
        float a0,a1,a2,a3;
        asm("mov.b64 {%0, %1}, %2;" : "=f"(a0), "=f"(a1) : "l"(A01));
        asm("mov.b64 {%0, %1}, %2;" : "=f"(a2), "=f"(a3) : "l"(A23));
        d0 = fminf(d0, (a0 + a1) + (a2 + a3));
        asm("mov.b64 {%0, %1}, %2;" : "=f"(a0), "=f"(a1) : "l"(B01));
        asm("mov.b64 {%0, %1}, %2;" : "=f"(a2), "=f"(a3) : "l"(B23));
        d1 = fminf(d1, (a0 + a1) + (a2 + a3));
        if (t == MM - 1) break;
        unsigned want = (unsigned)(t + 1);
        float dm; unsigned pi;
        if (d0 >= d1) { dm = d0; pi = (unsigned)p0; } else { dm = d1; pi = (unsigned)p1; }
        unsigned long long pk = ((unsigned long long)__float_as_uint(dm) << 14)
                              | (unsigned long long)(16383u - pi);   // tie -> lowest idx
#pragma unroll
        for (int o = 16; o; o >>= 1) {
            unsigned long long q = __shfl_down_sync(0xFFFFFFFFu, pk, o);
            if (q > pk) pk = q;
        }
        if (lane == 0) sred[wid] = pk;
        __syncthreads();
        if (wid == 0) {
            unsigned long long v = (lane < 16) ? sred[lane] : 0ull;
#pragma unroll
            for (int o = 8; o; o >>= 1) {
                unsigned long long q = __shfl_down_sync(0xFFFFFFFFu, v, o);
                if (q > v) v = q;
            }
            v = __shfl_sync(0xFFFFFFFFu, v, 0) | ((unsigned long long)want << 46);
            if (lane < 16)
                remote_st(a_slots + (((want & 1u)*16u + (unsigned)crk) << 3), (uint32_t)lane, v);
        }
        // every warp polls local slots and reduces the global argmax
        {
            unsigned long long v = 0ull;
            const unsigned long long* sl = slots[want & 1];
            do { if (lane < 16) v = ldvol(&sl[lane]); }
            while (!__all_sync(0xFFFFFFFFu, lane >= 16 || (unsigned)(v >> 46) == want));
            if (lane >= 16) v = 0ull;
#pragma unroll
            for (int o = 8; o; o >>= 1) {
                unsigned long long q = __shfl_down_sync(0xFFFFFFFFu, v, o);
                if (q > v) v = q;
            }
            v = __shfl_sync(0xFFFFFFFFu, v, 0);
            f = 16383 - (int)(v & 16383ull);
        }
        // owner thread writes centroid m = t+1 (off critical path)
        {
            int half = f >> 13, rest = f & 8191;
            if ((rest >> 9) == crk && (rest & 511) == tid) {
                float2* dst = (float2*)&g_cent[(size_t)(b*MM + t + 1)*32];
                float x0v, x1v, x2v;
                if (half == 0) {
#pragma unroll
                    for (int i = 0; i < 16; i++) {
                        float lo, hi;
                        asm("mov.b64 {%0, %1}, %2;" : "=f"(lo), "=f"(hi) : "l"(nx0[i]));
                        dst[i] = make_float2(-lo, -hi);
                    }
                    float lo, hi;
                    asm("mov.b64 {%0, %1}, %2;" : "=f"(lo), "=f"(hi) : "l"(nx0[0]));
                    x0v = -lo; x1v = -hi;
                    asm("mov.b64 {%0, %1}, %2;" : "=f"(lo), "=f"(hi) : "l"(nx0[1]));
                    x2v = -lo;
                } else {
#pragma unroll
                    for (int i = 0; i < 16; i++) {
                        float lo, hi;
                        asm("mov.b64 {%0, %1}, %2;" : "=f"(lo), "=f"(hi) : "l"(nx1[i]));
                        dst[i] = make_float2(-lo, -hi);
                    }
                    float lo, hi;
                    asm("mov.b64 {%0, %1}, %2;" : "=f"(lo), "=f"(hi) : "l"(nx1[0]));
                    x0v = -lo; x1v = -hi;
                    asm("mov.b64 {%0, %1}, %2;" : "=f"(lo), "=f"(hi) : "l"(nx1[1]));
                    x2v = -lo;
                }
                int m = t + 1;
                out[(b*3 + 0)*MM + m] = x0v;
                out[(b*3 + 1)*MM + m] = x1v;
                out[(b*3 + 2)*MM + m] = x2v;
            }
        }
    }
    asm volatile("barrier.cluster.arrive.aligned;" ::: "memory");
    asm volatile("barrier.cluster.wait.aligned;"   ::: "memory");
}

// ball query BOTH scales in one scan: fp16 4-dim lower-bound prune (+0.01 margin),
// exact fp32 32-dim verify classifies into r=0.1 (k=32) and r=0.2 (k=64) lists.
__global__ __launch_bounds__(256) void k_ball2() {
    int w = threadIdx.x >> 5, lane = threadIdx.x & 31;
    int bm = blockIdx.x * 8 + w;
    int b = bm >> 10;
    const float* cen = &g_cent[bm*32];
    float c3 = cen[3], c4 = cen[4], c5 = cen[5], c6 = cen[6];
    int cnt0 = 0, cnt1 = 0;
    int* o0 = &g_bidx[(size_t)bm*64];
    int* o1 = &g_bidx[(size_t)(4096 + bm)*64];
    const uint2* filt = &((const uint2*)g_filth)[b*NN];
    const float R2S = 0.01f, R2L = 0.04f, TH = 0.04f + 0.01f;
    for (int it = 0; it < NN/32; it++) {
        int n = (it << 5) + lane;
        uint2 fv = filt[n];
        __half2 h01, h23;
        memcpy(&h01, &fv.x, 4); memcpy(&h23, &fv.y, 4);
        float2 f01 = __half22float2(h01), f23 = __half22float2(h23);
        float dx = f01.x - c3; float d4 = dx*dx;
        dx = f01.y - c4; d4 = fmaf(dx, dx, d4);
        dx = f23.x - c5; d4 = fmaf(dx, dx, d4);
        dx = f23.y - c6; d4 = fmaf(dx, dx, d4);
        bool p0 = false, p1 = false;
        if (d4 <= TH) {
            const float* pp = &g_support[(size_t)(b*NN + n)*32];
            float dd = 0.f;
#pragma unroll
            for (int i = 0; i < 32; i++) { float e = pp[i] - cen[i]; dd = fmaf(e, e, dd); }
            p1 = (dd <= R2L);
            p0 = (dd <= R2S);
        }
        unsigned bal1 = __ballot_sync(0xFFFFFFFFu, p1);
        unsigned bal0 = __ballot_sync(0xFFFFFFFFu, p0);
        while (bal1) {
            int l = __ffs(bal1) - 1; bal1 &= bal1 - 1;
            int idx = (it << 5) + l;
            if (cnt1 < 64) { if (lane == 0) o1[cnt1] = idx; cnt1++; }
            if (((bal0 >> l) & 1u) && cnt0 < 32) { if (lane == 0) o0[cnt0] = idx; cnt0++; }
        }
        if (cnt1 >= 64 && cnt0 >= 32) break;
    }
    if (lane == 0) { g_bcnt[bm] = cnt0; g_bcnt[4096 + bm] = cnt1; }
}

// attention over unmasked neighbors only; both scales in one launch (grid 1024)
__global__ __launch_bounds__(256) void k_att(const float* __restrict__ wq0,
                                             const float* __restrict__ wk0,
                                             const float* __restrict__ wv0,
                                             const float* __restrict__ wo0,
                                             const float* __restrict__ wq1,
                                             const float* __restrict__ wk1,
                                             const float* __restrict__ wv1,
                                             const float* __restrict__ wo1) {
    __shared__ float s_q[32*64], s_k[32*64], s_v[32*64], s_oT[64*32];
    __shared__ float s_x[8][32], s_y[8][32], s_o[8][64], s_l[8][128];
    int tid = threadIdx.x;
    int s = blockIdx.x >> 9;
    const float* wq = s ? wq1 : wq0;
    const float* wk = s ? wk1 : wk0;
    const float* wv = s ? wv1 : wv0;
    const float* wo = s ? wo1 : wo0;
    for (int i = tid; i < 2048; i += 256) {
        int oc = i >> 5, c = i & 31;
        s_q[c*64 + oc] = wq[i];
        s_k[c*64 + oc] = wk[i];
        s_v[c*64 + oc] = wv[i];
        int oc2 = i >> 6, c2 = i & 63;
        s_oT[c2*32 + oc2] = wo[i];
    }
    __syncthreads();
    int w = tid >> 5, lane = tid & 31;
    int bm = (blockIdx.x & 511) * 8 + w;
    int b = bm >> 10;
    float xv = g_cent[bm*32 + lane];
    s_x[w][lane] = xv;
    __syncwarp();
    float q0 = 0.f, q1 = 0.f;
#pragma unroll
    for (int c = 0; c < 32; c++) {
        float xc = s_x[w][c];
        q0 = fmaf(s_q[c*64 + lane],      xc, q0);
        q1 = fmaf(s_q[c*64 + 32 + lane], xc, q1);
    }
    int cnt = g_bcnt[s*4096 + bm];
    const int* bidx = &g_bidx[(size_t)(s*4096 + bm)*64];
    const float rs = 0.17677669529663687f;  // 1/sqrt(32)
    for (int j = 0; j < cnt; j++) {
        int id = bidx[j];
        float yv = g_support[(size_t)(b*NN + id)*32 + lane] - s_x[w][lane];
        s_y[w][lane] = yv; __syncwarp();
        float k0 = 0.f, k1 = 0.f;
#pragma unroll
        for (int c = 0; c < 32; c++) {
            float yc = s_y[w][c];
            k0 = fmaf(s_k[c*64 + lane],      yc, k0);
            k1 = fmaf(s_k[c*64 + 32 + lane], yc, k1);
        }
        float l0 = q0*k0, l1 = q1*k1;
#pragma unroll
        for (int o = 16; o; o >>= 1) {
            l0 += __shfl_xor_sync(0xFFFFFFFFu, l0, o);
            l1 += __shfl_xor_sync(0xFFFFFFFFu, l1, o);
        }
        if (lane == 0) { s_l[w][j] = l0*rs; s_l[w][64 + j] = l1*rs; }
        __syncwarp();
    }
#pragma unroll
    for (int h = 0; h < 2; h++) {
        float v0 = (lane      < cnt) ? s_l[w][h*64 + lane]      : -3e38f;
        float v1 = (lane + 32 < cnt) ? s_l[w][h*64 + lane + 32] : -3e38f;
        float mx = fmaxf(v0, v1);
#pragma unroll
        for (int o = 16; o; o >>= 1) mx = fmaxf(mx, __shfl_xor_sync(0xFFFFFFFFu, mx, o));
        float e0 = (lane      < cnt) ? __expf(v0 - mx) : 0.f;
        float e1 = (lane + 32 < cnt) ? __expf(v1 - mx) : 0.f;
        float sm = e0 + e1;
#pragma unroll
        for (int o = 16; o; o >>= 1) sm += __shfl_xor_sync(0xFFFFFFFFu, sm, o);
        float inv = 1.f / sm;
        if (lane      < cnt) s_l[w][h*64 + lane]      = e0 * inv;
        if (lane + 32 < cnt) s_l[w][h*64 + lane + 32] = e1 * inv;
    }
    __syncwarp();
    float o0 = 0.f, o1 = 0.f;
    for (int j = 0; j < cnt; j++) {
        int id = bidx[j];
        float yv = g_support[(size_t)(b*NN + id)*32 + lane] - s_x[w][lane];
        s_y[w][lane] = yv; __syncwarp();
        float v0 = 0.f, v1 = 0.f;
#pragma unroll
        for (int c = 0; c < 32; c++) {
            float yc = s_y[w][c];
            v0 = fmaf(s_v[c*64 + lane],      yc, v0);
            v1 = fmaf(s_v[c*64 + 32 + lane], yc, v1);
        }
        o0 = fmaf(s_l[w][j],      v0, o0);
        o1 = fmaf(s_l[w][64 + j], v1, o1);
        __syncwarp();
    }
    s_o[w][lane] = o0; s_o[w][32 + lane] = o1; __syncwarp();
    float outv = s_x[w][lane];
#pragma unroll
    for (int c = 0; c < 64; c++) outv = fmaf(s_oT[c*32 + lane], s_o[w][c], outv);
    g_att[(size_t)(s*4096 + bm)*32 + lane] = outv;
}

// MLP layer 1 + BN1 partial stats; both scales in one launch (grid 2048)
__global__ __launch_bounds__(256) void k_mlp1(const float* __restrict__ W00,
                                              const float* __restrict__ b00,
                                              const float* __restrict__ W10,
                                              const float* __restrict__ b10) {
    __shared__ float sW[32*64];
    __shared__ float s_in[4][32];
    __shared__ float sh[4][64];
    int tid = threadIdx.x;
    int s = blockIdx.x >> 10;
    const float* W0 = s ? W10 : W00;
    const float* b0 = s ? b10 : b00;
    for (int i = tid; i < 2048; i += 256) { int oc = i >> 5, c = i & 31; sW[c*64 + oc] = W0[i]; }
    int bm0 = (blockIdx.x & 1023) * 4;
    if (tid < 128) s_in[tid >> 5][tid & 31] = g_att[(size_t)(s*4096 + bm0)*32 + tid];
    __syncthreads();
    int oc = tid & 63, q = tid >> 6;
    float h = b0[oc];
#pragma unroll
    for (int c = 0; c < 32; c++) h = fmaf(sW[c*64 + oc], s_in[q][c], h);
    g_h1[(size_t)(s*4096 + bm0 + q)*64 + oc] = h;
    sh[q][oc] = h;
    __syncthreads();
    if (q == 0) {
        float s1 = 0.f, s2 = 0.f;
#pragma unroll
        for (int qq = 0; qq < 4; qq++) { float v = sh[qq][oc]; s1 += v; s2 = fmaf(v, v, s2); }
        atomicAdd(&g_s1a[s*64 + oc], s1);
        atomicAdd(&g_s2a[s*64 + oc], s2);
    }
}

__global__ void k_fin1(const float* __restrict__ g0, const float* __restrict__ beta0,
                       const float* __restrict__ g1, const float* __restrict__ beta1) {
    int s = blockIdx.x, oc = threadIdx.x;
    const float* g = s ? g1 : g0;
    const float* beta = s ? beta1 : beta0;
    float mu  = g_s1a[s*64 + oc] * (1.f/4096.f);
    float var = g_s2a[s*64 + oc] * (1.f/4096.f) - mu*mu;
    float A = g[oc] * rsqrtf(var + 1e-5f);
    g_A1[s*64 + oc] = A;
    g_C1[s*64 + oc] = beta[oc] - mu*A;
}

// MLP layer 2 (+BN1/leaky fused) + BN2 partial stats; both scales (grid 4096)
__global__ __launch_bounds__(256) void k_mlp2(const float* __restrict__ W01,
                                              const float* __restrict__ b01,
                                              const float* __restrict__ W11,
                                              const float* __restrict__ b11) {
    __shared__ float sW[64*128];
    __shared__ float sact[2][64];
    __shared__ float sh[2][128];
    int tid = threadIdx.x;
    int s = blockIdx.x >> 11;
    const float* W1 = s ? W11 : W01;
    const float* b1 = s ? b11 : b01;
    for (int i = tid; i < 8192; i += 256) { int oc = i >> 6, c = i & 63; sW[c*128 + oc] = W1[i]; }
    int bm0 = (blockIdx.x & 2047) * 2;
    if (tid < 128) {
        int q = tid >> 6, c = tid & 63;
        float v = g_h1[(size_t)(s*4096 + bm0 + q)*64 + c];
        v = g_A1[s*64 + c]*v + g_C1[s*64 + c];
        sact[q][c] = v > 0.f ? v : 0.02f*v;
    }
    __syncthreads();
    int oc = tid & 127, q = tid >> 7;
    float h = b1[oc];
#pragma unroll
    for (int c = 0; c < 64; c++) h = fmaf(sW[c*128 + oc], sact[q][c], h);
    g_h2[(size_t)(s*4096 + bm0 + q)*128 + oc] = h;
    sh[q][oc] = h;
    __syncthreads();
    if (q == 0) {
        float a = sh[0][oc], bb = sh[1][oc];
        atomicAdd(&g_s1b[s*128 + oc], a + bb);
        atomicAdd(&g_s2b[s*128 + oc], fmaf(a, a, bb*bb));
    }
}

__global__ void k_fin2(const float* __restrict__ g0, const float* __restrict__ beta0,
                       const float* __restrict__ g1, const float* __restrict__ beta1) {
    int s = blockIdx.x, oc = threadIdx.x;
    const float* g = s ? g1 : g0;
    const float* beta = s ? beta1 : beta0;
    float mu  = g_s1b[s*128 + oc] * (1.f/4096.f);
    float var = g_s2b[s*128 + oc] * (1.f/4096.f) - mu*mu;
    float A = g[oc] * rsqrtf(var + 1e-5f);
    g_A2[s*128 + oc] = A;
    g_C2[s*128 + oc] = beta[oc] - mu*A;
}

// final BN2 apply + scatter, both scales (grid 4096)
__global__ __launch_bounds__(256) void k_out(float* __restrict__ out) {
    int s = blockIdx.x >> 11;
    int idx = (blockIdx.x & 2047) * 256 + threadIdx.x;
    int m = idx & 1023;
    int t2 = idx >> 10;
    int oc = t2 & 127, b = t2 >> 7;
    int bm = b*1024 + m;
    float v = g_h2[(size_t)(s*4096 + bm)*128 + oc];
    v = g_A2[s*128 + oc]*v + g_C2[s*128 + oc];
    out[12288 + (((b*256) + s*128 + oc) << 10) + m] = v;
}

extern "C" void kernel_launch(void* const* d_in, const int* in_sizes, int n_in,
                              void* d_out, int out_size) {
    (void)in_sizes; (void)n_in; (void)out_size;
    const float* xyz = (const float*)d_in[0];
    const float* pf  = (const float*)d_in[1];
    float* out = (float*)d_out;
    k_init<<<1, 256>>>();
    k_build<<<2048, 256>>>(xyz, pf);
    {
        cudaFuncSetAttribute(k_fps, cudaFuncAttributeNonPortableClusterSizeAllowed, 1);
        cudaLaunchConfig_t cfg = {};
        cfg.gridDim  = dim3(64, 1, 1);
        cfg.blockDim = dim3(512, 1, 1);
        cfg.dynamicSmemBytes = 0;
        cfg.stream = 0;
        cudaLaunchAttribute at[1];
        at[0].id = cudaLaunchAttributeClusterDimension;
        at[0].val.clusterDim.x = 16; at[0].val.clusterDim.y = 1; at[0].val.clusterDim.z = 1;
        cfg.attrs = at;
        cfg.numAttrs = 1;
        cudaLaunchKernelEx(&cfg, k_fps, out);
    }
    k_ball2<<<512, 256>>>();
    k_att<<<1024, 256>>>((const float*)d_in[2],  (const float*)d_in[3],
                         (const float*)d_in[4],  (const float*)d_in[5],
                         (const float*)d_in[14], (const float*)d_in[15],
                         (const float*)d_in[16], (const float*)d_in[17]);
    k_mlp1<<<2048, 256>>>((const float*)d_in[6],  (const float*)d_in[7],
                          (const float*)d_in[18], (const float*)d_in[19]);
    k_fin1<<<2, 64>>>((const float*)d_in[8],  (const float*)d_in[9],
                      (const float*)d_in[20], (const float*)d_in[21]);
    k_mlp2<<<4096, 256>>>((const float*)d_in[10], (const float*)d_in[11],
                          (const float*)d_in[22], (const float*)d_in[23]);
    k_fin2<<<2, 128>>>((const float*)d_in[12], (const float*)d_in[13],
                       (const float*)d_in[24], (const float*)d_in[25]);
    k_out<<<4096, 256>>>(out);
}

// round 15
// speedup vs baseline: 4.4781x; 1.0392x over previous
#include <cuda_runtime.h>
#include <cuda_fp16.h>
#include <cstdint>
#include <cstring>

#define BB 4
#define NN 16384
#define MM 1024

// ---- static scratch (no allocation) ----
__device__ float  g_support[BB*NN*32];
__device__ __align__(8) __half2 g_filth[BB*NN*2];   // 4 filter dims as fp16
__device__ float  g_cent[BB*MM*32];
__device__ int    g_bidx[2*BB*MM*64];
__device__ int    g_bcnt[2*BB*MM];
__device__ float  g_att[2*BB*MM*32];
__device__ float  g_h1[2*BB*MM*64];
__device__ float  g_h2[2*BB*MM*128];
__device__ float  g_s1a[2*64], g_s2a[2*64], g_s1b[2*128], g_s2b[2*128];
__device__ float  g_A1[2*64], g_C1[2*64], g_A2[2*128], g_C2[2*128];

// transpose [B,32,N] channel-major inputs -> point-major support + fp16 filter
// block 0 also zeroes the BN stat accumulators (replaces k_init)
__global__ __launch_bounds__(256) void k_build(const float* __restrict__ xyz,
                                               const float* __restrict__ pf) {
    __shared__ float t[32][33];
    int b  = blockIdx.x >> 9;
    int n0 = (blockIdx.x & 511) << 5;
    int tid = threadIdx.x;
    if (blockIdx.x == 0) {
        if (tid < 128) { g_s1a[tid] = 0.f; g_s2a[tid] = 0.f; }
        g_s1b[tid] = 0.f; g_s2b[tid] = 0.f;
    }
#pragma unroll
    for (int i = 0; i < 4; i++) {
        int e = tid + i*256, c = e >> 5, n = e & 31;
        float v = (c < 3) ? xyz[(b*3 + c)*NN + n0 + n] : pf[(b*29 + (c-3))*NN + n0 + n];
        t[n][c] = v;
    }
    __syncthreads();
    int n = tid >> 3, c0 = (tid & 7) << 2;
    *(float4*)&g_support[((size_t)(b*NN + n0 + n))*32 + c0] =
        make_float4(t[n][c0], t[n][c0+1], t[n][c0+2], t[n][c0+3]);
    if (tid < 32) {
        __half2 h01 = __float22half2_rn(make_float2(t[tid][3], t[tid][4]));
        __half2 h23 = __float22half2_rn(make_float2(t[tid][5], t[tid][6]));
        uint2 u; memcpy(&u.x, &h01, 4); memcpy(&u.y, &h23, 4);
        ((uint2*)g_filth)[b*NN + n0 + tid] = u;
    }
}

__device__ __forceinline__ uint32_t smem_u32(const void* p) {
    uint32_t a;
    asm("{ .reg .u64 t; cvta.to.shared.u64 t, %1; cvt.u32.u64 %0, t; }" : "=r"(a) : "l"(p));
    return a;
}
__device__ __forceinline__ void remote_st(uint32_t laddr, uint32_t rank, unsigned long long v) {
    uint32_t ra;
    asm volatile("mapa.shared::cluster.u32 %0, %1, %2;" : "=r"(ra) : "r"(laddr), "r"(rank));
    asm volatile("st.relaxed.cluster.shared::cluster.u64 [%0], %1;" :: "r"(ra), "l"(v) : "memory");
}
__device__ __forceinline__ unsigned long long ldvol(const unsigned long long* p) {
    unsigned long long v;
    asm volatile("ld.volatile.shared.u64 %0, [%1];" : "=l"(v) : "r"(smem_u32(p)) : "memory");
    return v;
}

// FPS: one 16-CTA cluster per batch, 512 thr/CTA, 2 pts/thread (f32x2 math).
// Sync v8: bar.sync intra-CTA; all-to-all DSMEM exchange cross-CTA.
// Winning point's owner thread writes the centroid + new_xyz inline.
__global__ void __launch_bounds__(512, 1) k_fps(float* __restrict__ out) {
    __shared__ unsigned long long sred[16];       // untagged warp candidates
    __shared__ unsigned long long slots[2][16];   // parity x rank: tagged CTA candidates
    int b   = blockIdx.x >> 4;
    int crk = blockIdx.x & 15;
    int tid = threadIdx.x, wid = tid >> 5, lane = tid & 31;
    if (tid < 16) { slots[0][tid] = 0ull; slots[1][tid] = 0ull; }
    __syncthreads();
    asm volatile("barrier.cluster.arrive.aligned;" ::: "memory");
    asm volatile("barrier.cluster.wait.aligned;"   ::: "memory");
    int p0 = (crk << 9) + tid, p1 = p0 + 8192;
    unsigned long long nx0[16], nx1[16];
    {
        const float4* a = (const float4*)&g_support[(size_t)(b*NN + p0)*32];
        const float4* c = (const float4*)&g_support[(size_t)(b*NN + p1)*32];
#pragma unroll
        for (int i = 0; i < 8; i++) {
            float4 v = a[i], u = c[i];
            asm("mov.b64 %0, {%1, %2};" : "=l"(nx0[2*i])   : "f"(-v.x), "f"(-v.y));
            asm("mov.b64 %0, {%1, %2};" : "=l"(nx0[2*i+1]) : "f"(-v.z), "f"(-v.w));
            asm("mov.b64 %0, {%1, %2};" : "=l"(nx1[2*i])   : "f"(-u.x), "f"(-u.y));
            asm("mov.b64 %0, {%1, %2};" : "=l"(nx1[2*i+1]) : "f"(-u.z), "f"(-u.w));
        }
    }
    float d0 = 1e10f, d1 = 1e10f;
    int f = 0;
    // centroid m=0 is point 0: owner is crk0/tid0/half0
    if (crk == 0 && tid == 0) {
        float2* dst = (float2*)&g_cent[(size_t)b*MM*32];
#pragma unroll
        for (int i = 0; i < 16; i++) {
            float lo, hi;
            asm("mov.b64 {%0, %1}, %2;" : "=f"(lo), "=f"(hi) : "l"(nx0[i]));
            dst[i] = make_float2(-lo, -hi);
        }
        float l0, h0, l1, h1;
        asm("mov.b64 {%0, %1}, %2;" : "=f"(l0), "=f"(h0) : "l"(nx0[0]));
        asm("mov.b64 {%0, %1}, %2;" : "=f"(l1), "=f"(h1) : "l"(nx0[1]));
        out[(b*3 + 0)*MM] = -l0; out[(b*3 + 1)*MM] = -h0; out[(b*3 + 2)*MM] = -l1;
    }
    uint32_t a_slots = smem_u32(slots);
    for (int t = 0; t < MM; t++) {
        const ulonglong2* cp = (const ulonglong2*)&g_support[(size_t)(b*NN + f)*32];
        unsigned long long A01 = 0ull, A23 = 0ull, B01 = 0ull, B23 = 0ull;
#pragma unroll
        for (int i = 0; i < 8; i++) {
            ulonglong2 cv = cp[i];
            unsigned long long e;
            asm("add.rn.f32x2 %0, %1, %2;"     : "=l"(e)   : "l"(cv.x), "l"(nx0[2*i]));
            asm("fma.rn.f32x2 %0, %1, %2, %3;" : "=l"(A01) : "l"(e), "l"(e), "l"(A01));
            asm("add.rn.f32x2 %0, %1, %2;"     : "=l"(e)   : "l"(cv.y), "l"(nx0[2*i+1]));
            asm("fma.rn.f32x2 %0, %1, %2, %3;" : "=l"(A23) : "l"(e), "l"(e), "l"(A23));
            asm("add.rn.f32x2 %0, %1, %2;"     : "=l"(e)   : "l"(cv.x), "l"(nx1[2*i]));
            asm("fma.rn.f32x2 %0, %1, %2, %3;" : "=l"(B01) : "l"(e), "l"(e), "l"(B01));
            asm("add.rn.f32x2 %0, %1, %2;"     : "=l"(e)   : "l"(cv.y), "l"(nx1[2*i+1]));
            asm("fma.rn.f32x2 %0, %1, %2, %3;" : "=l"(B23) : "l"(e), "l"(e), "l"(B23));
        }
        float a0,a1,a2,a3;
        asm("mov.b64 {%0, %1}, %2;" : "=f"(a0), "=f"(a1) : "l"(A01));
        asm("mov.b64 {%0, %1}, %2;" : "=f"(a2), "=f"(a3) : "l"(A23));
        d0 = fminf(d0, (a0 + a1) + (a2 + a3));
        asm("mov.b64 {%0, %1}, %2;" : "=f"(a0), "=f"(a1) : "l"(B01));
        asm("mov.b64 {%0, %1}, %2;" : "=f"(a2), "=f"(a3) : "l"(B23));
        d1 = fminf(d1, (a0 + a1) + (a2 + a3));
        if (t == MM - 1) break;
        unsigned want = (unsigned)(t + 1);
        float dm; unsigned pi;
        if (d0 >= d1) { dm = d0; pi = (unsigned)p0; } else { dm = d1; pi = (unsigned)p1; }
        unsigned long long pk = ((unsigned long long)__float_as_uint(dm) << 14)
                              | (unsigned long long)(16383u - pi);   // tie -> lowest idx
#pragma unroll
        for (int o = 16; o; o >>= 1) {
            unsigned long long q = __shfl_down_sync(0xFFFFFFFFu, pk, o);
            if (q > pk) pk = q;
        }
        if (lane == 0) sred[wid] = pk;
        __syncthreads();
        if (wid == 0) {
            unsigned long long v = (lane < 16) ? sred[lane] : 0ull;
#pragma unroll
            for (int o = 8; o; o >>= 1) {
                unsigned long long q = __shfl_down_sync(0xFFFFFFFFu, v, o);
                if (q > v) v = q;
            }
            v = __shfl_sync(0xFFFFFFFFu, v, 0) | ((unsigned long long)want << 46);
            if (lane < 16)
                remote_st(a_slots + (((want & 1u)*16u + (unsigned)crk) << 3), (uint32_t)lane, v);
        }
        // every warp polls local slots and reduces the global argmax
        {
            unsigned long long v = 0ull;
            const unsigned long long* sl = slots[want & 1];
            do { if (lane < 16) v = ldvol(&sl[lane]); }
            while (!__all_sync(0xFFFFFFFFu, lane >= 16 || (unsigned)(v >> 46) == want));
            if (lane >= 16) v = 0ull;
#pragma unroll
            for (int o = 8; o; o >>= 1) {
                unsigned long long q = __shfl_down_sync(0xFFFFFFFFu, v, o);
                if (q > v) v = q;
            }
            v = __shfl_sync(0xFFFFFFFFu, v, 0);
            f = 16383 - (int)(v & 16383ull);
        }
        // owner thread writes centroid m = t+1 (off critical path)
        {
            int half = f >> 13, rest = f & 8191;
            if ((rest >> 9) == crk && (rest & 511) == tid) {
                float2* dst = (float2*)&g_cent[(size_t)(b*MM + t + 1)*32];
                float x0v, x1v, x2v;
                if (half == 0) {
#pragma unroll
                    for (int i = 0; i < 16; i++) {
                        float lo, hi;
                        asm("mov.b64 {%0, %1}, %2;" : "=f"(lo), "=f"(hi) : "l"(nx0[i]));
                        dst[i] = make_float2(-lo, -hi);
                    }
                    float lo, hi;
                    asm("mov.b64 {%0, %1}, %2;" : "=f"(lo), "=f"(hi) : "l"(nx0[0]));
                    x0v = -lo; x1v = -hi;
                    asm("mov.b64 {%0, %1}, %2;" : "=f"(lo), "=f"(hi) : "l"(nx0[1]));
                    x2v = -lo;
                } else {
#pragma unroll
                    for (int i = 0; i < 16; i++) {
                        float lo, hi;
                        asm("mov.b64 {%0, %1}, %2;" : "=f"(lo), "=f"(hi) : "l"(nx1[i]));
                        dst[i] = make_float2(-lo, -hi);
                    }
                    float lo, hi;
                    asm("mov.b64 {%0, %1}, %2;" : "=f"(lo), "=f"(hi) : "l"(nx1[0]));
                    x0v = -lo; x1v = -hi;
                    asm("mov.b64 {%0, %1}, %2;" : "=f"(lo), "=f"(hi) : "l"(nx1[1]));
                    x2v = -lo;
                }
                int m = t + 1;
                out[(b*3 + 0)*MM + m] = x0v;
                out[(b*3 + 1)*MM + m] = x1v;
                out[(b*3 + 2)*MM + m] = x2v;
            }
        }
    }
    asm volatile("barrier.cluster.arrive.aligned;" ::: "memory");
    asm volatile("barrier.cluster.wait.aligned;"   ::: "memory");
}

// ball query BOTH scales in one scan, 2 points/lane/iter, native half2 prune
// (threshold 0.07 covers worst-case fp16 error; exact fp32 verify classifies).
__global__ __launch_bounds__(256) void k_ball2() {
    int w = threadIdx.x >> 5, lane = threadIdx.x & 31;
    int bm = blockIdx.x * 8 + w;
    int b = bm >> 10;
    const float* cen = &g_cent[bm*32];
    __half2 c01 = __floats2half2_rn(cen[3], cen[4]);
    __half2 c23 = __floats2half2_rn(cen[5], cen[6]);
    const __half TH = __float2half(0.07f);
    int cnt0 = 0, cnt1 = 0;
    int* o0 = &g_bidx[(size_t)bm*64];
    int* o1 = &g_bidx[(size_t)(4096 + bm)*64];
    const uint2* filt = &((const uint2*)g_filth)[b*NN];
    const float R2S = 0.01f, R2L = 0.04f;
    for (int it = 0; it < NN/64; it++) {
        int nA = (it << 6) + lane;
        int nB = nA + 32;
        uint2 fa = filt[nA], fb = filt[nB];
        __half2 a01, a23, b01h, b23h;
        memcpy(&a01,  &fa.x, 4); memcpy(&a23,  &fa.y, 4);
        memcpy(&b01h, &fb.x, 4); memcpy(&b23h, &fb.y, 4);
        __half2 eA = __hsub2(a01, c01);
        __half2 sA = __hmul2(eA, eA);
        eA = __hsub2(a23, c23);
        sA = __hfma2(eA, eA, sA);
        __half2 eB = __hsub2(b01h, c01);
        __half2 sB = __hmul2(eB, eB);
        eB = __hsub2(b23h, c23);
        sB = __hfma2(eB, eB, sB);
        __half2 d4 = __hadd2(__lows2half2(sA, sB), __highs2half2(sA, sB)); // (d4A, d4B)
        bool passA = __hle(__low2half(d4), TH);
        bool passB = __hle(__high2half(d4), TH);
        bool p0A = false, p1A = false, p0B = false, p1B = false;
        if (passA) {
            const float* pp = &g_support[(size_t)(b*NN + nA)*32];
            float dd = 0.f;
#pragma unroll
            for (int i = 0; i < 32; i++) { float e = pp[i] - cen[i]; dd = fmaf(e, e, dd); }
            p1A = (dd <= R2L); p0A = (dd <= R2S);
        }
        if (passB) {
            const float* pp = &g_support[(size_t)(b*NN + nB)*32];
            float dd = 0.f;
#pragma unroll
            for (int i = 0; i < 32; i++) { float e = pp[i] - cen[i]; dd = fmaf(e, e, dd); }
            p1B = (dd <= R2L); p0B = (dd <= R2S);
        }
        unsigned balA1 = __ballot_sync(0xFFFFFFFFu, p1A);
        unsigned balA0 = __ballot_sync(0xFFFFFFFFu, p0A);
        unsigned balB1 = __ballot_sync(0xFFFFFFFFu, p1B);
        unsigned balB0 = __ballot_sync(0xFFFFFFFFu, p0B);
        while (balA1) {
            int l = __ffs(balA1) - 1; balA1 &= balA1 - 1;
            int idx = (it << 6) + l;
            if (cnt1 < 64) { if (lane == 0) o1[cnt1] = idx; cnt1++; }
            if (((balA0 >> l) & 1u) && cnt0 < 32) { if (lane == 0) o0[cnt0] = idx; cnt0++; }
        }
        while (balB1) {
            int l = __ffs(balB1) - 1; balB1 &= balB1 - 1;
            int idx = (it << 6) + 32 + l;
            if (cnt1 < 64) { if (lane == 0) o1[cnt1] = idx; cnt1++; }
            if (((balB0 >> l) & 1u) && cnt0 < 32) { if (lane == 0) o0[cnt0] = idx; cnt0++; }
        }
        if (cnt1 >= 64 && cnt0 >= 32) break;
    }
    if (lane == 0) { g_bcnt[bm] = cnt0; g_bcnt[4096 + bm] = cnt1; }
}

// attention over unmasked neighbors only; both scales in one launch (grid 1024)
__global__ __launch_bounds__(256) void k_att(const float* __restrict__ wq0,
                                             const float* __restrict__ wk0,
                                             const float* __restrict__ wv0,
                                             const float* __restrict__ wo0,
                                             const float* __restrict__ wq1,
                                             const float* __restrict__ wk1,
                                             const float* __restrict__ wv1,
                                             const float* __restrict__ wo1) {
    __shared__ float s_q[32*64], s_k[32*64], s_v[32*64], s_oT[64*32];
    __shared__ float s_x[8][32], s_y[8][32], s_o[8][64], s_l[8][128];
    int tid = threadIdx.x;
    int s = blockIdx.x >> 9;
    const float* wq = s ? wq1 : wq0;
    const float* wk = s ? wk1 : wk0;
    const float* wv = s ? wv1 : wv0;
    const float* wo = s ? wo1 : wo0;
    for (int i = tid; i < 2048; i += 256) {
        int oc = i >> 5, c = i & 31;
        s_q[c*64 + oc] = wq[i];
        s_k[c*64 + oc] = wk[i];
        s_v[c*64 + oc] = wv[i];
        int oc2 = i >> 6, c2 = i & 63;
        s_oT[c2*32 + oc2] = wo[i];
    }
    __syncthreads();
    int w = tid >> 5, lane = tid & 31;
    int bm = (blockIdx.x & 511) * 8 + w;
    int b = bm >> 10;
    float xv = g_cent[bm*32 + lane];
    s_x[w][lane] = xv;
    __syncwarp();
    float q0 = 0.f, q1 = 0.f;
#pragma unroll
    for (int c = 0; c < 32; c++) {
        float xc = s_x[w][c];
        q0 = fmaf(s_q[c*64 + lane],      xc, q0);
        q1 = fmaf(s_q[c*64 + 32 + lane], xc, q1);
    }
    int cnt = g_bcnt[s*4096 + bm];
    const int* bidx = &g_bidx[(size_t)(s*4096 + bm)*64];
    const float rs = 0.17677669529663687f;  // 1/sqrt(32)
    for (int j = 0; j < cnt; j++) {
        int id = bidx[j];
        float yv = g_support[(size_t)(b*NN + id)*32 + lane] - s_x[w][lane];
        s_y[w][lane] = yv; __syncwarp();
        float k0 = 0.f, k1 = 0.f;
#pragma unroll
        for (int c = 0; c < 32; c++) {
            float yc = s_y[w][c];
            k0 = fmaf(s_k[c*64 + lane],      yc, k0);
            k1 = fmaf(s_k[c*64 + 32 + lane], yc, k1);
        }
        float l0 = q0*k0, l1 = q1*k1;
#pragma unroll
        for (int o = 16; o; o >>= 1) {
            l0 += __shfl_xor_sync(0xFFFFFFFFu, l0, o);
            l1 += __shfl_xor_sync(0xFFFFFFFFu, l1, o);
        }
        if (lane == 0) { s_l[w][j] = l0*rs; s_l[w][64 + j] = l1*rs; }
        __syncwarp();
    }
#pragma unroll
    for (int h = 0; h < 2; h++) {
        float v0 = (lane      < cnt) ? s_l[w][h*64 + lane]      : -3e38f;
        float v1 = (lane + 32 < cnt) ? s_l[w][h*64 + lane + 32] : -3e38f;
        float mx = fmaxf(v0, v1);
#pragma unroll
        for (int o = 16; o; o >>= 1) mx = fmaxf(mx, __shfl_xor_sync(0xFFFFFFFFu, mx, o));
        float e0 = (lane      < cnt) ? __expf(v0 - mx) : 0.f;
        float e1 = (lane + 32 < cnt) ? __expf(v1 - mx) : 0.f;
        float sm = e0 + e1;
#pragma unroll
        for (int o = 16; o; o >>= 1) sm += __shfl_xor_sync(0xFFFFFFFFu, sm, o);
        float inv = 1.f / sm;
        if (lane      < cnt) s_l[w][h*64 + lane]      = e0 * inv;
        if (lane + 32 < cnt) s_l[w][h*64 + lane + 32] = e1 * inv;
    }
    __syncwarp();
    float o0 = 0.f, o1 = 0.f;
    for (int j = 0; j < cnt; j++) {
        int id = bidx[j];
        float yv = g_support[(size_t)(b*NN + id)*32 + lane] - s_x[w][lane];
        s_y[w][lane] = yv; __syncwarp();
        float v0 = 0.f, v1 = 0.f;
#pragma unroll
        for (int c = 0; c < 32; c++) {
            float yc = s_y[w][c];
            v0 = fmaf(s_v[c*64 + lane],      yc, v0);
            v1 = fmaf(s_v[c*64 + 32 + lane], yc, v1);
        }
        o0 = fmaf(s_l[w][j],      v0, o0);
        o1 = fmaf(s_l[w][64 + j], v1, o1);
        __syncwarp();
    }
    s_o[w][lane] = o0; s_o[w][32 + lane] = o1; __syncwarp();
    float outv = s_x[w][lane];
#pragma unroll
    for (int c = 0; c < 64; c++) outv = fmaf(s_oT[c*32 + lane], s_o[w][c], outv);
    g_att[(size_t)(s*4096 + bm)*32 + lane] = outv;
}

// MLP layer 1 + BN1 partial stats; both scales in one launch (grid 2048)
__global__ __launch_bounds__(256) void k_mlp1(const float* __restrict__ W00,
                                              const float* __restrict__ b00,
                                              const float* __restrict__ W10,
                                              const float* __restrict__ b10) {
    __shared__ float sW[32*64];
    __shared__ float s_in[4][32];
    __shared__ float sh[4][64];
    int tid = threadIdx.x;
    int s = blockIdx.x >> 10;
    const float* W0 = s ? W10 : W00;
    const float* b0 = s ? b10 : b00;
    for (int i = tid; i < 2048; i += 256) { int oc = i >> 5, c = i & 31; sW[c*64 + oc] = W0[i]; }
    int bm0 = (blockIdx.x & 1023) * 4;
    if (tid < 128) s_in[tid >> 5][tid & 31] = g_att[(size_t)(s*4096 + bm0)*32 + tid];
    __syncthreads();
    int oc = tid & 63, q = tid >> 6;
    float h = b0[oc];
#pragma unroll
    for (int c = 0; c < 32; c++) h = fmaf(sW[c*64 + oc], s_in[q][c], h);
    g_h1[(size_t)(s*4096 + bm0 + q)*64 + oc] = h;
    sh[q][oc] = h;
    __syncthreads();
    if (q == 0) {
        float s1 = 0.f, s2 = 0.f;
#pragma unroll
        for (int qq = 0; qq < 4; qq++) { float v = sh[qq][oc]; s1 += v; s2 = fmaf(v, v, s2); }
        atomicAdd(&g_s1a[s*64 + oc], s1);
        atomicAdd(&g_s2a[s*64 + oc], s2);
    }
}

__global__ void k_fin1(const float* __restrict__ g0, const float* __restrict__ beta0,
                       const float* __restrict__ g1, const float* __restrict__ beta1) {
    int s = blockIdx.x, oc = threadIdx.x;
    const float* g = s ? g1 : g0;
    const float* beta = s ? beta1 : beta0;
    float mu  = g_s1a[s*64 + oc] * (1.f/4096.f);
    float var = g_s2a[s*64 + oc] * (1.f/4096.f) - mu*mu;
    float A = g[oc] * rsqrtf(var + 1e-5f);
    g_A1[s*64 + oc] = A;
    g_C1[s*64 + oc] = beta[oc] - mu*A;
}

// MLP layer 2 (+BN1/leaky fused) + BN2 partial stats; both scales (grid 4096)
__global__ __launch_bounds__(256) void k_mlp2(const float* __restrict__ W01,
                                              const float* __restrict__ b01,
                                              const float* __restrict__ W11,
                                              const float* __restrict__ b11) {
    __shared__ float sW[64*128];
    __shared__ float sact[2][64];
    __shared__ float sh[2][128];
    int tid = threadIdx.x;
    int s = blockIdx.x >> 11;
    const float* W1 = s ? W11 : W01;
    const float* b1 = s ? b11 : b01;
    for (int i = tid; i < 8192; i += 256) { int oc = i >> 6, c = i & 63; sW[c*128 + oc] = W1[i]; }
    int bm0 = (blockIdx.x & 2047) * 2;
    if (tid < 128) {
        int q = tid >> 6, c = tid & 63;
        float v = g_h1[(size_t)(s*4096 + bm0 + q)*64 + c];
        v = g_A1[s*64 + c]*v + g_C1[s*64 + c];
        sact[q][c] = v > 0.f ? v : 0.02f*v;
    }
    __syncthreads();
    int oc = tid & 127, q = tid >> 7;
    float h = b1[oc];
#pragma unroll
    for (int c = 0; c < 64; c++) h = fmaf(sW[c*128 + oc], sact[q][c], h);
    g_h2[(size_t)(s*4096 + bm0 + q)*128 + oc] = h;
    sh[q][oc] = h;
    __syncthreads();
    if (q == 0) {
        float a = sh[0][oc], bb = sh[1][oc];
        atomicAdd(&g_s1b[s*128 + oc], a + bb);
        atomicAdd(&g_s2b[s*128 + oc], fmaf(a, a, bb*bb));
    }
}

__global__ void k_fin2(const float* __restrict__ g0, const float* __restrict__ beta0,
                       const float* __restrict__ g1, const float* __restrict__ beta1) {
    int s = blockIdx.x, oc = threadIdx.x;
    const float* g = s ? g1 : g0;
    const float* beta = s ? beta1 : beta0;
    float mu  = g_s1b[s*128 + oc] * (1.f/4096.f);
    float var = g_s2b[s*128 + oc] * (1.f/4096.f) - mu*mu;
    float A = g[oc] * rsqrtf(var + 1e-5f);
    g_A2[s*128 + oc] = A;
    g_C2[s*128 + oc] = beta[oc] - mu*A;
}

// final BN2 apply + scatter, both scales (grid 4096)
__global__ __launch_bounds__(256) void k_out(float* __restrict__ out) {
    int s = blockIdx.x >> 11;
    int idx = (blockIdx.x & 2047) * 256 + threadIdx.x;
    int m = idx & 1023;
    int t2 = idx >> 10;
    int oc = t2 & 127, b = t2 >> 7;
    int bm = b*1024 + m;
    float v = g_h2[(size_t)(s*4096 + bm)*128 + oc];
    v = g_A2[s*128 + oc]*v + g_C2[s*128 + oc];
    out[12288 + (((b*256) + s*128 + oc) << 10) + m] = v;
}

extern "C" void kernel_launch(void* const* d_in, const int* in_sizes, int n_in,
                              void* d_out, int out_size) {
    (void)in_sizes; (void)n_in; (void)out_size;
    const float* xyz = (const float*)d_in[0];
    const float* pf  = (const float*)d_in[1];
    float* out = (float*)d_out;
    k_build<<<2048, 256>>>(xyz, pf);
    {
        cudaFuncSetAttribute(k_fps, cudaFuncAttributeNonPortableClusterSizeAllowed, 1);
        cudaLaunchConfig_t cfg = {};
        cfg.gridDim  = dim3(64, 1, 1);
        cfg.blockDim = dim3(512, 1, 1);
        cfg.dynamicSmemBytes = 0;
        cfg.stream = 0;
        cudaLaunchAttribute at[1];
        at[0].id = cudaLaunchAttributeClusterDimension;
        at[0].val.clusterDim.x = 16; at[0].val.clusterDim.y = 1; at[0].val.clusterDim.z = 1;
        cfg.attrs = at;
        cfg.numAttrs = 1;
        cudaLaunchKernelEx(&cfg, k_fps, out);
    }
    k_ball2<<<512, 256>>>();
    k_att<<<1024, 256>>>((const float*)d_in[2],  (const float*)d_in[3],
                         (const float*)d_in[4],  (const float*)d_in[5],
                         (const float*)d_in[14], (const float*)d_in[15],
                         (const float*)d_in[16], (const float*)d_in[17]);
    k_mlp1<<<2048, 256>>>((const float*)d_in[6],  (const float*)d_in[7],
                          (const float*)d_in[18], (const float*)d_in[19]);
    k_fin1<<<2, 64>>>((const float*)d_in[8],  (const float*)d_in[9],
                      (const float*)d_in[20], (const float*)d_in[21]);
    k_mlp2<<<4096, 256>>>((const float*)d_in[10], (const float*)d_in[11],
                          (const float*)d_in[22], (const float*)d_in[23]);
    k_fin2<<<2, 128>>>((const float*)d_in[12], (const float*)d_in[13],
                       (const float*)d_in[24], (const float*)d_in[25]);
    k_out<<<4096, 256>>>(out);
}

// round 16
// speedup vs baseline: 4.6449x; 1.0372x over previous
#include <cuda_runtime.h>
#include <cuda_fp16.h>
#include <cstdint>
#include <cstring>

#define BB 4
#define NN 16384
#define MM 1024

// ---- static scratch (no allocation) ----
__device__ float  g_support[BB*NN*32];
__device__ __align__(8) __half2 g_filth[BB*NN*2];   // 4 filter dims as fp16
__device__ float  g_cent[BB*MM*32];
__device__ int    g_bidx[2*BB*MM*64];
__device__ int    g_bcnt[2*BB*MM];
__device__ float  g_att[2*BB*MM*32];
__device__ float  g_h1[2*BB*MM*64];
__device__ float  g_h2[2*BB*MM*128];
__device__ float  g_s1a[2*64], g_s2a[2*64], g_s1b[2*128], g_s2b[2*128];
__device__ float  g_A1[2*64], g_C1[2*64], g_A2[2*128], g_C2[2*128];

// transpose [B,32,N] channel-major inputs -> point-major support + fp16 filter
// block 0 also zeroes the BN stat accumulators
__global__ __launch_bounds__(256) void k_build(const float* __restrict__ xyz,
                                               const float* __restrict__ pf) {
    __shared__ float t[32][33];
    int b  = blockIdx.x >> 9;
    int n0 = (blockIdx.x & 511) << 5;
    int tid = threadIdx.x;
    if (blockIdx.x == 0) {
        if (tid < 128) { g_s1a[tid] = 0.f; g_s2a[tid] = 0.f; }
        g_s1b[tid] = 0.f; g_s2b[tid] = 0.f;
    }
#pragma unroll
    for (int i = 0; i < 4; i++) {
        int e = tid + i*256, c = e >> 5, n = e & 31;
        float v = (c < 3) ? xyz[(b*3 + c)*NN + n0 + n] : pf[(b*29 + (c-3))*NN + n0 + n];
        t[n][c] = v;
    }
    __syncthreads();
    int n = tid >> 3, c0 = (tid & 7) << 2;
    *(float4*)&g_support[((size_t)(b*NN + n0 + n))*32 + c0] =
        make_float4(t[n][c0], t[n][c0+1], t[n][c0+2], t[n][c0+3]);
    if (tid < 32) {
        __half2 h01 = __float22half2_rn(make_float2(t[tid][3], t[tid][4]));
        __half2 h23 = __float22half2_rn(make_float2(t[tid][5], t[tid][6]));
        uint2 u; memcpy(&u.x, &h01, 4); memcpy(&u.y, &h23, 4);
        ((uint2*)g_filth)[b*NN + n0 + tid] = u;
    }
}

__device__ __forceinline__ uint32_t smem_u32(const void* p) {
    uint32_t a;
    asm("{ .reg .u64 t; cvta.to.shared.u64 t, %1; cvt.u32.u64 %0, t; }" : "=r"(a) : "l"(p));
    return a;
}
__device__ __forceinline__ void remote_st(uint32_t laddr, uint32_t rank, unsigned long long v) {
    uint32_t ra;
    asm volatile("mapa.shared::cluster.u32 %0, %1, %2;" : "=r"(ra) : "r"(laddr), "r"(rank));
    asm volatile("st.relaxed.cluster.shared::cluster.u64 [%0], %1;" :: "r"(ra), "l"(v) : "memory");
}
__device__ __forceinline__ unsigned long long ldvol(const unsigned long long* p) {
    unsigned long long v;
    asm volatile("ld.volatile.shared.u64 %0, [%1];" : "=l"(v) : "r"(smem_u32(p)) : "memory");
    return v;
}

// FPS: one 16-CTA cluster per batch, 512 thr/CTA, 2 pts/thread (f32x2 math).
// Sync v8: bar.sync intra-CTA; all-to-all DSMEM exchange cross-CTA.
__global__ void __launch_bounds__(512, 1) k_fps(float* __restrict__ out) {
    __shared__ unsigned long long sred[16];
    __shared__ unsigned long long slots[2][16];
    int b   = blockIdx.x >> 4;
    int crk = blockIdx.x & 15;
    int tid = threadIdx.x, wid = tid >> 5, lane = tid & 31;
    if (tid < 16) { slots[0][tid] = 0ull; slots[1][tid] = 0ull; }
    __syncthreads();
    asm volatile("barrier.cluster.arrive.aligned;" ::: "memory");
    asm volatile("barrier.cluster.wait.aligned;"   ::: "memory");
    int p0 = (crk << 9) + tid, p1 = p0 + 8192;
    unsigned long long nx0[16], nx1[16];
    {
        const float4* a = (const float4*)&g_support[(size_t)(b*NN + p0)*32];
        const float4* c = (const float4*)&g_support[(size_t)(b*NN + p1)*32];
#pragma unroll
        for (int i = 0; i < 8; i++) {
            float4 v = a[i], u = c[i];
            asm("mov.b64 %0, {%1, %2};" : "=l"(nx0[2*i])   : "f"(-v.x), "f"(-v.y));
            asm("mov.b64 %0, {%1, %2};" : "=l"(nx0[2*i+1]) : "f"(-v.z), "f"(-v.w));
            asm("mov.b64 %0, {%1, %2};" : "=l"(nx1[2*i])   : "f"(-u.x), "f"(-u.y));
            asm("mov.b64 %0, {%1, %2};" : "=l"(nx1[2*i+1]) : "f"(-u.z), "f"(-u.w));
        }
    }
    float d0 = 1e10f, d1 = 1e10f;
    int f = 0;
    if (crk == 0 && tid == 0) {
        float2* dst = (float2*)&g_cent[(size_t)b*MM*32];
#pragma unroll
        for (int i = 0; i < 16; i++) {
            float lo, hi;
            asm("mov.b64 {%0, %1}, %2;" : "=f"(lo), "=f"(hi) : "l"(nx0[i]));
            dst[i] = make_float2(-lo, -hi);
        }
        float l0, h0, l1, h1;
        asm("mov.b64 {%0, %1}, %2;" : "=f"(l0), "=f"(h0) : "l"(nx0[0]));
        asm("mov.b64 {%0, %1}, %2;" : "=f"(l1), "=f"(h1) : "l"(nx0[1]));
        out[(b*3 + 0)*MM] = -l0; out[(b*3 + 1)*MM] = -h0; out[(b*3 + 2)*MM] = -l1;
    }
    uint32_t a_slots = smem_u32(slots);
    for (int t = 0; t < MM; t++) {
        const ulonglong2* cp = (const ulonglong2*)&g_support[(size_t)(b*NN + f)*32];
        unsigned long long A01 = 0ull, A23 = 0ull, B01 = 0ull, B23 = 0ull;
#pragma unroll
        for (int i = 0; i < 8; i++) {
            ulonglong2 cv = cp[i];
            unsigned long long e;
            asm("add.rn.f32x2 %0, %1, %2;"     : "=l"(e)   : "l"(cv.x), "l"(nx0[2*i]));
            asm("fma.rn.f32x2 %0, %1, %2, %3;" : "=l"(A01) : "l"(e), "l"(e), "l"(A01));
            asm("add.rn.f32x2 %0, %1, %2;"     : "=l"(e)   : "l"(cv.y), "l"(nx0[2*i+1]));
            asm("fma.rn.f32x2 %0, %1, %2, %3;" : "=l"(A23) : "l"(e), "l"(e), "l"(A23));
            asm("add.rn.f32x2 %0, %1, %2;"     : "=l"(e)   : "l"(cv.x), "l"(nx1[2*i]));
            asm("fma.rn.f32x2 %0, %1, %2, %3;" : "=l"(B01) : "l"(e), "l"(e), "l"(B01));
            asm("add.rn.f32x2 %0, %1, %2;"     : "=l"(e)   : "l"(cv.y), "l"(nx1[2*i+1]));
            asm("fma.rn.f32x2 %0, %1, %2, %3;" : "=l"(B23) : "l"(e), "l"(e), "l"(B23));
        }
        float a0,a1,a2,a3;
        asm("mov.b64 {%0, %1}, %2;" : "=f"(a0), "=f"(a1) : "l"(A01));
        asm("mov.b64 {%0, %1}, %2;" : "=f"(a2), "=f"(a3) : "l"(A23));
        d0 = fminf(d0, (a0 + a1) + (a2 + a3));
        asm("mov.b64 {%0, %1}, %2;" : "=f"(a0), "=f"(a1) : "l"(B01));
        asm("mov.b64 {%0, %1}, %2;" : "=f"(a2), "=f"(a3) : "l"(B23));
        d1 = fminf(d1, (a0 + a1) + (a2 + a3));
        if (t == MM - 1) break;
        unsigned want = (unsigned)(t + 1);
        float dm; unsigned pi;
        if (d0 >= d1) { dm = d0; pi = (unsigned)p0; } else { dm = d1; pi = (unsigned)p1; }
        unsigned long long pk = ((unsigned long long)__float_as_uint(dm) << 14)
                              | (unsigned long long)(16383u - pi);   // tie -> lowest idx
#pragma unroll
        for (int o = 16; o; o >>= 1) {
            unsigned long long q = __shfl_down_sync(0xFFFFFFFFu, pk, o);
            if (q > pk) pk = q;
        }
        if (lane == 0) sred[wid] = pk;
        __syncthreads();
        if (wid == 0) {
            unsigned long long v = (lane < 16) ? sred[lane] : 0ull;
#pragma unroll
            for (int o = 8; o; o >>= 1) {
                unsigned long long q = __shfl_down_sync(0xFFFFFFFFu, v, o);
                if (q > v) v = q;
            }
            v = __shfl_sync(0xFFFFFFFFu, v, 0) | ((unsigned long long)want << 46);
            if (lane < 16)
                remote_st(a_slots + (((want & 1u)*16u + (unsigned)crk) << 3), (uint32_t)lane, v);
        }
        {
            unsigned long long v = 0ull;
            const unsigned long long* sl = slots[want & 1];
            do { if (lane < 16) v = ldvol(&sl[lane]); }
            while (!__all_sync(0xFFFFFFFFu, lane >= 16 || (unsigned)(v >> 46) == want));
            if (lane >= 16) v = 0ull;
#pragma unroll
            for (int o = 8; o; o >>= 1) {
                unsigned long long q = __shfl_down_sync(0xFFFFFFFFu, v, o);
                if (q > v) v = q;
            }
            v = __shfl_sync(0xFFFFFFFFu, v, 0);
            f = 16383 - (int)(v & 16383ull);
        }
        {
            int half = f >> 13, rest = f & 8191;
            if ((rest >> 9) == crk && (rest & 511) == tid) {
                float2* dst = (float2*)&g_cent[(size_t)(b*MM + t + 1)*32];
                float x0v, x1v, x2v;
                if (half == 0) {
#pragma unroll
                    for (int i = 0; i < 16; i++) {
                        float lo, hi;
                        asm("mov.b64 {%0, %1}, %2;" : "=f"(lo), "=f"(hi) : "l"(nx0[i]));
                        dst[i] = make_float2(-lo, -hi);
                    }
                    float lo, hi;
                    asm("mov.b64 {%0, %1}, %2;" : "=f"(lo), "=f"(hi) : "l"(nx0[0]));
                    x0v = -lo; x1v = -hi;
                    asm("mov.b64 {%0, %1}, %2;" : "=f"(lo), "=f"(hi) : "l"(nx0[1]));
                    x2v = -lo;
                } else {
#pragma unroll
                    for (int i = 0; i < 16; i++) {
                        float lo, hi;
                        asm("mov.b64 {%0, %1}, %2;" : "=f"(lo), "=f"(hi) : "l"(nx1[i]));
                        dst[i] = make_float2(-lo, -hi);
                    }
                    float lo, hi;
                    asm("mov.b64 {%0, %1}, %2;" : "=f"(lo), "=f"(hi) : "l"(nx1[0]));
                    x0v = -lo; x1v = -hi;
                    asm("mov.b64 {%0, %1}, %2;" : "=f"(lo), "=f"(hi) : "l"(nx1[1]));
                    x2v = -lo;
                }
                int m = t + 1;
                out[(b*3 + 0)*MM + m] = x0v;
                out[(b*3 + 1)*MM + m] = x1v;
                out[(b*3 + 2)*MM + m] = x2v;
            }
        }
    }
    asm volatile("barrier.cluster.arrive.aligned;" ::: "memory");
    asm volatile("barrier.cluster.wait.aligned;"   ::: "memory");
}

// ball query BOTH scales, 2 pts/lane, half2 prune, NO early exit (loads pipeline),
// classify path guarded by any_sync (rare). Exact fp32 verify decides membership.
__global__ __launch_bounds__(256) void k_ball2() {
    int w = threadIdx.x >> 5, lane = threadIdx.x & 31;
    int bm = blockIdx.x * 8 + w;
    int b = bm >> 10;
    const float* cen = &g_cent[bm*32];
    __half2 c01 = __floats2half2_rn(cen[3], cen[4]);
    __half2 c23 = __floats2half2_rn(cen[5], cen[6]);
    const __half TH = __float2half(0.07f);
    int cnt0 = 0, cnt1 = 0;
    int* o0 = &g_bidx[(size_t)bm*64];
    int* o1 = &g_bidx[(size_t)(4096 + bm)*64];
    const uint2* __restrict__ filt = &((const uint2*)g_filth)[b*NN];
    const float R2S = 0.01f, R2L = 0.04f;
#pragma unroll 2
    for (int it = 0; it < NN/64; it++) {
        int nA = (it << 6) + lane;
        int nB = nA + 32;
        uint2 fa = filt[nA], fb = filt[nB];
        __half2 a01, a23, b01h, b23h;
        memcpy(&a01,  &fa.x, 4); memcpy(&a23,  &fa.y, 4);
        memcpy(&b01h, &fb.x, 4); memcpy(&b23h, &fb.y, 4);
        __half2 eA = __hsub2(a01, c01);
        __half2 sA = __hmul2(eA, eA);
        eA = __hsub2(a23, c23);
        sA = __hfma2(eA, eA, sA);
        __half2 eB = __hsub2(b01h, c01);
        __half2 sB = __hmul2(eB, eB);
        eB = __hsub2(b23h, c23);
        sB = __hfma2(eB, eB, sB);
        __half2 d4 = __hadd2(__lows2half2(sA, sB), __highs2half2(sA, sB));
        bool passA = __hle(__low2half(d4), TH);
        bool passB = __hle(__high2half(d4), TH);
        if (__any_sync(0xFFFFFFFFu, passA || passB)) {
            bool p0A = false, p1A = false, p0B = false, p1B = false;
            if (passA) {
                const float* pp = &g_support[(size_t)(b*NN + nA)*32];
                float dd = 0.f;
#pragma unroll
                for (int i = 0; i < 32; i++) { float e = pp[i] - cen[i]; dd = fmaf(e, e, dd); }
                p1A = (dd <= R2L); p0A = (dd <= R2S);
            }
            if (passB) {
                const float* pp = &g_support[(size_t)(b*NN + nB)*32];
                float dd = 0.f;
#pragma unroll
                for (int i = 0; i < 32; i++) { float e = pp[i] - cen[i]; dd = fmaf(e, e, dd); }
                p1B = (dd <= R2L); p0B = (dd <= R2S);
            }
            unsigned balA1 = __ballot_sync(0xFFFFFFFFu, p1A);
            unsigned balA0 = __ballot_sync(0xFFFFFFFFu, p0A);
            unsigned balB1 = __ballot_sync(0xFFFFFFFFu, p1B);
            unsigned balB0 = __ballot_sync(0xFFFFFFFFu, p0B);
            while (balA1) {
                int l = __ffs(balA1) - 1; balA1 &= balA1 - 1;
                int idx = (it << 6) + l;
                if (cnt1 < 64) { if (lane == 0) o1[cnt1] = idx; cnt1++; }
                if (((balA0 >> l) & 1u) && cnt0 < 32) { if (lane == 0) o0[cnt0] = idx; cnt0++; }
            }
            while (balB1) {
                int l = __ffs(balB1) - 1; balB1 &= balB1 - 1;
                int idx = (it << 6) + 32 + l;
                if (cnt1 < 64) { if (lane == 0) o1[cnt1] = idx; cnt1++; }
                if (((balB0 >> l) & 1u) && cnt0 < 32) { if (lane == 0) o0[cnt0] = idx; cnt0++; }
            }
        }
    }
    if (lane == 0) { g_bcnt[bm] = cnt0; g_bcnt[4096 + bm] = cnt1; }
}

// attention over unmasked neighbors only; both scales in one launch (grid 1024)
__global__ __launch_bounds__(256) void k_att(const float* __restrict__ wq0,
                                             const float* __restrict__ wk0,
                                             const float* __restrict__ wv0,
                                             const float* __restrict__ wo0,
                                             const float* __restrict__ wq1,
                                             const float* __restrict__ wk1,
                                             const float* __restrict__ wv1,
                                             const float* __restrict__ wo1) {
    __shared__ float s_q[32*64], s_k[32*64], s_v[32*64], s_oT[64*32];
    __shared__ float s_x[8][32], s_y[8][32], s_o[8][64], s_l[8][128];
    int tid = threadIdx.x;
    int s = blockIdx.x >> 9;
    const float* wq = s ? wq1 : wq0;
    const float* wk = s ? wk1 : wk0;
    const float* wv = s ? wv1 : wv0;
    const float* wo = s ? wo1 : wo0;
    for (int i = tid; i < 2048; i += 256) {
        int oc = i >> 5, c = i & 31;
        s_q[c*64 + oc] = wq[i];
        s_k[c*64 + oc] = wk[i];
        s_v[c*64 + oc] = wv[i];
        int oc2 = i >> 6, c2 = i & 63;
        s_oT[c2*32 + oc2] = wo[i];
    }
    __syncthreads();
    int w = tid >> 5, lane = tid & 31;
    int bm = (blockIdx.x & 511) * 8 + w;
    int b = bm >> 10;
    float xv = g_cent[bm*32 + lane];
    s_x[w][lane] = xv;
    __syncwarp();
    float q0 = 0.f, q1 = 0.f;
#pragma unroll
    for (int c = 0; c < 32; c++) {
        float xc = s_x[w][c];
        q0 = fmaf(s_q[c*64 + lane],      xc, q0);
        q1 = fmaf(s_q[c*64 + 32 + lane], xc, q1);
    }
    int cnt = g_bcnt[s*4096 + bm];
    const int* bidx = &g_bidx[(size_t)(s*4096 + bm)*64];
    const float rs = 0.17677669529663687f;  // 1/sqrt(32)
    for (int j = 0; j < cnt; j++) {
        int id = bidx[j];
        float yv = g_support[(size_t)(b*NN + id)*32 + lane] - s_x[w][lane];
        s_y[w][lane] = yv; __syncwarp();
        float k0 = 0.f, k1 = 0.f;
#pragma unroll
        for (int c = 0; c < 32; c++) {
            float yc = s_y[w][c];
            k0 = fmaf(s_k[c*64 + lane],      yc, k0);
            k1 = fmaf(s_k[c*64 + 32 + lane], yc, k1);
        }
        float l0 = q0*k0, l1 = q1*k1;
#pragma unroll
        for (int o = 16; o; o >>= 1) {
            l0 += __shfl_xor_sync(0xFFFFFFFFu, l0, o);
            l1 += __shfl_xor_sync(0xFFFFFFFFu, l1, o);
        }
        if (lane == 0) { s_l[w][j] = l0*rs; s_l[w][64 + j] = l1*rs; }
        __syncwarp();
    }
#pragma unroll
    for (int h = 0; h < 2; h++) {
        float v0 = (lane      < cnt) ? s_l[w][h*64 + lane]      : -3e38f;
        float v1 = (lane + 32 < cnt) ? s_l[w][h*64 + lane + 32] : -3e38f;
        float mx = fmaxf(v0, v1);
#pragma unroll
        for (int o = 16; o; o >>= 1) mx = fmaxf(mx, __shfl_xor_sync(0xFFFFFFFFu, mx, o));
        float e0 = (lane      < cnt) ? __expf(v0 - mx) : 0.f;
        float e1 = (lane + 32 < cnt) ? __expf(v1 - mx) : 0.f;
        float sm = e0 + e1;
#pragma unroll
        for (int o = 16; o; o >>= 1) sm += __shfl_xor_sync(0xFFFFFFFFu, sm, o);
        float inv = 1.f / sm;
        if (lane      < cnt) s_l[w][h*64 + lane]      = e0 * inv;
        if (lane + 32 < cnt) s_l[w][h*64 + lane + 32] = e1 * inv;
    }
    __syncwarp();
    float o0 = 0.f, o1 = 0.f;
    for (int j = 0; j < cnt; j++) {
        int id = bidx[j];
        float yv = g_support[(size_t)(b*NN + id)*32 + lane] - s_x[w][lane];
        s_y[w][lane] = yv; __syncwarp();
        float v0 = 0.f, v1 = 0.f;
#pragma unroll
        for (int c = 0; c < 32; c++) {
            float yc = s_y[w][c];
            v0 = fmaf(s_v[c*64 + lane],      yc, v0);
            v1 = fmaf(s_v[c*64 + 32 + lane], yc, v1);
        }
        o0 = fmaf(s_l[w][j],      v0, o0);
        o1 = fmaf(s_l[w][64 + j], v1, o1);
        __syncwarp();
    }
    s_o[w][lane] = o0; s_o[w][32 + lane] = o1; __syncwarp();
    float outv = s_x[w][lane];
#pragma unroll
    for (int c = 0; c < 64; c++) outv = fmaf(s_oT[c*32 + lane], s_o[w][c], outv);
    g_att[(size_t)(s*4096 + bm)*32 + lane] = outv;
}

// MLP layer 1 + BN1 partial stats; 16 points/block (grid 512)
__global__ __launch_bounds__(256) void k_mlp1(const float* __restrict__ W00,
                                              const float* __restrict__ b00,
                                              const float* __restrict__ W10,
                                              const float* __restrict__ b10) {
    __shared__ float sW[32*64];
    __shared__ float s_in[16][32];
    __shared__ float2 red[4][64];
    int tid = threadIdx.x;
    int s = blockIdx.x >> 8;
    const float* W0 = s ? W10 : W00;
    const float* b0 = s ? b10 : b00;
    for (int i = tid; i < 2048; i += 256) { int oc = i >> 5, c = i & 31; sW[c*64 + oc] = W0[i]; }
    int bm0 = (blockIdx.x & 255) * 16;
    for (int j = tid; j < 512; j += 256)
        s_in[j >> 5][j & 31] = g_att[(size_t)(s*4096 + bm0)*32 + j];
    __syncthreads();
    int oc = tid & 63, q0 = tid >> 6;
    float bias = b0[oc];
    float s1 = 0.f, s2 = 0.f;
#pragma unroll
    for (int pass = 0; pass < 4; pass++) {
        int q = pass*4 + q0;
        float h = bias;
#pragma unroll
        for (int c = 0; c < 32; c++) h = fmaf(sW[c*64 + oc], s_in[q][c], h);
        g_h1[(size_t)(s*4096 + bm0 + q)*64 + oc] = h;
        s1 += h; s2 = fmaf(h, h, s2);
    }
    red[q0][oc] = make_float2(s1, s2);
    __syncthreads();
    if (q0 == 0) {
        float a1 = 0.f, a2 = 0.f;
#pragma unroll
        for (int qq = 0; qq < 4; qq++) { float2 v = red[qq][oc]; a1 += v.x; a2 += v.y; }
        atomicAdd(&g_s1a[s*64 + oc], a1);
        atomicAdd(&g_s2a[s*64 + oc], a2);
    }
}

__global__ void k_fin1(const float* __restrict__ g0, const float* __restrict__ beta0,
                       const float* __restrict__ g1, const float* __restrict__ beta1) {
    int s = blockIdx.x, oc = threadIdx.x;
    const float* g = s ? g1 : g0;
    const float* beta = s ? beta1 : beta0;
    float mu  = g_s1a[s*64 + oc] * (1.f/4096.f);
    float var = g_s2a[s*64 + oc] * (1.f/4096.f) - mu*mu;
    float A = g[oc] * rsqrtf(var + 1e-5f);
    g_A1[s*64 + oc] = A;
    g_C1[s*64 + oc] = beta[oc] - mu*A;
}

// MLP layer 2 (+BN1/leaky fused) + BN2 partial stats; 8 points/block (grid 1024)
__global__ __launch_bounds__(256) void k_mlp2(const float* __restrict__ W01,
                                              const float* __restrict__ b01,
                                              const float* __restrict__ W11,
                                              const float* __restrict__ b11) {
    __shared__ float sW[64*128];
    __shared__ float sact[8][64];
    __shared__ float2 red[2][128];
    int tid = threadIdx.x;
    int s = blockIdx.x >> 9;
    const float* W1 = s ? W11 : W01;
    const float* b1 = s ? b11 : b01;
    for (int i = tid; i < 8192; i += 256) { int oc = i >> 6, c = i & 63; sW[c*128 + oc] = W1[i]; }
    int bm0 = (blockIdx.x & 511) * 8;
    for (int j = tid; j < 512; j += 256) {
        int q = j >> 6, c = j & 63;
        float v = g_h1[(size_t)(s*4096 + bm0)*64 + j];
        v = g_A1[s*64 + c]*v + g_C1[s*64 + c];
        sact[q][c] = v > 0.f ? v : 0.02f*v;
    }
    __syncthreads();
    int oc = tid & 127, q0 = tid >> 7;
    float bias = b1[oc];
    float s1 = 0.f, s2 = 0.f;
#pragma unroll
    for (int pass = 0; pass < 4; pass++) {
        int q = pass*2 + q0;
        float h = bias;
#pragma unroll
        for (int c = 0; c < 64; c++) h = fmaf(sW[c*128 + oc], sact[q][c], h);
        g_h2[(size_t)(s*4096 + bm0 + q)*128 + oc] = h;
        s1 += h; s2 = fmaf(h, h, s2);
    }
    red[q0][oc] = make_float2(s1, s2);
    __syncthreads();
    if (q0 == 0) {
        float2 a = red[0][oc], c = red[1][oc];
        atomicAdd(&g_s1b[s*128 + oc], a.x + c.x);
        atomicAdd(&g_s2b[s*128 + oc], a.y + c.y);
    }
}

__global__ void k_fin2(const float* __restrict__ g0, const float* __restrict__ beta0,
                       const float* __restrict__ g1, const float* __restrict__ beta1) {
    int s = blockIdx.x, oc = threadIdx.x;
    const float* g = s ? g1 : g0;
    const float* beta = s ? beta1 : beta0;
    float mu  = g_s1b[s*128 + oc] * (1.f/4096.f);
    float var = g_s2b[s*128 + oc] * (1.f/4096.f) - mu*mu;
    float A = g[oc] * rsqrtf(var + 1e-5f);
    g_A2[s*128 + oc] = A;
    g_C2[s*128 + oc] = beta[oc] - mu*A;
}

// final BN2 apply + scatter, both scales (grid 4096)
__global__ __launch_bounds__(256) void k_out(float* __restrict__ out) {
    int s = blockIdx.x >> 11;
    int idx = (blockIdx.x & 2047) * 256 + threadIdx.x;
    int m = idx & 1023;
    int t2 = idx >> 10;
    int oc = t2 & 127, b = t2 >> 7;
    int bm = b*1024 + m;
    float v = g_h2[(size_t)(s*4096 + bm)*128 + oc];
    v = g_A2[s*128 + oc]*v + g_C2[s*128 + oc];
    out[12288 + (((b*256) + s*128 + oc) << 10) + m] = v;
}

extern "C" void kernel_launch(void* const* d_in, const int* in_sizes, int n_in,
                              void* d_out, int out_size) {
    (void)in_sizes; (void)n_in; (void)out_size;
    const float* xyz = (const float*)d_in[0];
    const float* pf  = (const float*)d_in[1];
    float* out = (float*)d_out;
    k_build<<<2048, 256>>>(xyz, pf);
    {
        cudaFuncSetAttribute(k_fps, cudaFuncAttributeNonPortableClusterSizeAllowed, 1);
        cudaLaunchConfig_t cfg = {};
        cfg.gridDim  = dim3(64, 1, 1);
        cfg.blockDim = dim3(512, 1, 1);
        cfg.dynamicSmemBytes = 0;
        cfg.stream = 0;
        cudaLaunchAttribute at[1];
        at[0].id = cudaLaunchAttributeClusterDimension;
        at[0].val.clusterDim.x = 16; at[0].val.clusterDim.y = 1; at[0].val.clusterDim.z = 1;
        cfg.attrs = at;
        cfg.numAttrs = 1;
        cudaLaunchKernelEx(&cfg, k_fps, out);
    }
    k_ball2<<<512, 256>>>();
    k_att<<<1024, 256>>>((const float*)d_in[2],  (const float*)d_in[3],
                         (const float*)d_in[4],  (const float*)d_in[5],
                         (const float*)d_in[14], (const float*)d_in[15],
                         (const float*)d_in[16], (const float*)d_in[17]);
    k_mlp1<<<512, 256>>>((const float*)d_in[6],  (const float*)d_in[7],
                         (const float*)d_in[18], (const float*)d_in[19]);
    k_fin1<<<2, 64>>>((const float*)d_in[8],  (const float*)d_in[9],
                      (const float*)d_in[20], (const float*)d_in[21]);
    k_mlp2<<<1024, 256>>>((const float*)d_in[10], (const float*)d_in[11],
                          (const float*)d_in[22], (const float*)d_in[23]);
    k_fin2<<<2, 128>>>((const float*)d_in[12], (const float*)d_in[13],
                       (const float*)d_in[24], (const float*)d_in[25]);
    k_out<<<4096, 256>>>(out);
}

// round 17
// speedup vs baseline: 5.0071x; 1.0780x over previous
#include <cuda_runtime.h>
#include <cuda_fp16.h>
#include <cstdint>
#include <cstring>

#define BB 4
#define NN 16384
#define MM 1024

// ---- static scratch (no allocation) ----
__device__ float  g_support[BB*NN*32];
__device__ __align__(8) __half2 g_filth[BB*NN*2];   // 4 filter dims as fp16
__device__ float  g_cent[BB*MM*32];
__device__ int    g_bidx[2*BB*MM*64];
__device__ int    g_bcnt[2*BB*MM];
__device__ float  g_att[2*BB*MM*32];
__device__ float  g_h1[2*BB*MM*64];
__device__ float  g_h2[2*BB*MM*128];
__device__ float  g_s1a[2*64], g_s2a[2*64], g_s1b[2*128], g_s2b[2*128];
__device__ float  g_A1[2*64], g_C1[2*64], g_A2[2*128], g_C2[2*128];

// transpose [B,32,N] channel-major inputs -> point-major support + fp16 filter
__global__ __launch_bounds__(256) void k_build(const float* __restrict__ xyz,
                                               const float* __restrict__ pf) {
    __shared__ float t[32][33];
    int b  = blockIdx.x >> 9;
    int n0 = (blockIdx.x & 511) << 5;
    int tid = threadIdx.x;
    if (blockIdx.x == 0) {
        if (tid < 128) { g_s1a[tid] = 0.f; g_s2a[tid] = 0.f; }
        g_s1b[tid] = 0.f; g_s2b[tid] = 0.f;
    }
#pragma unroll
    for (int i = 0; i < 4; i++) {
        int e = tid + i*256, c = e >> 5, n = e & 31;
        float v = (c < 3) ? xyz[(b*3 + c)*NN + n0 + n] : pf[(b*29 + (c-3))*NN + n0 + n];
        t[n][c] = v;
    }
    __syncthreads();
    int n = tid >> 3, c0 = (tid & 7) << 2;
    *(float4*)&g_support[((size_t)(b*NN + n0 + n))*32 + c0] =
        make_float4(t[n][c0], t[n][c0+1], t[n][c0+2], t[n][c0+3]);
    if (tid < 32) {
        __half2 h01 = __float22half2_rn(make_float2(t[tid][3], t[tid][4]));
        __half2 h23 = __float22half2_rn(make_float2(t[tid][5], t[tid][6]));
        uint2 u; memcpy(&u.x, &h01, 4); memcpy(&u.y, &h23, 4);
        ((uint2*)g_filth)[b*NN + n0 + tid] = u;
    }
}

__device__ __forceinline__ uint32_t smem_u32(const void* p) {
    uint32_t a;
    asm("{ .reg .u64 t; cvta.to.shared.u64 t, %1; cvt.u32.u64 %0, t; }" : "=r"(a) : "l"(p));
    return a;
}
__device__ __forceinline__ void remote_st(uint32_t laddr, uint32_t rank, unsigned long long v) {
    uint32_t ra;
    asm volatile("mapa.shared::cluster.u32 %0, %1, %2;" : "=r"(ra) : "r"(laddr), "r"(rank));
    asm volatile("st.relaxed.cluster.shared::cluster.u64 [%0], %1;" :: "r"(ra), "l"(v) : "memory");
}
__device__ __forceinline__ unsigned long long ldvol(const unsigned long long* p) {
    unsigned long long v;
    asm volatile("ld.volatile.shared.u64 %0, [%1];" : "=l"(v) : "r"(smem_u32(p)) : "memory");
    return v;
}

// FPS: one 16-CTA cluster per batch, 512 thr/CTA, 2 pts/thread (f32x2 math).
// Sync v8 (frozen from R13): bar.sync intra-CTA; all-to-all DSMEM exchange.
__global__ void __launch_bounds__(512, 1) k_fps(float* __restrict__ out) {
    __shared__ unsigned long long sred[16];
    __shared__ unsigned long long slots[2][16];
    int b   = blockIdx.x >> 4;
    int crk = blockIdx.x & 15;
    int tid = threadIdx.x, wid = tid >> 5, lane = tid & 31;
    if (tid < 16) { slots[0][tid] = 0ull; slots[1][tid] = 0ull; }
    __syncthreads();
    asm volatile("barrier.cluster.arrive.aligned;" ::: "memory");
    asm volatile("barrier.cluster.wait.aligned;"   ::: "memory");
    int p0 = (crk << 9) + tid, p1 = p0 + 8192;
    unsigned long long nx0[16], nx1[16];
    {
        const float4* a = (const float4*)&g_support[(size_t)(b*NN + p0)*32];
        const float4* c = (const float4*)&g_support[(size_t)(b*NN + p1)*32];
#pragma unroll
        for (int i = 0; i < 8; i++) {
            float4 v = a[i], u = c[i];
            asm("mov.b64 %0, {%1, %2};" : "=l"(nx0[2*i])   : "f"(-v.x), "f"(-v.y));
            asm("mov.b64 %0, {%1, %2};" : "=l"(nx0[2*i+1]) : "f"(-v.z), "f"(-v.w));
            asm("mov.b64 %0, {%1, %2};" : "=l"(nx1[2*i])   : "f"(-u.x), "f"(-u.y));
            asm("mov.b64 %0, {%1, %2};" : "=l"(nx1[2*i+1]) : "f"(-u.z), "f"(-u.w));
        }
    }
    float d0 = 1e10f, d1 = 1e10f;
    int f = 0;
    if (crk == 0 && tid == 0) {
        float2* dst = (float2*)&g_cent[(size_t)b*MM*32];
#pragma unroll
        for (int i = 0; i < 16; i++) {
            float lo, hi;
            asm("mov.b64 {%0, %1}, %2;" : "=f"(lo), "=f"(hi) : "l"(nx0[i]));
            dst[i] = make_float2(-lo, -hi);
        }
        float l0, h0, l1, h1;
        asm("mov.b64 {%0, %1}, %2;" : "=f"(l0), "=f"(h0) : "l"(nx0[0]));
        asm("mov.b64 {%0, %1}, %2;" : "=f"(l1), "=f"(h1) : "l"(nx0[1]));
        out[(b*3 + 0)*MM] = -l0; out[(b*3 + 1)*MM] = -h0; out[(b*3 + 2)*MM] = -l1;
    }
    uint32_t a_slots = smem_u32(slots);
    for (int t = 0; t < MM; t++) {
        const ulonglong2* cp = (const ulonglong2*)&g_support[(size_t)(b*NN + f)*32];
        unsigned long long A01 = 0ull, A23 = 0ull, B01 = 0ull, B23 = 0ull;
#pragma unroll
        for (int i = 0; i < 8; i++) {
            ulonglong2 cv = cp[i];
            unsigned long long e;
            asm("add.rn.f32x2 %0, %1, %2;"     : "=l"(e)   : "l"(cv.x), "l"(nx0[2*i]));
            asm("fma.rn.f32x2 %0, %1, %2, %3;" : "=l"(A01) : "l"(e), "l"(e), "l"(A01));
            asm("add.rn.f32x2 %0, %1, %2;"     : "=l"(e)   : "l"(cv.y), "l"(nx0[2*i+1]));
            asm("fma.rn.f32x2 %0, %1, %2, %3;" : "=l"(A23) : "l"(e), "l"(e), "l"(A23));
            asm("add.rn.f32x2 %0, %1, %2;"     : "=l"(e)   : "l"(cv.x), "l"(nx1[2*i]));
            asm("fma.rn.f32x2 %0, %1, %2, %3;" : "=l"(B01) : "l"(e), "l"(e), "l"(B01));
            asm("add.rn.f32x2 %0, %1, %2;"     : "=l"(e)   : "l"(cv.y), "l"(nx1[2*i+1]));
            asm("fma.rn.f32x2 %0, %1, %2, %3;" : "=l"(B23) : "l"(e), "l"(e), "l"(B23));
        }
        float a0,a1,a2,a3;
        asm("mov.b64 {%0, %1}, %2;" : "=f"(a0), "=f"(a1) : "l"(A01));
        asm("mov.b64 {%0, %1}, %2;" : "=f"(a2), "=f"(a3) : "l"(A23));
        d0 = fminf(d0, (a0 + a1) + (a2 + a3));
        asm("mov.b64 {%0, %1}, %2;" : "=f"(a0), "=f"(a1) : "l"(B01));
        asm("mov.b64 {%0, %1}, %2;" : "=f"(a2), "=f"(a3) : "l"(B23));
        d1 = fminf(d1, (a0 + a1) + (a2 + a3));
        if (t == MM - 1) break;
        unsigned want = (unsigned)(t + 1);
        float dm; unsigned pi;
        if (d0 >= d1) { dm = d0; pi = (unsigned)p0; } else { dm = d1; pi = (unsigned)p1; }
        unsigned long long pk = ((unsigned long long)__float_as_uint(dm) << 14)
                              | (unsigned long long)(16383u - pi);   // tie -> lowest idx
#pragma unroll
        for (int o = 16; o; o >>= 1) {
            unsigned long long q = __shfl_down_sync(0xFFFFFFFFu, pk, o);
            if (q > pk) pk = q;
        }
        if (lane == 0) sred[wid] = pk;
        __syncthreads();
        if (wid == 0) {
            unsigned long long v = (lane < 16) ? sred[lane] : 0ull;
#pragma unroll
            for (int o = 8; o; o >>= 1) {
                unsigned long long q = __shfl_down_sync(0xFFFFFFFFu, v, o);
                if (q > v) v = q;
            }
            v = __shfl_sync(0xFFFFFFFFu, v, 0) | ((unsigned long long)want << 46);
            if (lane < 16)
                remote_st(a_slots + (((want & 1u)*16u + (unsigned)crk) << 3), (uint32_t)lane, v);
        }
        {
            unsigned long long v = 0ull;
            const unsigned long long* sl = slots[want & 1];
            do { if (lane < 16) v = ldvol(&sl[lane]); }
            while (!__all_sync(0xFFFFFFFFu, lane >= 16 || (unsigned)(v >> 46) == want));
            if (lane >= 16) v = 0ull;
#pragma unroll
            for (int o = 8; o; o >>= 1) {
                unsigned long long q = __shfl_down_sync(0xFFFFFFFFu, v, o);
                if (q > v) v = q;
            }
            v = __shfl_sync(0xFFFFFFFFu, v, 0);
            f = 16383 - (int)(v & 16383ull);
        }
        {
            int half = f >> 13, rest = f & 8191;
            if ((rest >> 9) == crk && (rest & 511) == tid) {
                float2* dst = (float2*)&g_cent[(size_t)(b*MM + t + 1)*32];
                float x0v, x1v, x2v;
                if (half == 0) {
#pragma unroll
                    for (int i = 0; i < 16; i++) {
                        float lo, hi;
                        asm("mov.b64 {%0, %1}, %2;" : "=f"(lo), "=f"(hi) : "l"(nx0[i]));
                        dst[i] = make_float2(-lo, -hi);
                    }
                    float lo, hi;
                    asm("mov.b64 {%0, %1}, %2;" : "=f"(lo), "=f"(hi) : "l"(nx0[0]));
                    x0v = -lo; x1v = -hi;
                    asm("mov.b64 {%0, %1}, %2;" : "=f"(lo), "=f"(hi) : "l"(nx0[1]));
                    x2v = -lo;
                } else {
#pragma unroll
                    for (int i = 0; i < 16; i++) {
                        float lo, hi;
                        asm("mov.b64 {%0, %1}, %2;" : "=f"(lo), "=f"(hi) : "l"(nx1[i]));
                        dst[i] = make_float2(-lo, -hi);
                    }
                    float lo, hi;
                    asm("mov.b64 {%0, %1}, %2;" : "=f"(lo), "=f"(hi) : "l"(nx1[0]));
                    x0v = -lo; x1v = -hi;
                    asm("mov.b64 {%0, %1}, %2;" : "=f"(lo), "=f"(hi) : "l"(nx1[1]));
                    x2v = -lo;
                }
                int m = t + 1;
                out[(b*3 + 0)*MM + m] = x0v;
                out[(b*3 + 1)*MM + m] = x1v;
                out[(b*3 + 2)*MM + m] = x2v;
            }
        }
    }
    asm volatile("barrier.cluster.arrive.aligned;" ::: "memory");
    asm volatile("barrier.cluster.wait.aligned;"   ::: "memory");
}

// ball query BOTH scales, 2 pts/lane, half2 prune, no early exit.
__global__ __launch_bounds__(256) void k_ball2() {
    int w = threadIdx.x >> 5, lane = threadIdx.x & 31;
    int bm = blockIdx.x * 8 + w;
    int b = bm >> 10;
    const float* cen = &g_cent[bm*32];
    __half2 c01 = __floats2half2_rn(cen[3], cen[4]);
    __half2 c23 = __floats2half2_rn(cen[5], cen[6]);
    const __half TH = __float2half(0.07f);
    int cnt0 = 0, cnt1 = 0;
    int* o0 = &g_bidx[(size_t)bm*64];
    int* o1 = &g_bidx[(size_t)(4096 + bm)*64];
    const uint2* __restrict__ filt = &((const uint2*)g_filth)[b*NN];
    const float R2S = 0.01f, R2L = 0.04f;
#pragma unroll 2
    for (int it = 0; it < NN/64; it++) {
        int nA = (it << 6) + lane;
        int nB = nA + 32;
        uint2 fa = filt[nA], fb = filt[nB];
        __half2 a01, a23, b01h, b23h;
        memcpy(&a01,  &fa.x, 4); memcpy(&a23,  &fa.y, 4);
        memcpy(&b01h, &fb.x, 4); memcpy(&b23h, &fb.y, 4);
        __half2 eA = __hsub2(a01, c01);
        __half2 sA = __hmul2(eA, eA);
        eA = __hsub2(a23, c23);
        sA = __hfma2(eA, eA, sA);
        __half2 eB = __hsub2(b01h, c01);
        __half2 sB = __hmul2(eB, eB);
        eB = __hsub2(b23h, c23);
        sB = __hfma2(eB, eB, sB);
        __half2 d4 = __hadd2(__lows2half2(sA, sB), __highs2half2(sA, sB));
        bool passA = __hle(__low2half(d4), TH);
        bool passB = __hle(__high2half(d4), TH);
        if (__any_sync(0xFFFFFFFFu, passA || passB)) {
            bool p0A = false, p1A = false, p0B = false, p1B = false;
            if (passA) {
                const float* pp = &g_support[(size_t)(b*NN + nA)*32];
                float dd = 0.f;
#pragma unroll
                for (int i = 0; i < 32; i++) { float e = pp[i] - cen[i]; dd = fmaf(e, e, dd); }
                p1A = (dd <= R2L); p0A = (dd <= R2S);
            }
            if (passB) {
                const float* pp = &g_support[(size_t)(b*NN + nB)*32];
                float dd = 0.f;
#pragma unroll
                for (int i = 0; i < 32; i++) { float e = pp[i] - cen[i]; dd = fmaf(e, e, dd); }
                p1B = (dd <= R2L); p0B = (dd <= R2S);
            }
            unsigned balA1 = __ballot_sync(0xFFFFFFFFu, p1A);
            unsigned balA0 = __ballot_sync(0xFFFFFFFFu, p0A);
            unsigned balB1 = __ballot_sync(0xFFFFFFFFu, p1B);
            unsigned balB0 = __ballot_sync(0xFFFFFFFFu, p0B);
            while (balA1) {
                int l = __ffs(balA1) - 1; balA1 &= balA1 - 1;
                int idx = (it << 6) + l;
                if (cnt1 < 64) { if (lane == 0) o1[cnt1] = idx; cnt1++; }
                if (((balA0 >> l) & 1u) && cnt0 < 32) { if (lane == 0) o0[cnt0] = idx; cnt0++; }
            }
            while (balB1) {
                int l = __ffs(balB1) - 1; balB1 &= balB1 - 1;
                int idx = (it << 6) + 32 + l;
                if (cnt1 < 64) { if (lane == 0) o1[cnt1] = idx; cnt1++; }
                if (((balB0 >> l) & 1u) && cnt0 < 32) { if (lane == 0) o0[cnt0] = idx; cnt0++; }
            }
        }
    }
    if (lane == 0) { g_bcnt[bm] = cnt0; g_bcnt[4096 + bm] = cnt1; }
}

// attention; both scales in one launch, 4 centroids per warp (grid 256)
__global__ __launch_bounds__(256) void k_att(const float* __restrict__ wq0,
                                             const float* __restrict__ wk0,
                                             const float* __restrict__ wv0,
                                             const float* __restrict__ wo0,
                                             const float* __restrict__ wq1,
                                             const float* __restrict__ wk1,
                                             const float* __restrict__ wv1,
                                             const float* __restrict__ wo1) {
    __shared__ float s_q[32*64], s_k[32*64], s_v[32*64], s_oT[64*32];
    __shared__ float s_x[8][32], s_y[8][32], s_o[8][64], s_l[8][128];
    int tid = threadIdx.x;
    int s = blockIdx.x >> 7;
    const float* wq = s ? wq1 : wq0;
    const float* wk = s ? wk1 : wk0;
    const float* wv = s ? wv1 : wv0;
    const float* wo = s ? wo1 : wo0;
    for (int i = tid; i < 2048; i += 256) {
        int oc = i >> 5, c = i & 31;
        s_q[c*64 + oc] = wq[i];
        s_k[c*64 + oc] = wk[i];
        s_v[c*64 + oc] = wv[i];
        int oc2 = i >> 6, c2 = i & 63;
        s_oT[c2*32 + oc2] = wo[i];
    }
    __syncthreads();
    int w = tid >> 5, lane = tid & 31;
    int bm_base = (blockIdx.x & 127) * 32 + w;
    const float rs = 0.17677669529663687f;  // 1/sqrt(32)
    for (int rep = 0; rep < 4; rep++) {
        int bm = bm_base + rep * 8;
        int b = bm >> 10;
        float xv = g_cent[bm*32 + lane];
        s_x[w][lane] = xv;
        __syncwarp();
        float q0 = 0.f, q1 = 0.f;
#pragma unroll
        for (int c = 0; c < 32; c++) {
            float xc = s_x[w][c];
            q0 = fmaf(s_q[c*64 + lane],      xc, q0);
            q1 = fmaf(s_q[c*64 + 32 + lane], xc, q1);
        }
        int cnt = g_bcnt[s*4096 + bm];
        const int* bidx = &g_bidx[(size_t)(s*4096 + bm)*64];
        for (int j = 0; j < cnt; j++) {
            int id = bidx[j];
            float yv = g_support[(size_t)(b*NN + id)*32 + lane] - s_x[w][lane];
            s_y[w][lane] = yv; __syncwarp();
            float k0 = 0.f, k1 = 0.f;
#pragma unroll
            for (int c = 0; c < 32; c++) {
                float yc = s_y[w][c];
                k0 = fmaf(s_k[c*64 + lane],      yc, k0);
                k1 = fmaf(s_k[c*64 + 32 + lane], yc, k1);
            }
            float l0 = q0*k0, l1 = q1*k1;
#pragma unroll
            for (int o = 16; o; o >>= 1) {
                l0 += __shfl_xor_sync(0xFFFFFFFFu, l0, o);
                l1 += __shfl_xor_sync(0xFFFFFFFFu, l1, o);
            }
            if (lane == 0) { s_l[w][j] = l0*rs; s_l[w][64 + j] = l1*rs; }
            __syncwarp();
        }
#pragma unroll
        for (int h = 0; h < 2; h++) {
            float v0 = (lane      < cnt) ? s_l[w][h*64 + lane]      : -3e38f;
            float v1 = (lane + 32 < cnt) ? s_l[w][h*64 + lane + 32] : -3e38f;
            float mx = fmaxf(v0, v1);
#pragma unroll
            for (int o = 16; o; o >>= 1) mx = fmaxf(mx, __shfl_xor_sync(0xFFFFFFFFu, mx, o));
            float e0 = (lane      < cnt) ? __expf(v0 - mx) : 0.f;
            float e1 = (lane + 32 < cnt) ? __expf(v1 - mx) : 0.f;
            float sm = e0 + e1;
#pragma unroll
            for (int o = 16; o; o >>= 1) sm += __shfl_xor_sync(0xFFFFFFFFu, sm, o);
            float inv = 1.f / sm;
            if (lane      < cnt) s_l[w][h*64 + lane]      = e0 * inv;
            if (lane + 32 < cnt) s_l[w][h*64 + lane + 32] = e1 * inv;
        }
        __syncwarp();
        float o0 = 0.f, o1 = 0.f;
        for (int j = 0; j < cnt; j++) {
            int id = bidx[j];
            float yv = g_support[(size_t)(b*NN + id)*32 + lane] - s_x[w][lane];
            s_y[w][lane] = yv; __syncwarp();
            float v0 = 0.f, v1 = 0.f;
#pragma unroll
            for (int c = 0; c < 32; c++) {
                float yc = s_y[w][c];
                v0 = fmaf(s_v[c*64 + lane],      yc, v0);
                v1 = fmaf(s_v[c*64 + 32 + lane], yc, v1);
            }
            o0 = fmaf(s_l[w][j],      v0, o0);
            o1 = fmaf(s_l[w][64 + j], v1, o1);
            __syncwarp();
        }
        s_o[w][lane] = o0; s_o[w][32 + lane] = o1; __syncwarp();
        float outv = s_x[w][lane];
#pragma unroll
        for (int c = 0; c < 64; c++) outv = fmaf(s_oT[c*32 + lane], s_o[w][c], outv);
        g_att[(size_t)(s*4096 + bm)*32 + lane] = outv;
        __syncwarp();
    }
}

// MLP layer 1 + BN1 partial stats; 32 points/block (grid 256)
__global__ __launch_bounds__(256) void k_mlp1(const float* __restrict__ W00,
                                              const float* __restrict__ b00,
                                              const float* __restrict__ W10,
                                              const float* __restrict__ b10) {
    __shared__ float sW[32*64];
    __shared__ float s_in[32][32];
    __shared__ float2 red[4][64];
    int tid = threadIdx.x;
    int s = blockIdx.x >> 7;
    const float* W0 = s ? W10 : W00;
    const float* b0 = s ? b10 : b00;
    for (int i = tid; i < 2048; i += 256) { int oc = i >> 5, c = i & 31; sW[c*64 + oc] = W0[i]; }
    int bm0 = (blockIdx.x & 127) * 32;
    for (int j = tid; j < 1024; j += 256)
        s_in[j >> 5][j & 31] = g_att[(size_t)(s*4096 + bm0)*32 + j];
    __syncthreads();
    int oc = tid & 63, q0 = tid >> 6;
    float bias = b0[oc];
    float s1 = 0.f, s2 = 0.f;
#pragma unroll
    for (int pass = 0; pass < 8; pass++) {
        int q = pass*4 + q0;
        float h = bias;
#pragma unroll
        for (int c = 0; c < 32; c++) h = fmaf(sW[c*64 + oc], s_in[q][c], h);
        g_h1[(size_t)(s*4096 + bm0 + q)*64 + oc] = h;
        s1 += h; s2 = fmaf(h, h, s2);
    }
    red[q0][oc] = make_float2(s1, s2);
    __syncthreads();
    if (q0 == 0) {
        float a1 = 0.f, a2 = 0.f;
#pragma unroll
        for (int qq = 0; qq < 4; qq++) { float2 v = red[qq][oc]; a1 += v.x; a2 += v.y; }
        atomicAdd(&g_s1a[s*64 + oc], a1);
        atomicAdd(&g_s2a[s*64 + oc], a2);
    }
}

__global__ void k_fin1(const float* __restrict__ g0, const float* __restrict__ beta0,
                       const float* __restrict__ g1, const float* __restrict__ beta1) {
    int s = blockIdx.x, oc = threadIdx.x;
    const float* g = s ? g1 : g0;
    const float* beta = s ? beta1 : beta0;
    float mu  = g_s1a[s*64 + oc] * (1.f/4096.f);
    float var = g_s2a[s*64 + oc] * (1.f/4096.f) - mu*mu;
    float A = g[oc] * rsqrtf(var + 1e-5f);
    g_A1[s*64 + oc] = A;
    g_C1[s*64 + oc] = beta[oc] - mu*A;
}

// MLP layer 2 (+BN1/leaky fused) + BN2 partial stats; 16 points/block (grid 512)
__global__ __launch_bounds__(256) void k_mlp2(const float* __restrict__ W01,
                                              const float* __restrict__ b01,
                                              const float* __restrict__ W11,
                                              const float* __restrict__ b11) {
    __shared__ float sW[64*128];
    __shared__ float sact[16][64];
    __shared__ float2 red[2][128];
    int tid = threadIdx.x;
    int s = blockIdx.x >> 8;
    const float* W1 = s ? W11 : W01;
    const float* b1 = s ? b11 : b01;
    for (int i = tid; i < 8192; i += 256) { int oc = i >> 6, c = i & 63; sW[c*128 + oc] = W1[i]; }
    int bm0 = (blockIdx.x & 255) * 16;
    for (int j = tid; j < 1024; j += 256) {
        int q = j >> 6, c = j & 63;
        float v = g_h1[(size_t)(s*4096 + bm0)*64 + j];
        v = g_A1[s*64 + c]*v + g_C1[s*64 + c];
        sact[q][c] = v > 0.f ? v : 0.02f*v;
    }
    __syncthreads();
    int oc = tid & 127, q0 = tid >> 7;
    float bias = b1[oc];
    float s1 = 0.f, s2 = 0.f;
#pragma unroll
    for (int pass = 0; pass < 8; pass++) {
        int q = pass*2 + q0;
        float h = bias;
#pragma unroll
        for (int c = 0; c < 64; c++) h = fmaf(sW[c*128 + oc], sact[q][c], h);
        g_h2[(size_t)(s*4096 + bm0 + q)*128 + oc] = h;
        s1 += h; s2 = fmaf(h, h, s2);
    }
    red[q0][oc] = make_float2(s1, s2);
    __syncthreads();
    if (q0 == 0) {
        float2 a = red[0][oc], c = red[1][oc];
        atomicAdd(&g_s1b[s*128 + oc], a.x + c.x);
        atomicAdd(&g_s2b[s*128 + oc], a.y + c.y);
    }
}

__global__ void k_fin2(const float* __restrict__ g0, const float* __restrict__ beta0,
                       const float* __restrict__ g1, const float* __restrict__ beta1) {
    int s = blockIdx.x, oc = threadIdx.x;
    const float* g = s ? g1 : g0;
    const float* beta = s ? beta1 : beta0;
    float mu  = g_s1b[s*128 + oc] * (1.f/4096.f);
    float var = g_s2b[s*128 + oc] * (1.f/4096.f) - mu*mu;
    float A = g[oc] * rsqrtf(var + 1e-5f);
    g_A2[s*128 + oc] = A;
    g_C2[s*128 + oc] = beta[oc] - mu*A;
}

// final BN2 apply + scatter, both scales (grid 4096)
__global__ __launch_bounds__(256) void k_out(float* __restrict__ out) {
    int s = blockIdx.x >> 11;
    int idx = (blockIdx.x & 2047) * 256 + threadIdx.x;
    int m = idx & 1023;
    int t2 = idx >> 10;
    int oc = t2 & 127, b = t2 >> 7;
    int bm = b*1024 + m;
    float v = g_h2[(size_t)(s*4096 + bm)*128 + oc];
    v = g_A2[s*128 + oc]*v + g_C2[s*128 + oc];
    out[12288 + (((b*256) + s*128 + oc) << 10) + m] = v;
}

extern "C" void kernel_launch(void* const* d_in, const int* in_sizes, int n_in,
                              void* d_out, int out_size) {
    (void)in_sizes; (void)n_in; (void)out_size;
    const float* xyz = (const float*)d_in[0];
    const float* pf  = (const float*)d_in[1];
    float* out = (float*)d_out;
    k_build<<<2048, 256>>>(xyz, pf);
    {
        cudaFuncSetAttribute(k_fps, cudaFuncAttributeNonPortableClusterSizeAllowed, 1);
        cudaLaunchConfig_t cfg = {};
        cfg.gridDim  = dim3(64, 1, 1);
        cfg.blockDim = dim3(512, 1, 1);
        cfg.dynamicSmemBytes = 0;
        cfg.stream = 0;
        cudaLaunchAttribute at[1];
        at[0].id = cudaLaunchAttributeClusterDimension;
        at[0].val.clusterDim.x = 16; at[0].val.clusterDim.y = 1; at[0].val.clusterDim.z = 1;
        cfg.attrs = at;
        cfg.numAttrs = 1;
        cudaLaunchKernelEx(&cfg, k_fps, out);
    }
    k_ball2<<<512, 256>>>();
    k_att<<<256, 256>>>((const float*)d_in[2],  (const float*)d_in[3],
                        (const float*)d_in[4],  (const float*)d_in[5],
                        (const float*)d_in[14], (const float*)d_in[15],
                        (const float*)d_in[16], (const float*)d_in[17]);
    k_mlp1<<<256, 256>>>((const float*)d_in[6],  (const float*)d_in[7],
                         (const float*)d_in[18], (const float*)d_in[19]);
    k_fin1<<<2, 64>>>((const float*)d_in[8],  (const float*)d_in[9],
                      (const float*)d_in[20], (const float*)d_in[21]);
    k_mlp2<<<512, 256>>>((const float*)d_in[10], (const float*)d_in[11],
                         (const float*)d_in[22], (const float*)d_in[23]);
    k_fin2<<<2, 128>>>((const float*)d_in[12], (const float*)d_in[13],
                       (const float*)d_in[24], (const float*)d_in[25]);
    k_out<<<4096, 256>>>(out);
}